// round 9
// baseline (speedup 1.0000x reference)
#include <cuda_runtime.h>
#include <cuda_fp16.h>
#include <math.h>
#include <stdint.h>

constexpr int Nn  = 4096;
constexpr int ATT = 64;
constexpr int OUTD = 64;
constexpr float SCALE_AN = 16384.f;
constexpr float SCALE_AW = 64.f;

// ---------------- scratch (device globals; no allocation allowed) ----------------
__device__ float g_Aorig[(size_t)Nn * Nn];
__device__ float g_A[(size_t)Nn * Nn];
__device__ float g_H [Nn * 256];
__device__ float g_H2[Nn * 256];
__device__ float g_HW[Nn * 256];
__device__ float g_HWT[256 * Nn];
__device__ float g_AWT[64 * Nn];
__device__ float g_part[(size_t)8 * Nn * 256];
__device__ float g_P0[Nn * ATT];
__device__ float g_P1[Nn * ATT];
__device__ float g_rspart[64 * Nn];
__device__ float g_a0[Nn], g_a1[Nn], g_dinv[Nn];
__device__ float g_rs0[Nn];
__device__ float g_mu[256], g_var[256];

// ---------------- helpers ----------------
__device__ __forceinline__ uint32_t smem_u32(const void* p) {
    uint32_t a;
    asm("{ .reg .u64 t; cvta.to.shared.u64 t, %1; cvt.u32.u64 %0, t; }" : "=r"(a) : "l"(p));
    return a;
}
__device__ __forceinline__ void cpa16(uint32_t dst, const void* src) {
    asm volatile("cp.async.cg.shared.global [%0], [%1], 16;" :: "r"(dst), "l"(src));
}
__device__ __forceinline__ void mma16(float (&c)[4], const uint32_t (&a)[4],
                                      uint32_t b0, uint32_t b1) {
    asm volatile(
        "mma.sync.aligned.m16n8k16.row.col.f32.f16.f16.f32 "
        "{%0,%1,%2,%3}, {%4,%5,%6,%7}, {%8,%9}, {%0,%1,%2,%3};"
        : "+f"(c[0]), "+f"(c[1]), "+f"(c[2]), "+f"(c[3])
        : "r"(a[0]), "r"(a[1]), "r"(a[2]), "r"(a[3]), "r"(b0), "r"(b1));
}
__device__ __forceinline__ void ldsm4(uint32_t (&r)[4], uint32_t addr) {
    asm volatile("ldmatrix.sync.aligned.m8n8.x4.shared.b16 {%0,%1,%2,%3}, [%4];"
                 : "=r"(r[0]), "=r"(r[1]), "=r"(r[2]), "=r"(r[3]) : "r"(addr));
}
__device__ __forceinline__ void splitpair(float x, float y, uint32_t& h, uint32_t& l) {
    __half hx = __float2half_rn(x), hy = __float2half_rn(y);
    __half lx = __float2half_rn(x - __half2float(hx));
    __half ly = __float2half_rn(y - __half2float(hy));
    __half2 hp = __halves2half2(hx, hy), lp = __halves2half2(lx, ly);
    h = *reinterpret_cast<uint32_t*>(&hp);
    l = *reinterpret_cast<uint32_t*>(&lp);
}

// ============================================================================
// f16x3 NT GEMM via mma.sync m16n8k16 + ldmatrix fragment loads.
// hi/lo split once per CTA in smem; MMA reads via ldmatrix.x4.
// EPI: 0 = raw store to part[z]; 1 = sigmoid + rowsum partial store
// ============================================================================
template<int BN, int EPI>
__global__ void __launch_bounds__(256, 2) gemm_f16(
    const float* __restrict__ A, const float* __restrict__ B, float* __restrict__ C,
    int lda, int ldb, int ldc, int nch, long long zstride, float* __restrict__ rs)
{
    constexpr int RAWS = 36;                 // raw staging row stride (floats)
    constexpr int TS   = 20;                 // f16-pair tile row stride (u32)
    constexpr int NT2  = BN / 16;
    extern __shared__ char smc[];
    float*    raw = reinterpret_cast<float*>(smc);
    uint32_t* Ahi = reinterpret_cast<uint32_t*>(smc + (128 + BN) * RAWS * 4);
    uint32_t* Alo = Ahi + 128 * TS;
    uint32_t* Bhi = Alo + 128 * TS;
    uint32_t* Blo = Bhi + BN * TS;

    const int tid  = threadIdx.x;
    const int warp = tid >> 5, lane = tid & 31;
    const int g = lane >> 2, tg = lane & 3;
    const int lr = lane & 15, lc = lane >> 4;      // ldmatrix row / col-block
    const int wm = warp >> 1, wn = warp & 1;
    const int rm = wm * 32, cn = wn * (BN / 2);
    const int bm = blockIdx.y * 128, bn = blockIdx.x * BN;
    const int kbeg = blockIdx.z * nch * 32;

    const uint32_t raw_u = smem_u32(raw);
    const uint32_t Ahi_u = smem_u32(Ahi), Alo_u = smem_u32(Alo);
    const uint32_t Bhi_u = smem_u32(Bhi), Blo_u = smem_u32(Blo);

    auto issue = [&](int c) {
        const int k0 = kbeg + c * 32;
#pragma unroll
        for (int i = 0; i < 4; i++) {
            int idx = tid + i * 256;
            int r = idx >> 3, q = idx & 7;
            cpa16(raw_u + (r * RAWS + q * 4) * 4, A + (size_t)(bm + r) * lda + k0 + q * 4);
        }
#pragma unroll
        for (int i = 0; i < BN / 32; i++) {
            int idx = tid + i * 256;
            int r = idx >> 3, q = idx & 7;
            cpa16(raw_u + ((128 + r) * RAWS + q * 4) * 4, B + (size_t)(bn + r) * ldb + k0 + q * 4);
        }
        asm volatile("cp.async.commit_group;" ::: "memory");
    };

    float acc[2][NT2][4];
#pragma unroll
    for (int mt = 0; mt < 2; mt++)
#pragma unroll
        for (int nt = 0; nt < NT2; nt++)
#pragma unroll
            for (int j = 0; j < 4; j++) acc[mt][nt][j] = 0.f;

    issue(0);
    for (int c = 0; c < nch; c++) {
        asm volatile("cp.async.wait_group 0;" ::: "memory");
        __syncthreads();

        // convert raw fp32 -> hi/lo f16-pair tiles (once per CTA)
#pragma unroll
        for (int i = 0; i < 4; i++) {
            int idx = tid + i * 256;
            int r = idx >> 3, q = idx & 7;
            float4 v = *reinterpret_cast<const float4*>(&raw[r * RAWS + q * 4]);
            uint32_t h0, l0, h1, l1;
            splitpair(v.x, v.y, h0, l0);
            splitpair(v.z, v.w, h1, l1);
            *reinterpret_cast<uint2*>(&Ahi[r * TS + 2 * q]) = make_uint2(h0, h1);
            *reinterpret_cast<uint2*>(&Alo[r * TS + 2 * q]) = make_uint2(l0, l1);
        }
#pragma unroll
        for (int i = 0; i < BN / 32; i++) {
            int idx = tid + i * 256;
            int r = idx >> 3, q = idx & 7;
            float4 v = *reinterpret_cast<const float4*>(&raw[(128 + r) * RAWS + q * 4]);
            uint32_t h0, l0, h1, l1;
            splitpair(v.x, v.y, h0, l0);
            splitpair(v.z, v.w, h1, l1);
            *reinterpret_cast<uint2*>(&Bhi[r * TS + 2 * q]) = make_uint2(h0, h1);
            *reinterpret_cast<uint2*>(&Blo[r * TS + 2 * q]) = make_uint2(l0, l1);
        }
        __syncthreads();

        if (c + 1 < nch) issue(c + 1);

#pragma unroll
        for (int ks = 0; ks < 2; ks++) {
            const int kp = ks * 8;
            // A fragments: ldmatrix.x4 per (mt, hi/lo); lane lr = row, lc = k-halfblock
            uint32_t ah[2][4], al[2][4];
#pragma unroll
            for (int mt = 0; mt < 2; mt++) {
                uint32_t off = (((rm + mt * 16 + lr) * TS) + kp + lc * 4) * 4;
                ldsm4(ah[mt], Ahi_u + off);
                ldsm4(al[mt], Alo_u + off);
            }
#pragma unroll
            for (int ntp = 0; ntp < NT2 / 2; ntp++) {
                uint32_t bh[4], bl[4];
                uint32_t boff = (((cn + ntp * 16 + lr) * TS) + kp + lc * 4) * 4;
                ldsm4(bh, Bhi_u + boff);
                ldsm4(bl, Blo_u + boff);
                // bh = [b0_even, b0_odd, b1_even, b1_odd]
#pragma unroll
                for (int e = 0; e < 2; e++) {
                    const int nt = ntp * 2 + e;
#pragma unroll
                    for (int mt = 0; mt < 2; mt++) {
                        mma16(acc[mt][nt], ah[mt], bh[e], bh[2 + e]);
                        mma16(acc[mt][nt], ah[mt], bl[e], bl[2 + e]);
                        mma16(acc[mt][nt], al[mt], bh[e], bh[2 + e]);
                    }
                }
            }
        }
    }

    // epilogue
    float* Cz = C + (size_t)blockIdx.z * zstride;
#pragma unroll
    for (int mt = 0; mt < 2; mt++) {
        const int r0 = bm + rm + mt * 16 + g;
        const int r1 = r0 + 8;
        float s0 = 0.f, s1 = 0.f;
#pragma unroll
        for (int nt = 0; nt < NT2; nt++) {
            float c0 = acc[mt][nt][0], c1 = acc[mt][nt][1];
            float c2 = acc[mt][nt][2], c3 = acc[mt][nt][3];
            if (EPI == 1) {
                c0 = 1.f / (1.f + expf(-c0)); c1 = 1.f / (1.f + expf(-c1));
                c2 = 1.f / (1.f + expf(-c2)); c3 = 1.f / (1.f + expf(-c3));
                s0 += c0 + c1; s1 += c2 + c3;
            }
            const int col = bn + cn + nt * 8 + 2 * tg;
            *reinterpret_cast<float2*>(Cz + (size_t)r0 * ldc + col) = make_float2(c0, c1);
            *reinterpret_cast<float2*>(Cz + (size_t)r1 * ldc + col) = make_float2(c2, c3);
        }
        if (EPI == 1) {
            s0 += __shfl_xor_sync(0xFFFFFFFFu, s0, 1);
            s0 += __shfl_xor_sync(0xFFFFFFFFu, s0, 2);
            s1 += __shfl_xor_sync(0xFFFFFFFFu, s1, 1);
            s1 += __shfl_xor_sync(0xFFFFFFFFu, s1, 2);
            if (tg == 0) {
                float* rp = rs + (size_t)(blockIdx.x * 2 + wn) * Nn;
                rp[r0] = s0;
                rp[r1] = s1;
            }
        }
    }
}

// ---------------- small utility kernels ----------------
__global__ void fill_zero4(float* p, size_t n4) {
    size_t i = (size_t)blockIdx.x * blockDim.x + threadIdx.x;
    if (i < n4) reinterpret_cast<float4*>(p)[i] = make_float4(0.f, 0.f, 0.f, 0.f);
}

__global__ void scatter_edges(const int* __restrict__ ei, const float* __restrict__ ew,
                              float* __restrict__ A, int E) {
    int t = blockIdx.x * blockDim.x + threadIdx.x;
    if (t < E) {
        int r = ei[t];
        int c = ei[E + t];
        atomicAdd(A + (size_t)r * Nn + c, ew[t]);
    }
}

__global__ void rowsum_kernel(const float* __restrict__ A, float* __restrict__ rs) {
    int row = blockIdx.x;
    const float4* p = reinterpret_cast<const float4*>(A + (size_t)row * Nn);
    float s = 0.f;
    for (int i = threadIdx.x; i < Nn / 4; i += blockDim.x) {
        float4 v = p[i];
        s += v.x + v.y + v.z + v.w;
    }
    __shared__ float sh[256];
    sh[threadIdx.x] = s;
    __syncthreads();
    for (int d = 128; d; d >>= 1) {
        if (threadIdx.x < d) sh[threadIdx.x] += sh[threadIdx.x + d];
        __syncthreads();
    }
    if (threadIdx.x == 0) rs[row] = sh[0];
}

__global__ void transpose_k(const float* __restrict__ in, float* __restrict__ out,
                            int R, int Cc, float scale) {
    __shared__ float t[32][33];
    int bx = blockIdx.x * 32, by = blockIdx.y * 32;
    int x = bx + threadIdx.x;
    for (int dy = 0; dy < 32; dy += 8) {
        int y = by + threadIdx.y + dy;
        if (x < Cc && y < R) t[threadIdx.y + dy][threadIdx.x] = in[(size_t)y * Cc + x];
    }
    __syncthreads();
    int xo = by + threadIdx.x;
    for (int dy = 0; dy < 32; dy += 8) {
        int yo = bx + threadIdx.y + dy;
        if (xo < R && yo < Cc) out[(size_t)yo * R + xo] = t[threadIdx.x][threadIdx.y + dy] * scale;
    }
}

// ---------------- SIMT GEMM for small-K matmuls (HW = h@gw, final out) -------
__global__ __launch_bounds__(256) void gemm_nn_splitk(
    const float* __restrict__ A, const float* __restrict__ B,
    float* __restrict__ part, int M, int Ncols, int K, int Kc)
{
    __shared__ float As[16][132];
    __shared__ float Bs[16][64];
    const int tid = threadIdx.x;
    const int tr = tid >> 4, tc = tid & 15;
    const int bm = blockIdx.y * 128, bn = blockIdx.x * 64;
    const int kbeg = blockIdx.z * Kc;

    float acc[8][4];
#pragma unroll
    for (int i = 0; i < 8; i++)
#pragma unroll
        for (int j = 0; j < 4; j++) acc[i][j] = 0.f;

    for (int k0 = kbeg; k0 < kbeg + Kc; k0 += 16) {
#pragma unroll
        for (int s = 0; s < 2; s++) {
            int slot = tid + s * 256;
            int r = slot >> 2, q = slot & 3;
            float4 va = *reinterpret_cast<const float4*>(A + (size_t)(bm + r) * K + k0 + q * 4);
            As[q * 4 + 0][r] = va.x; As[q * 4 + 1][r] = va.y;
            As[q * 4 + 2][r] = va.z; As[q * 4 + 3][r] = va.w;
        }
        {
            int r = tid >> 4, q = tid & 15;
            *reinterpret_cast<float4*>(&Bs[r][q * 4]) =
                *reinterpret_cast<const float4*>(B + (size_t)(k0 + r) * Ncols + bn + q * 4);
        }
        __syncthreads();
#pragma unroll
        for (int kk = 0; kk < 16; kk++) {
            float a[8], b[4];
            *reinterpret_cast<float4*>(&a[0]) = *reinterpret_cast<const float4*>(&As[kk][tr * 4]);
            *reinterpret_cast<float4*>(&a[4]) = *reinterpret_cast<const float4*>(&As[kk][64 + tr * 4]);
            *reinterpret_cast<float4*>(&b[0]) = *reinterpret_cast<const float4*>(&Bs[kk][tc * 4]);
#pragma unroll
            for (int i = 0; i < 8; i++)
#pragma unroll
                for (int j = 0; j < 4; j++) acc[i][j] += a[i] * b[j];
        }
        __syncthreads();
    }

    float* out = part + (size_t)blockIdx.z * M * Ncols;
#pragma unroll
    for (int i = 0; i < 8; i++) {
        int row = bm + ((i < 4) ? tr * 4 + i : 64 + tr * 4 + (i - 4));
        *reinterpret_cast<float4*>(out + (size_t)row * Ncols + bn + tc * 4) =
            make_float4(acc[i][0], acc[i][1], acc[i][2], acc[i][3]);
    }
}

__global__ void reduce_part(const float* __restrict__ part, float* __restrict__ out,
                            int M, int Ncols, int split, const float* __restrict__ bias,
                            float scale) {
    int idx = blockIdx.x * 256 + threadIdx.x;
    int total = M * Ncols;
    if (idx < total) {
        float s = 0.f;
        for (int p = 0; p < split; p++) s += part[(size_t)p * total + idx];
        s *= scale;
        if (bias) s += bias[idx % Ncols];
        out[idx] = s;
    }
}

// ---------------- attention coefficients + degree/dinv ----------------
__global__ void attention_kernel(const float* __restrict__ P0, const float* __restrict__ P1,
                                 const float* __restrict__ aw2, const float* __restrict__ ab2,
                                 const float* __restrict__ rs0, const float* __restrict__ rspart,
                                 float* __restrict__ a0o, float* __restrict__ a1o,
                                 float* __restrict__ dinv) {
    int warp = (blockIdx.x * blockDim.x + threadIdx.x) >> 5;
    int lane = threadIdx.x & 31;
    if (warp >= Nn) return;
    float s0 = 0.f, s1 = 0.f;
    for (int t = lane; t < ATT; t += 32) {
        float w2 = aw2[t];
        s0 += tanhf(P0[warp * ATT + t]) * w2;
        s1 += tanhf(P1[warp * ATT + t]) * w2;
    }
    float sr = rspart[(size_t)lane * Nn + warp] + rspart[(size_t)(lane + 32) * Nn + warp];
#pragma unroll
    for (int o = 16; o; o >>= 1) {
        s0 += __shfl_down_sync(0xFFFFFFFFu, s0, o);
        s1 += __shfl_down_sync(0xFFFFFFFFu, s1, o);
        sr += __shfl_down_sync(0xFFFFFFFFu, sr, o);
    }
    if (lane == 0) {
        float b2 = ab2[0];
        s0 += b2; s1 += b2;
        float m = fmaxf(s0, s1);
        float e0 = expf(s0 - m), e1 = expf(s1 - m);
        float inv = 1.f / (e0 + e1);
        float a0 = e0 * inv, a1 = e1 * inv;
        float deg = a0 * rs0[warp] + a1 * sr + 1.f;
        a0o[warp] = a0; a1o[warp] = a1;
        dinv[warp] = deg > 0.f ? rsqrtf(deg) : 0.f;
    }
}

// ---------------- fused A_m + final_A store + An (scaled, in place over S) --------
__global__ void build_An(const float* __restrict__ Ao, float* __restrict__ S,
                         const float* __restrict__ a0, const float* __restrict__ a1,
                         const float* __restrict__ dinv, float* __restrict__ finalA) {
    size_t gid = (size_t)blockIdx.x * blockDim.x + threadIdx.x;
    if (gid >= (size_t)Nn * Nn / 4) return;
    int i  = (int)(gid / (Nn / 4));
    int j4 = (int)(gid % (Nn / 4)) * 4;
    float4 o = *reinterpret_cast<const float4*>(Ao + (size_t)i * Nn + j4);
    float4 s = *reinterpret_cast<const float4*>(S  + (size_t)i * Nn + j4);
    float A0 = a0[i], A1 = a1[i], di = dinv[i] * SCALE_AN;
    float4 am;
    am.x = A0 * o.x + A1 * s.x;
    am.y = A0 * o.y + A1 * s.y;
    am.z = A0 * o.z + A1 * s.z;
    am.w = A0 * o.w + A1 * s.w;
    if (finalA) *reinterpret_cast<float4*>(finalA + (size_t)i * Nn + j4) = am;
    float4 dj = *reinterpret_cast<const float4*>(dinv + j4);
    float4 an;
    an.x = di * dj.x * (am.x + ((j4 + 0 == i) ? 1.f : 0.f));
    an.y = di * dj.y * (am.y + ((j4 + 1 == i) ? 1.f : 0.f));
    an.z = di * dj.z * (am.z + ((j4 + 2 == i) ? 1.f : 0.f));
    an.w = di * dj.w * (am.w + ((j4 + 3 == i) ? 1.f : 0.f));
    *reinterpret_cast<float4*>(S + (size_t)i * Nn + j4) = an;
}

// ---------------- BatchNorm (two-pass) ----------------
__global__ void bn_stats(const float* __restrict__ H, int dout,
                         float* __restrict__ mu, float* __restrict__ var) {
    int col = blockIdx.x * 32 + threadIdx.x;
    __shared__ float sh[8][32];
    __shared__ float shm[32];

    float s = 0.f;
    for (int r = threadIdx.y; r < Nn; r += 8)
        s += H[(size_t)r * dout + col];
    sh[threadIdx.y][threadIdx.x] = s;
    __syncthreads();
    if (threadIdx.y == 0) {
#pragma unroll
        for (int y = 1; y < 8; y++) s += sh[y][threadIdx.x];
        shm[threadIdx.x] = s / (float)Nn;
    }
    __syncthreads();
    float m = shm[threadIdx.x];

    float s2 = 0.f;
    for (int r = threadIdx.y; r < Nn; r += 8) {
        float d = H[(size_t)r * dout + col] - m;
        s2 += d * d;
    }
    __syncthreads();
    sh[threadIdx.y][threadIdx.x] = s2;
    __syncthreads();
    if (threadIdx.y == 0) {
#pragma unroll
        for (int y = 1; y < 8; y++) s2 += sh[y][threadIdx.x];
        mu[col]  = m;
        var[col] = s2 / (float)Nn;
    }
}

__global__ void bn_apply(const float* __restrict__ Hin, float* __restrict__ Hout, int dout,
                         const float* __restrict__ mu, const float* __restrict__ var,
                         const float* __restrict__ gamma, const float* __restrict__ beta) {
    int idx = blockIdx.x * 256 + threadIdx.x;
    if (idx < Nn * dout) {
        int c = idx % dout;
        float x = Hin[idx];
        float y = gamma[c] * (x - mu[c]) * rsqrtf(var[c] + 1e-5f) + beta[c];
        Hout[idx] = y > 0.f ? y : 0.01f * y;
    }
}

// ---------------- host orchestration ----------------
extern "C" void kernel_launch(void* const* d_in, const int* in_sizes, int n_in,
                              void* d_out, int out_size) {
    const float* X  = (const float*)d_in[0];
    const int*   ei = (const int*)d_in[1];
    const float* ew = (const float*)d_in[2];
    const float *gw[3], *gb[3], *bng[3], *bnb[3], *aw1[3], *ab1[3], *aw2[3], *ab2[3];
    for (int i = 0; i < 3; i++) {
        int b = 3 + i * 8;
        gw[i]  = (const float*)d_in[b + 0];
        gb[i]  = (const float*)d_in[b + 1];
        bng[i] = (const float*)d_in[b + 2];
        bnb[i] = (const float*)d_in[b + 3];
        aw1[i] = (const float*)d_in[b + 4];
        ab1[i] = (const float*)d_in[b + 5];
        aw2[i] = (const float*)d_in[b + 6];
        ab2[i] = (const float*)d_in[b + 7];
    }
    const float* lw = (const float*)d_in[27];
    const float* lb = (const float*)d_in[28];
    const int E = in_sizes[2];

    float *Ao, *Am, *H, *H2, *HW, *HWT, *AWT, *part, *P0, *P1, *rspart,
          *a0, *a1, *dinv, *rs0, *mu, *var;
    cudaGetSymbolAddress((void**)&Ao,     g_Aorig);
    cudaGetSymbolAddress((void**)&Am,     g_A);
    cudaGetSymbolAddress((void**)&H,      g_H);
    cudaGetSymbolAddress((void**)&H2,     g_H2);
    cudaGetSymbolAddress((void**)&HW,     g_HW);
    cudaGetSymbolAddress((void**)&HWT,    g_HWT);
    cudaGetSymbolAddress((void**)&AWT,    g_AWT);
    cudaGetSymbolAddress((void**)&part,   g_part);
    cudaGetSymbolAddress((void**)&P0,     g_P0);
    cudaGetSymbolAddress((void**)&P1,     g_P1);
    cudaGetSymbolAddress((void**)&rspart, g_rspart);
    cudaGetSymbolAddress((void**)&a0,     g_a0);
    cudaGetSymbolAddress((void**)&a1,     g_a1);
    cudaGetSymbolAddress((void**)&dinv,   g_dinv);
    cudaGetSymbolAddress((void**)&rs0,    g_rs0);
    cudaGetSymbolAddress((void**)&mu,     g_mu);
    cudaGetSymbolAddress((void**)&var,    g_var);

    const int SM128 = (256 * 36 * 4) + (512 * 20 * 4);   // 77824
    const int SM64  = (192 * 36 * 4) + (384 * 20 * 4);   // 58368
    cudaFuncSetAttribute(gemm_f16<128, 1>, cudaFuncAttributeMaxDynamicSharedMemorySize, SM128);
    cudaFuncSetAttribute(gemm_f16<128, 0>, cudaFuncAttributeMaxDynamicSharedMemorySize, SM128);
    cudaFuncSetAttribute(gemm_f16<64, 0>,  cudaFuncAttributeMaxDynamicSharedMemorySize, SM64);

    // A_orig = scatter(edge_w); rs0 = rowsum(A_orig)
    fill_zero4<<<(int)(((size_t)Nn * Nn / 4 + 255) / 256), 256>>>(Ao, (size_t)Nn * Nn / 4);
    scatter_edges<<<(E + 255) / 256, 256>>>(ei, ew, Ao, E);
    rowsum_kernel<<<Nn, 256>>>(Ao, rs0);

    const float* h = X;
    const int din[3] = {256, 256, 256};
    const int dof[3] = {256, 256, 128};

    for (int L = 0; L < 3; L++) {
        const int K = din[L], dout = dof[L];

        // S = sigmoid(h @ h^T), rowsum partials -> rspart
        gemm_f16<128, 1><<<dim3(32, 32, 1), 256, SM128>>>(
            h, h, Am, K, K, Nn, K / 32, 0LL, rspart);

        // attention projections: P = [Ao|S] @ (64*aw1) / 64 + ab1  (split-K 8)
        transpose_k<<<dim3(2, Nn / 32), dim3(32, 8)>>>(aw1[L], AWT, Nn, ATT, SCALE_AW);
        gemm_f16<64, 0><<<dim3(1, 32, 8), 256, SM64>>>(
            Ao, AWT, part, Nn, Nn, ATT, (Nn / 32) / 8, (long long)Nn * ATT, nullptr);
        reduce_part<<<(Nn * ATT + 255) / 256, 256>>>(part, P0, Nn, ATT, 8, ab1[L], 1.f / SCALE_AW);
        gemm_f16<64, 0><<<dim3(1, 32, 8), 256, SM64>>>(
            Am, AWT, part, Nn, Nn, ATT, (Nn / 32) / 8, (long long)Nn * ATT, nullptr);
        reduce_part<<<(Nn * ATT + 255) / 256, 256>>>(part, P1, Nn, ATT, 8, ab1[L], 1.f / SCALE_AW);

        attention_kernel<<<Nn / 4, 128>>>(P0, P1, aw2[L], ab2[L], rs0, rspart, a0, a1, dinv);

        // HW = h @ gw (SIMT, K=256), then HWT = HW^T
        gemm_nn_splitk<<<dim3(dout / 64, 32, 1), 256>>>(h, gw[L], part, Nn, dout, K, K);
        reduce_part<<<(Nn * dout + 255) / 256, 256>>>(part, HW, Nn, dout, 1, nullptr, 1.f);
        transpose_k<<<dim3(dout / 32, Nn / 32), dim3(32, 8)>>>(HW, HWT, Nn, dout, 1.f);

        // Build An (scaled) in place; stream final_A on last layer
        float* finalA = nullptr;
        if (L == 2 && out_size >= Nn * OUTD + Nn * Nn)
            finalA = (float*)d_out + (size_t)Nn * OUTD;
        build_An<<<16384, 256>>>(Ao, Am, a0, a1, dinv, finalA);

        // H2 = (An_scaled @ HW) / SCALE_AN + gb
        const int zsp = (dout == 256) ? 4 : 8;
        gemm_f16<128, 0><<<dim3(dout / 128, 32, zsp), 256, SM128>>>(
            Am, HWT, part, Nn, Nn, dout, (Nn / 32) / zsp, (long long)Nn * dout, nullptr);
        reduce_part<<<(Nn * dout + 255) / 256, 256>>>(part, H2, Nn, dout, zsp, gb[L], 1.f / SCALE_AN);

        // BatchNorm + LeakyReLU -> H
        bn_stats<<<dout / 32, dim3(32, 8)>>>(H2, dout, mu, var);
        bn_apply<<<(Nn * dout + 255) / 256, 256>>>(H2, H, dout, mu, var, bng[L], bnb[L]);
        h = H;
    }

    // out = h @ lin_w + lin_b (K=128, SIMT)
    gemm_nn_splitk<<<dim3(1, 32, 1), 256>>>(h, lw, part, Nn, OUTD, 128, 128);
    reduce_part<<<(Nn * OUTD + 255) / 256, 256>>>(part, (float*)d_out, Nn, OUTD, 1, lb, 1.f);
}

// round 10
// speedup vs baseline: 1.0613x; 1.0613x over previous
#include <cuda_runtime.h>
#include <cuda_fp16.h>
#include <math.h>
#include <stdint.h>

constexpr int Nn  = 4096;
constexpr int ATT = 64;
constexpr int OUTD = 64;
constexpr float SCALE_AN = 16384.f;
constexpr float SCALE_AW = 64.f;

// ---------------- scratch (device globals; no allocation allowed) ----------------
__device__ float  g_Aorig[(size_t)Nn * Nn];
__device__ __half g_Aoh[(size_t)Nn * Nn];
__device__ __half g_Aol[(size_t)Nn * Nn];
__device__ __half g_Sh[(size_t)Nn * Nn];
__device__ __half g_Sl[(size_t)Nn * Nn];
__device__ float  g_H [Nn * 256];
__device__ float  g_H2[Nn * 256];
__device__ float  g_HW[Nn * 256];
__device__ __half g_hh[Nn * 256];
__device__ __half g_hl[Nn * 256];
__device__ __half g_HWTh[256 * Nn];
__device__ __half g_HWTl[256 * Nn];
__device__ __half g_AWTh[64 * Nn];
__device__ __half g_AWTl[64 * Nn];
__device__ float  g_part[(size_t)8 * Nn * 256];
__device__ float  g_P0[Nn * ATT];
__device__ float  g_P1[Nn * ATT];
__device__ float  g_rspart[64 * Nn];
__device__ float  g_a0[Nn], g_a1[Nn], g_dinv[Nn];
__device__ float  g_rs0[Nn];
__device__ float  g_mu[256], g_var[256];

// ---------------- helpers ----------------
__device__ __forceinline__ uint32_t smem_u32(const void* p) {
    uint32_t a;
    asm("{ .reg .u64 t; cvta.to.shared.u64 t, %1; cvt.u32.u64 %0, t; }" : "=r"(a) : "l"(p));
    return a;
}
__device__ __forceinline__ void cpa16(uint32_t dst, const void* src) {
    asm volatile("cp.async.cg.shared.global [%0], [%1], 16;" :: "r"(dst), "l"(src));
}
__device__ __forceinline__ void mma16(float (&c)[4], const uint32_t (&a)[4],
                                      uint32_t b0, uint32_t b1) {
    asm volatile(
        "mma.sync.aligned.m16n8k16.row.col.f32.f16.f16.f32 "
        "{%0,%1,%2,%3}, {%4,%5,%6,%7}, {%8,%9}, {%0,%1,%2,%3};"
        : "+f"(c[0]), "+f"(c[1]), "+f"(c[2]), "+f"(c[3])
        : "r"(a[0]), "r"(a[1]), "r"(a[2]), "r"(a[3]), "r"(b0), "r"(b1));
}
__device__ __forceinline__ void splitpair(float x, float y, uint32_t& h, uint32_t& l) {
    __half hx = __float2half_rn(x), hy = __float2half_rn(y);
    __half lx = __float2half_rn(x - __half2float(hx));
    __half ly = __float2half_rn(y - __half2float(hy));
    __half2 hp = __halves2half2(hx, hy), lp = __halves2half2(lx, ly);
    h = *reinterpret_cast<uint32_t*>(&hp);
    l = *reinterpret_cast<uint32_t*>(&lp);
}
__device__ __forceinline__ void split1(float x, __half& h, __half& l) {
    h = __float2half_rn(x);
    l = __float2half_rn(x - __half2float(h));
}

// ============================================================================
// f16x3 NT GEMM, pre-split hi/lo f16 operands, double-buffered cp.async.
// C[M,BN] = (Ah+Al)[M,K] * (Bh+Bl)[N,K]^T via 3-term mma (hh + hl + lh).
// EPI: 0 = f32 store to part[z]; 1 = sigmoid -> f16 hi/lo store + rowsum partials
// ============================================================================
template<int BN, int EPI>
__global__ void __launch_bounds__(256, 2) gemm_f16(
    const __half* __restrict__ Ah, const __half* __restrict__ Al,
    const __half* __restrict__ Bh, const __half* __restrict__ Bl,
    float* __restrict__ C, int lda, int ldb, int ldc, int nch,
    long long zstride, float* __restrict__ rs,
    __half* __restrict__ oh, __half* __restrict__ ol)
{
    constexpr int TS   = 20;                 // u32 stride per row (16 data + 4 pad)
    constexpr int NT2  = BN / 16;
    constexpr int ABUF = 128 * TS;
    constexpr int BBUF = BN * TS;
    constexpr int BUFSZ = 2 * ABUF + 2 * BBUF;
    extern __shared__ uint32_t smu[];

    const int tid  = threadIdx.x;
    const int warp = tid >> 5, lane = tid & 31;
    const int g = lane >> 2, tg = lane & 3;
    const int wm = warp >> 1, wn = warp & 1;
    const int rm = wm * 32, cn = wn * (BN / 2);
    const int bm = blockIdx.y * 128, bn = blockIdx.x * BN;
    const int kbeg = blockIdx.z * nch * 32;

    const uint32_t smu_u = smem_u32(smu);

    auto issue = [&](int c) {
        const int b = c & 1;
        const int k0 = kbeg + c * 32;
        const uint32_t base = smu_u + b * BUFSZ * 4;
#pragma unroll
        for (int i = 0; i < 2; i++) {                    // A: 128 rows x 4 chunks
            int idx = tid + i * 256;
            int r = idx >> 2, q = idx & 3;
            const size_t go = (size_t)(bm + r) * lda + k0 + q * 8;
            cpa16(base + (r * TS + q * 4) * 4, Ah + go);
            cpa16(base + (ABUF + r * TS + q * 4) * 4, Al + go);
        }
#pragma unroll
        for (int i = 0; i < BN / 64; i++) {              // B: BN rows x 4 chunks
            int idx = tid + i * 256;
            int r = idx >> 2, q = idx & 3;
            const size_t go = (size_t)(bn + r) * ldb + k0 + q * 8;
            cpa16(base + (2 * ABUF + r * TS + q * 4) * 4, Bh + go);
            cpa16(base + (2 * ABUF + BBUF + r * TS + q * 4) * 4, Bl + go);
        }
        asm volatile("cp.async.commit_group;" ::: "memory");
    };

    float acc[2][NT2][4];
#pragma unroll
    for (int mt = 0; mt < 2; mt++)
#pragma unroll
        for (int nt = 0; nt < NT2; nt++)
#pragma unroll
            for (int j = 0; j < 4; j++) acc[mt][nt][j] = 0.f;

    issue(0);
    for (int c = 0; c < nch; c++) {
        if (c + 1 < nch) {
            issue(c + 1);
            asm volatile("cp.async.wait_group 1;" ::: "memory");
        } else {
            asm volatile("cp.async.wait_group 0;" ::: "memory");
        }
        __syncthreads();

        const uint32_t* Athi = smu + (c & 1) * BUFSZ;
        const uint32_t* Atlo = Athi + ABUF;
        const uint32_t* Bthi = Athi + 2 * ABUF;
        const uint32_t* Btlo = Bthi + BBUF;

#pragma unroll
        for (int ks = 0; ks < 2; ks++) {
            const int kp = ks * 8;
            uint32_t ah[2][4], al[2][4];
#pragma unroll
            for (int mt = 0; mt < 2; mt++) {
                const int ro = (rm + mt * 16 + g) * TS;
                ah[mt][0] = Athi[ro + kp + tg];
                ah[mt][1] = Athi[ro + 8 * TS + kp + tg];
                ah[mt][2] = Athi[ro + kp + tg + 4];
                ah[mt][3] = Athi[ro + 8 * TS + kp + tg + 4];
                al[mt][0] = Atlo[ro + kp + tg];
                al[mt][1] = Atlo[ro + 8 * TS + kp + tg];
                al[mt][2] = Atlo[ro + kp + tg + 4];
                al[mt][3] = Atlo[ro + 8 * TS + kp + tg + 4];
            }
#pragma unroll
            for (int nt = 0; nt < NT2; nt++) {
                const int bo = (cn + nt * 8 + g) * TS + kp;
                uint32_t bh0 = Bthi[bo + tg], bh1 = Bthi[bo + tg + 4];
                uint32_t bl0 = Btlo[bo + tg], bl1 = Btlo[bo + tg + 4];
#pragma unroll
                for (int mt = 0; mt < 2; mt++) {
                    mma16(acc[mt][nt], ah[mt], bh0, bh1);
                    mma16(acc[mt][nt], ah[mt], bl0, bl1);
                    mma16(acc[mt][nt], al[mt], bh0, bh1);
                }
            }
        }
        __syncthreads();
    }

    // epilogue
#pragma unroll
    for (int mt = 0; mt < 2; mt++) {
        const int r0 = bm + rm + mt * 16 + g;
        const int r1 = r0 + 8;
        float s0 = 0.f, s1 = 0.f;
#pragma unroll
        for (int nt = 0; nt < NT2; nt++) {
            float c0 = acc[mt][nt][0], c1 = acc[mt][nt][1];
            float c2 = acc[mt][nt][2], c3 = acc[mt][nt][3];
            const int col = bn + cn + nt * 8 + 2 * tg;
            if (EPI == 1) {
                c0 = 1.f / (1.f + expf(-c0)); c1 = 1.f / (1.f + expf(-c1));
                c2 = 1.f / (1.f + expf(-c2)); c3 = 1.f / (1.f + expf(-c3));
                s0 += c0 + c1; s1 += c2 + c3;
                uint32_t h01, l01, h23, l23;
                splitpair(c0, c1, h01, l01);
                splitpair(c2, c3, h23, l23);
                *reinterpret_cast<uint32_t*>(oh + (size_t)r0 * ldc + col) = h01;
                *reinterpret_cast<uint32_t*>(ol + (size_t)r0 * ldc + col) = l01;
                *reinterpret_cast<uint32_t*>(oh + (size_t)r1 * ldc + col) = h23;
                *reinterpret_cast<uint32_t*>(ol + (size_t)r1 * ldc + col) = l23;
            } else {
                float* Cz = C + (size_t)blockIdx.z * zstride;
                *reinterpret_cast<float2*>(Cz + (size_t)r0 * ldc + col) = make_float2(c0, c1);
                *reinterpret_cast<float2*>(Cz + (size_t)r1 * ldc + col) = make_float2(c2, c3);
            }
        }
        if (EPI == 1) {
            s0 += __shfl_xor_sync(0xFFFFFFFFu, s0, 1);
            s0 += __shfl_xor_sync(0xFFFFFFFFu, s0, 2);
            s1 += __shfl_xor_sync(0xFFFFFFFFu, s1, 1);
            s1 += __shfl_xor_sync(0xFFFFFFFFu, s1, 2);
            if (tg == 0) {
                float* rp = rs + (size_t)(blockIdx.x * 2 + wn) * Nn;
                rp[r0] = s0;
                rp[r1] = s1;
            }
        }
    }
}

// ---------------- conversion / utility kernels ----------------
__global__ void conv_split(const float* __restrict__ in, __half* __restrict__ oh,
                           __half* __restrict__ ol, size_t n4) {
    size_t i = (size_t)blockIdx.x * blockDim.x + threadIdx.x;
    if (i >= n4) return;
    float4 v = reinterpret_cast<const float4*>(in)[i];
    uint32_t h01, l01, h23, l23;
    splitpair(v.x, v.y, h01, l01);
    splitpair(v.z, v.w, h23, l23);
    reinterpret_cast<uint2*>(oh)[i] = make_uint2(h01, h23);
    reinterpret_cast<uint2*>(ol)[i] = make_uint2(l01, l23);
}

__global__ void fill_zero4(float* p, size_t n4) {
    size_t i = (size_t)blockIdx.x * blockDim.x + threadIdx.x;
    if (i < n4) reinterpret_cast<float4*>(p)[i] = make_float4(0.f, 0.f, 0.f, 0.f);
}

__global__ void scatter_edges(const int* __restrict__ ei, const float* __restrict__ ew,
                              float* __restrict__ A, int E) {
    int t = blockIdx.x * blockDim.x + threadIdx.x;
    if (t < E) {
        int r = ei[t];
        int c = ei[E + t];
        atomicAdd(A + (size_t)r * Nn + c, ew[t]);
    }
}

__global__ void rowsum_kernel(const float* __restrict__ A, float* __restrict__ rs) {
    int row = blockIdx.x;
    const float4* p = reinterpret_cast<const float4*>(A + (size_t)row * Nn);
    float s = 0.f;
    for (int i = threadIdx.x; i < Nn / 4; i += blockDim.x) {
        float4 v = p[i];
        s += v.x + v.y + v.z + v.w;
    }
    __shared__ float sh[256];
    sh[threadIdx.x] = s;
    __syncthreads();
    for (int d = 128; d; d >>= 1) {
        if (threadIdx.x < d) sh[threadIdx.x] += sh[threadIdx.x + d];
        __syncthreads();
    }
    if (threadIdx.x == 0) rs[row] = sh[0];
}

__global__ void transpose_f16(const float* __restrict__ in, __half* __restrict__ oh,
                              __half* __restrict__ ol, int R, int Cc, float scale) {
    __shared__ float t[32][33];
    int bx = blockIdx.x * 32, by = blockIdx.y * 32;
    int x = bx + threadIdx.x;
    for (int dy = 0; dy < 32; dy += 8) {
        int y = by + threadIdx.y + dy;
        if (x < Cc && y < R) t[threadIdx.y + dy][threadIdx.x] = in[(size_t)y * Cc + x];
    }
    __syncthreads();
    int xo = by + threadIdx.x;
    for (int dy = 0; dy < 32; dy += 8) {
        int yo = bx + threadIdx.y + dy;
        if (xo < R && yo < Cc) {
            float v = t[threadIdx.x][threadIdx.y + dy] * scale;
            __half h, l;
            split1(v, h, l);
            oh[(size_t)yo * R + xo] = h;
            ol[(size_t)yo * R + xo] = l;
        }
    }
}

// ---------------- SIMT GEMM for small-K matmuls (HW = h@gw, final out) -------
__global__ __launch_bounds__(256) void gemm_nn_splitk(
    const float* __restrict__ A, const float* __restrict__ B,
    float* __restrict__ part, int M, int Ncols, int K, int Kc)
{
    __shared__ float As[16][132];
    __shared__ float Bs[16][64];
    const int tid = threadIdx.x;
    const int tr = tid >> 4, tc = tid & 15;
    const int bm = blockIdx.y * 128, bn = blockIdx.x * 64;
    const int kbeg = blockIdx.z * Kc;

    float acc[8][4];
#pragma unroll
    for (int i = 0; i < 8; i++)
#pragma unroll
        for (int j = 0; j < 4; j++) acc[i][j] = 0.f;

    for (int k0 = kbeg; k0 < kbeg + Kc; k0 += 16) {
#pragma unroll
        for (int s = 0; s < 2; s++) {
            int slot = tid + s * 256;
            int r = slot >> 2, q = slot & 3;
            float4 va = *reinterpret_cast<const float4*>(A + (size_t)(bm + r) * K + k0 + q * 4);
            As[q * 4 + 0][r] = va.x; As[q * 4 + 1][r] = va.y;
            As[q * 4 + 2][r] = va.z; As[q * 4 + 3][r] = va.w;
        }
        {
            int r = tid >> 4, q = tid & 15;
            *reinterpret_cast<float4*>(&Bs[r][q * 4]) =
                *reinterpret_cast<const float4*>(B + (size_t)(k0 + r) * Ncols + bn + q * 4);
        }
        __syncthreads();
#pragma unroll
        for (int kk = 0; kk < 16; kk++) {
            float a[8], b[4];
            *reinterpret_cast<float4*>(&a[0]) = *reinterpret_cast<const float4*>(&As[kk][tr * 4]);
            *reinterpret_cast<float4*>(&a[4]) = *reinterpret_cast<const float4*>(&As[kk][64 + tr * 4]);
            *reinterpret_cast<float4*>(&b[0]) = *reinterpret_cast<const float4*>(&Bs[kk][tc * 4]);
#pragma unroll
            for (int i = 0; i < 8; i++)
#pragma unroll
                for (int j = 0; j < 4; j++) acc[i][j] += a[i] * b[j];
        }
        __syncthreads();
    }

    float* out = part + (size_t)blockIdx.z * M * Ncols;
#pragma unroll
    for (int i = 0; i < 8; i++) {
        int row = bm + ((i < 4) ? tr * 4 + i : 64 + tr * 4 + (i - 4));
        *reinterpret_cast<float4*>(out + (size_t)row * Ncols + bn + tc * 4) =
            make_float4(acc[i][0], acc[i][1], acc[i][2], acc[i][3]);
    }
}

__global__ void reduce_part(const float* __restrict__ part, float* __restrict__ out,
                            int M, int Ncols, int split, const float* __restrict__ bias,
                            float scale) {
    int idx = blockIdx.x * 256 + threadIdx.x;
    int total = M * Ncols;
    if (idx < total) {
        float s = 0.f;
        for (int p = 0; p < split; p++) s += part[(size_t)p * total + idx];
        s *= scale;
        if (bias) s += bias[idx % Ncols];
        out[idx] = s;
    }
}

// ---------------- attention coefficients + degree/dinv ----------------
__global__ void attention_kernel(const float* __restrict__ P0, const float* __restrict__ P1,
                                 const float* __restrict__ aw2, const float* __restrict__ ab2,
                                 const float* __restrict__ rs0, const float* __restrict__ rspart,
                                 float* __restrict__ a0o, float* __restrict__ a1o,
                                 float* __restrict__ dinv) {
    int warp = (blockIdx.x * blockDim.x + threadIdx.x) >> 5;
    int lane = threadIdx.x & 31;
    if (warp >= Nn) return;
    float s0 = 0.f, s1 = 0.f;
    for (int t = lane; t < ATT; t += 32) {
        float w2 = aw2[t];
        s0 += tanhf(P0[warp * ATT + t]) * w2;
        s1 += tanhf(P1[warp * ATT + t]) * w2;
    }
    float sr = rspart[(size_t)lane * Nn + warp] + rspart[(size_t)(lane + 32) * Nn + warp];
#pragma unroll
    for (int o = 16; o; o >>= 1) {
        s0 += __shfl_down_sync(0xFFFFFFFFu, s0, o);
        s1 += __shfl_down_sync(0xFFFFFFFFu, s1, o);
        sr += __shfl_down_sync(0xFFFFFFFFu, sr, o);
    }
    if (lane == 0) {
        float b2 = ab2[0];
        s0 += b2; s1 += b2;
        float m = fmaxf(s0, s1);
        float e0 = expf(s0 - m), e1 = expf(s1 - m);
        float inv = 1.f / (e0 + e1);
        float a0 = e0 * inv, a1 = e1 * inv;
        float deg = a0 * rs0[warp] + a1 * sr + 1.f;
        a0o[warp] = a0; a1o[warp] = a1;
        dinv[warp] = deg > 0.f ? rsqrtf(deg) : 0.f;
    }
}

// ---------------- A_m + final_A + An (f16 pairs in place over S) ----------------
__global__ void build_An(const float* __restrict__ Ao, __half* __restrict__ Sh,
                         __half* __restrict__ Sl,
                         const float* __restrict__ a0, const float* __restrict__ a1,
                         const float* __restrict__ dinv, float* __restrict__ finalA) {
    size_t gid = (size_t)blockIdx.x * blockDim.x + threadIdx.x;
    if (gid >= (size_t)Nn * Nn / 4) return;
    int i  = (int)(gid / (Nn / 4));
    int j4 = (int)(gid % (Nn / 4)) * 4;
    float4 o = *reinterpret_cast<const float4*>(Ao + (size_t)i * Nn + j4);
    uint2 shv = *reinterpret_cast<const uint2*>(Sh + (size_t)i * Nn + j4);
    uint2 slv = *reinterpret_cast<const uint2*>(Sl + (size_t)i * Nn + j4);
    __half2 h01 = *reinterpret_cast<__half2*>(&shv.x), h23 = *reinterpret_cast<__half2*>(&shv.y);
    __half2 l01 = *reinterpret_cast<__half2*>(&slv.x), l23 = *reinterpret_cast<__half2*>(&slv.y);
    float4 s;
    s.x = __half2float(__low2half(h01)) + __half2float(__low2half(l01));
    s.y = __half2float(__high2half(h01)) + __half2float(__high2half(l01));
    s.z = __half2float(__low2half(h23)) + __half2float(__low2half(l23));
    s.w = __half2float(__high2half(h23)) + __half2float(__high2half(l23));
    float A0 = a0[i], A1 = a1[i], di = dinv[i] * SCALE_AN;
    float4 am;
    am.x = A0 * o.x + A1 * s.x;
    am.y = A0 * o.y + A1 * s.y;
    am.z = A0 * o.z + A1 * s.z;
    am.w = A0 * o.w + A1 * s.w;
    if (finalA) *reinterpret_cast<float4*>(finalA + (size_t)i * Nn + j4) = am;
    float4 dj = *reinterpret_cast<const float4*>(dinv + j4);
    float4 an;
    an.x = di * dj.x * (am.x + ((j4 + 0 == i) ? 1.f : 0.f));
    an.y = di * dj.y * (am.y + ((j4 + 1 == i) ? 1.f : 0.f));
    an.z = di * dj.z * (am.z + ((j4 + 2 == i) ? 1.f : 0.f));
    an.w = di * dj.w * (am.w + ((j4 + 3 == i) ? 1.f : 0.f));
    uint32_t nh01, nl01, nh23, nl23;
    splitpair(an.x, an.y, nh01, nl01);
    splitpair(an.z, an.w, nh23, nl23);
    *reinterpret_cast<uint2*>(Sh + (size_t)i * Nn + j4) = make_uint2(nh01, nh23);
    *reinterpret_cast<uint2*>(Sl + (size_t)i * Nn + j4) = make_uint2(nl01, nl23);
}

// ---------------- BatchNorm (two-pass) ----------------
__global__ void bn_stats(const float* __restrict__ H, int dout,
                         float* __restrict__ mu, float* __restrict__ var) {
    int col = blockIdx.x * 32 + threadIdx.x;
    __shared__ float sh[8][32];
    __shared__ float shm[32];

    float s = 0.f;
    for (int r = threadIdx.y; r < Nn; r += 8)
        s += H[(size_t)r * dout + col];
    sh[threadIdx.y][threadIdx.x] = s;
    __syncthreads();
    if (threadIdx.y == 0) {
#pragma unroll
        for (int y = 1; y < 8; y++) s += sh[y][threadIdx.x];
        shm[threadIdx.x] = s / (float)Nn;
    }
    __syncthreads();
    float m = shm[threadIdx.x];

    float s2 = 0.f;
    for (int r = threadIdx.y; r < Nn; r += 8) {
        float d = H[(size_t)r * dout + col] - m;
        s2 += d * d;
    }
    __syncthreads();
    sh[threadIdx.y][threadIdx.x] = s2;
    __syncthreads();
    if (threadIdx.y == 0) {
#pragma unroll
        for (int y = 1; y < 8; y++) s2 += sh[y][threadIdx.x];
        mu[col]  = m;
        var[col] = s2 / (float)Nn;
    }
}

// BN + LeakyReLU; writes f32 H and f16 hi/lo for the next sigmoid GEMM
__global__ void bn_apply(const float* __restrict__ Hin, float* __restrict__ Hout,
                         __half* __restrict__ oh, __half* __restrict__ ol, int dout,
                         const float* __restrict__ mu, const float* __restrict__ var,
                         const float* __restrict__ gamma, const float* __restrict__ beta) {
    int idx = blockIdx.x * 256 + threadIdx.x;
    if (idx < Nn * dout) {
        int c = idx % dout;
        float x = Hin[idx];
        float y = gamma[c] * (x - mu[c]) * rsqrtf(var[c] + 1e-5f) + beta[c];
        y = y > 0.f ? y : 0.01f * y;
        Hout[idx] = y;
        __half h, l;
        split1(y, h, l);
        oh[idx] = h;
        ol[idx] = l;
    }
}

// ---------------- host orchestration ----------------
extern "C" void kernel_launch(void* const* d_in, const int* in_sizes, int n_in,
                              void* d_out, int out_size) {
    const float* X  = (const float*)d_in[0];
    const int*   ei = (const int*)d_in[1];
    const float* ew = (const float*)d_in[2];
    const float *gw[3], *gb[3], *bng[3], *bnb[3], *aw1[3], *ab1[3], *aw2[3], *ab2[3];
    for (int i = 0; i < 3; i++) {
        int b = 3 + i * 8;
        gw[i]  = (const float*)d_in[b + 0];
        gb[i]  = (const float*)d_in[b + 1];
        bng[i] = (const float*)d_in[b + 2];
        bnb[i] = (const float*)d_in[b + 3];
        aw1[i] = (const float*)d_in[b + 4];
        ab1[i] = (const float*)d_in[b + 5];
        aw2[i] = (const float*)d_in[b + 6];
        ab2[i] = (const float*)d_in[b + 7];
    }
    const float* lw = (const float*)d_in[27];
    const float* lb = (const float*)d_in[28];
    const int E = in_sizes[2];

    float *Ao, *H, *H2, *HW, *part, *P0, *P1, *rspart, *a0, *a1, *dinv, *rs0, *mu, *var;
    __half *Aoh, *Aol, *Sh, *Sl, *hh, *hl, *HWTh, *HWTl, *AWTh, *AWTl;
    cudaGetSymbolAddress((void**)&Ao,     g_Aorig);
    cudaGetSymbolAddress((void**)&Aoh,    g_Aoh);
    cudaGetSymbolAddress((void**)&Aol,    g_Aol);
    cudaGetSymbolAddress((void**)&Sh,     g_Sh);
    cudaGetSymbolAddress((void**)&Sl,     g_Sl);
    cudaGetSymbolAddress((void**)&H,      g_H);
    cudaGetSymbolAddress((void**)&H2,     g_H2);
    cudaGetSymbolAddress((void**)&HW,     g_HW);
    cudaGetSymbolAddress((void**)&hh,     g_hh);
    cudaGetSymbolAddress((void**)&hl,     g_hl);
    cudaGetSymbolAddress((void**)&HWTh,   g_HWTh);
    cudaGetSymbolAddress((void**)&HWTl,   g_HWTl);
    cudaGetSymbolAddress((void**)&AWTh,   g_AWTh);
    cudaGetSymbolAddress((void**)&AWTl,   g_AWTl);
    cudaGetSymbolAddress((void**)&part,   g_part);
    cudaGetSymbolAddress((void**)&P0,     g_P0);
    cudaGetSymbolAddress((void**)&P1,     g_P1);
    cudaGetSymbolAddress((void**)&rspart, g_rspart);
    cudaGetSymbolAddress((void**)&a0,     g_a0);
    cudaGetSymbolAddress((void**)&a1,     g_a1);
    cudaGetSymbolAddress((void**)&dinv,   g_dinv);
    cudaGetSymbolAddress((void**)&rs0,    g_rs0);
    cudaGetSymbolAddress((void**)&mu,     g_mu);
    cudaGetSymbolAddress((void**)&var,    g_var);

    // dynamic smem: 2 buffers x (2*128 + 2*BN) rows x 20 u32
    const int SM128 = 2 * (2 * 128 * 20 + 2 * 128 * 20) * 4;  // 81920
    const int SM64  = 2 * (2 * 128 * 20 + 2 *  64 * 20) * 4;  // 61440
    cudaFuncSetAttribute(gemm_f16<128, 1>, cudaFuncAttributeMaxDynamicSharedMemorySize, SM128);
    cudaFuncSetAttribute(gemm_f16<128, 0>, cudaFuncAttributeMaxDynamicSharedMemorySize, SM128);
    cudaFuncSetAttribute(gemm_f16<64, 0>,  cudaFuncAttributeMaxDynamicSharedMemorySize, SM64);

    // 1..3: A_orig scatter + h split (keeps sigmoid GEMM as launch #4 for ncu)
    fill_zero4<<<(int)(((size_t)Nn * Nn / 4 + 255) / 256), 256>>>(Ao, (size_t)Nn * Nn / 4);
    scatter_edges<<<(E + 255) / 256, 256>>>(ei, ew, Ao, E);
    conv_split<<<(Nn * 256 / 4 + 255) / 256, 256>>>(X, hh, hl, Nn * 256 / 4);

    const int din[3] = {256, 256, 256};
    const int dof[3] = {256, 256, 128};
    const float* h = X;  // f32 view of current features (X, then H)

    for (int L = 0; L < 3; L++) {
        const int K = din[L], dout = dof[L];

        // S = sigmoid(h h^T) -> f16 pairs (Sh,Sl) + rowsum partials
        gemm_f16<128, 1><<<dim3(32, 32, 1), 256, SM128>>>(
            hh, hl, hh, hl, nullptr, K, K, Nn, K / 32, 0LL, rspart, Sh, Sl);

        if (L == 0) {
            conv_split<<<(int)(((size_t)Nn * Nn / 4 + 255) / 256), 256>>>(
                Ao, Aoh, Aol, (size_t)Nn * Nn / 4);
            rowsum_kernel<<<Nn, 256>>>(Ao, rs0);
        }

        // attention projections: P = [Ao|S] @ (64*aw1) / 64 + ab1 (split-K 8)
        transpose_f16<<<dim3(2, Nn / 32), dim3(32, 8)>>>(aw1[L], AWTh, AWTl, Nn, ATT, SCALE_AW);
        gemm_f16<64, 0><<<dim3(1, 32, 8), 256, SM64>>>(
            Aoh, Aol, AWTh, AWTl, part, Nn, Nn, ATT, (Nn / 32) / 8,
            (long long)Nn * ATT, nullptr, nullptr, nullptr);
        reduce_part<<<(Nn * ATT + 255) / 256, 256>>>(part, P0, Nn, ATT, 8, ab1[L], 1.f / SCALE_AW);
        gemm_f16<64, 0><<<dim3(1, 32, 8), 256, SM64>>>(
            Sh, Sl, AWTh, AWTl, part, Nn, Nn, ATT, (Nn / 32) / 8,
            (long long)Nn * ATT, nullptr, nullptr, nullptr);
        reduce_part<<<(Nn * ATT + 255) / 256, 256>>>(part, P1, Nn, ATT, 8, ab1[L], 1.f / SCALE_AW);

        attention_kernel<<<Nn / 4, 128>>>(P0, P1, aw2[L], ab2[L], rs0, rspart, a0, a1, dinv);

        // HW = h @ gw (SIMT), then HWT f16 pairs
        gemm_nn_splitk<<<dim3(dout / 64, 32, 1), 256>>>(h, gw[L], part, Nn, dout, K, K);
        reduce_part<<<(Nn * dout + 255) / 256, 256>>>(part, HW, Nn, dout, 1, nullptr, 1.f);
        transpose_f16<<<dim3(dout / 32, Nn / 32), dim3(32, 8)>>>(HW, HWTh, HWTl, Nn, dout, 1.f);

        // An (scaled, f16 pairs in place over S); stream final_A on last layer
        float* finalA = nullptr;
        if (L == 2 && out_size >= Nn * OUTD + Nn * Nn)
            finalA = (float*)d_out + (size_t)Nn * OUTD;
        build_An<<<16384, 256>>>(Ao, Sh, Sl, a0, a1, dinv, finalA);

        // H2 = (An_scaled @ HW) / SCALE_AN + gb
        const int zsp = (dout == 256) ? 4 : 8;
        gemm_f16<128, 0><<<dim3(dout / 128, 32, zsp), 256, SM128>>>(
            Sh, Sl, HWTh, HWTl, part, Nn, Nn, dout, (Nn / 32) / zsp,
            (long long)Nn * dout, nullptr, nullptr, nullptr);
        reduce_part<<<(Nn * dout + 255) / 256, 256>>>(part, H2, Nn, dout, zsp, gb[L], 1.f / SCALE_AN);

        // BatchNorm + LeakyReLU -> H (f32) + hh/hl (f16 pairs for next layer)
        bn_stats<<<dout / 32, dim3(32, 8)>>>(H2, dout, mu, var);
        bn_apply<<<(Nn * dout + 255) / 256, 256>>>(H2, H, hh, hl, dout, mu, var, bng[L], bnb[L]);
        h = H;
    }

    // out = h @ lin_w + lin_b (K=128, SIMT)
    gemm_nn_splitk<<<dim3(1, 32, 1), 256>>>(h, lw, part, Nn, OUTD, 128, 128);
    reduce_part<<<(Nn * OUTD + 255) / 256, 256>>>(part, (float*)d_out, Nn, OUTD, 1, lb, 1.f);
}

// round 11
// speedup vs baseline: 1.1459x; 1.0797x over previous
#include <cuda_runtime.h>
#include <cuda_fp16.h>
#include <math.h>
#include <stdint.h>

constexpr int Nn  = 4096;
constexpr int ATT = 64;
constexpr int OUTD = 64;
constexpr float SCALE_AN = 16384.f;
constexpr float SCALE_AW = 64.f;

// ---------------- scratch (device globals; no allocation allowed) ----------------
__device__ float  g_Aorig[(size_t)Nn * Nn];
__device__ __half g_Aoh[(size_t)Nn * Nn];
__device__ __half g_Aol[(size_t)Nn * Nn];
__device__ __half g_Sh[(size_t)Nn * Nn];
__device__ __half g_Sl[(size_t)Nn * Nn];
__device__ float  g_H [Nn * 256];
__device__ float  g_H2[Nn * 256];
__device__ float  g_HW[Nn * 256];
__device__ __half g_hh[Nn * 256];
__device__ __half g_hl[Nn * 256];
__device__ __half g_HWTh[256 * Nn];
__device__ __half g_HWTl[256 * Nn];
__device__ __half g_AWTh[64 * Nn];
__device__ __half g_AWTl[64 * Nn];
__device__ float  g_part[(size_t)8 * Nn * 256];
__device__ float  g_P0[Nn * ATT];
__device__ float  g_P1[Nn * ATT];
__device__ float  g_rspart[64 * Nn];
__device__ float  g_a0[Nn], g_a1[Nn], g_dinv[Nn];
__device__ float  g_rs0[Nn];
__device__ float  g_mu[256], g_var[256];

// ---------------- helpers ----------------
__device__ __forceinline__ uint32_t smem_u32(const void* p) {
    uint32_t a;
    asm("{ .reg .u64 t; cvta.to.shared.u64 t, %1; cvt.u32.u64 %0, t; }" : "=r"(a) : "l"(p));
    return a;
}
__device__ __forceinline__ void cpa16(uint32_t dst, const void* src) {
    asm volatile("cp.async.cg.shared.global [%0], [%1], 16;" :: "r"(dst), "l"(src));
}
__device__ __forceinline__ void mma16(float (&c)[4], const uint32_t (&a)[4],
                                      uint32_t b0, uint32_t b1) {
    asm volatile(
        "mma.sync.aligned.m16n8k16.row.col.f32.f16.f16.f32 "
        "{%0,%1,%2,%3}, {%4,%5,%6,%7}, {%8,%9}, {%0,%1,%2,%3};"
        : "+f"(c[0]), "+f"(c[1]), "+f"(c[2]), "+f"(c[3])
        : "r"(a[0]), "r"(a[1]), "r"(a[2]), "r"(a[3]), "r"(b0), "r"(b1));
}
__device__ __forceinline__ void splitpair(float x, float y, uint32_t& h, uint32_t& l) {
    __half hx = __float2half_rn(x), hy = __float2half_rn(y);
    __half lx = __float2half_rn(x - __half2float(hx));
    __half ly = __float2half_rn(y - __half2float(hy));
    __half2 hp = __halves2half2(hx, hy), lp = __halves2half2(lx, ly);
    h = *reinterpret_cast<uint32_t*>(&hp);
    l = *reinterpret_cast<uint32_t*>(&lp);
}
__device__ __forceinline__ void split1(float x, __half& h, __half& l) {
    h = __float2half_rn(x);
    l = __float2half_rn(x - __half2float(h));
}

// ============================================================================
// f16x3 NT GEMM, pre-split hi/lo f16 operands, double-buffered cp.async.
// EPI 0: f32 store to part[z].
// EPI 1: SYMMETRIC sigmoid GEMM (A==B). Only upper-triangular blocks (bx>=by)
//        compute; off-diagonal blocks mirror-write via smem transpose.
//        Rowsum partial slots: direct = 2*bx+wn; mirrored = 2*by+half.
// ============================================================================
template<int BN, int EPI>
__global__ void __launch_bounds__(256, 2) gemm_f16(
    const __half* __restrict__ Ah, const __half* __restrict__ Al,
    const __half* __restrict__ Bh, const __half* __restrict__ Bl,
    float* __restrict__ C, int lda, int ldb, int ldc, int nch,
    long long zstride, float* __restrict__ rs,
    __half* __restrict__ oh, __half* __restrict__ ol)
{
    constexpr int TS   = 20;                 // u32 stride per row (16 data + 4 pad)
    constexpr int TT   = 136;                // transpose tile row stride (halfs)
    constexpr int NT2  = BN / 16;
    constexpr int ABUF = 128 * TS;
    constexpr int BBUF = BN * TS;
    constexpr int BUFSZ = 2 * ABUF + 2 * BBUF;
    extern __shared__ uint32_t smu[];

    if (EPI == 1 && blockIdx.x < blockIdx.y) return;   // lower triangle: skip

    const int tid  = threadIdx.x;
    const int warp = tid >> 5, lane = tid & 31;
    const int g = lane >> 2, tg = lane & 3;
    const int wm = warp >> 1, wn = warp & 1;
    const int rm = wm * 32, cn = wn * (BN / 2);
    const int bm = blockIdx.y * 128, bn = blockIdx.x * BN;
    const int kbeg = blockIdx.z * nch * 32;

    const uint32_t smu_u = smem_u32(smu);

    auto issue = [&](int c) {
        const int b = c & 1;
        const int k0 = kbeg + c * 32;
        const uint32_t base = smu_u + b * BUFSZ * 4;
#pragma unroll
        for (int i = 0; i < 2; i++) {
            int idx = tid + i * 256;
            int r = idx >> 2, q = idx & 3;
            const size_t go = (size_t)(bm + r) * lda + k0 + q * 8;
            cpa16(base + (r * TS + q * 4) * 4, Ah + go);
            cpa16(base + (ABUF + r * TS + q * 4) * 4, Al + go);
        }
#pragma unroll
        for (int i = 0; i < BN / 64; i++) {
            int idx = tid + i * 256;
            int r = idx >> 2, q = idx & 3;
            const size_t go = (size_t)(bn + r) * ldb + k0 + q * 8;
            cpa16(base + (2 * ABUF + r * TS + q * 4) * 4, Bh + go);
            cpa16(base + (2 * ABUF + BBUF + r * TS + q * 4) * 4, Bl + go);
        }
        asm volatile("cp.async.commit_group;" ::: "memory");
    };

    float acc[2][NT2][4];
#pragma unroll
    for (int mt = 0; mt < 2; mt++)
#pragma unroll
        for (int nt = 0; nt < NT2; nt++)
#pragma unroll
            for (int j = 0; j < 4; j++) acc[mt][nt][j] = 0.f;

    issue(0);
    for (int c = 0; c < nch; c++) {
        if (c + 1 < nch) {
            issue(c + 1);
            asm volatile("cp.async.wait_group 1;" ::: "memory");
        } else {
            asm volatile("cp.async.wait_group 0;" ::: "memory");
        }
        __syncthreads();

        const uint32_t* Athi = smu + (c & 1) * BUFSZ;
        const uint32_t* Atlo = Athi + ABUF;
        const uint32_t* Bthi = Athi + 2 * ABUF;
        const uint32_t* Btlo = Bthi + BBUF;

#pragma unroll
        for (int ks = 0; ks < 2; ks++) {
            const int kp = ks * 8;
            uint32_t ah[2][4], al[2][4];
#pragma unroll
            for (int mt = 0; mt < 2; mt++) {
                const int ro = (rm + mt * 16 + g) * TS;
                ah[mt][0] = Athi[ro + kp + tg];
                ah[mt][1] = Athi[ro + 8 * TS + kp + tg];
                ah[mt][2] = Athi[ro + kp + tg + 4];
                ah[mt][3] = Athi[ro + 8 * TS + kp + tg + 4];
                al[mt][0] = Atlo[ro + kp + tg];
                al[mt][1] = Atlo[ro + 8 * TS + kp + tg];
                al[mt][2] = Atlo[ro + kp + tg + 4];
                al[mt][3] = Atlo[ro + 8 * TS + kp + tg + 4];
            }
#pragma unroll
            for (int nt = 0; nt < NT2; nt++) {
                const int bo = (cn + nt * 8 + g) * TS + kp;
                uint32_t bh0 = Bthi[bo + tg], bh1 = Bthi[bo + tg + 4];
                uint32_t bl0 = Btlo[bo + tg], bl1 = Btlo[bo + tg + 4];
#pragma unroll
                for (int mt = 0; mt < 2; mt++) {
                    mma16(acc[mt][nt], ah[mt], bh0, bh1);
                    mma16(acc[mt][nt], ah[mt], bl0, bl1);
                    mma16(acc[mt][nt], al[mt], bh0, bh1);
                }
            }
        }
        __syncthreads();
    }

    // ---------------- epilogue ----------------
    __half* Th = reinterpret_cast<__half*>(smu);       // transpose tiles (reuse bufs)
    __half* Tl = Th + 128 * TT;
    const bool mirror = (EPI == 1) && (blockIdx.x != blockIdx.y);

#pragma unroll
    for (int mt = 0; mt < 2; mt++) {
        const int r0l = rm + mt * 16 + g;
        const int r1l = r0l + 8;
        const int r0 = bm + r0l, r1 = bm + r1l;
        float s0 = 0.f, s1 = 0.f;
#pragma unroll
        for (int nt = 0; nt < NT2; nt++) {
            float c0 = acc[mt][nt][0], c1 = acc[mt][nt][1];
            float c2 = acc[mt][nt][2], c3 = acc[mt][nt][3];
            const int cl = cn + nt * 8 + 2 * tg;
            const int col = bn + cl;
            if (EPI == 1) {
                c0 = 1.f / (1.f + expf(-c0)); c1 = 1.f / (1.f + expf(-c1));
                c2 = 1.f / (1.f + expf(-c2)); c3 = 1.f / (1.f + expf(-c3));
                s0 += c0 + c1; s1 += c2 + c3;
                uint32_t h01, l01, h23, l23;
                splitpair(c0, c1, h01, l01);
                splitpair(c2, c3, h23, l23);
                *reinterpret_cast<uint32_t*>(oh + (size_t)r0 * ldc + col) = h01;
                *reinterpret_cast<uint32_t*>(ol + (size_t)r0 * ldc + col) = l01;
                *reinterpret_cast<uint32_t*>(oh + (size_t)r1 * ldc + col) = h23;
                *reinterpret_cast<uint32_t*>(ol + (size_t)r1 * ldc + col) = l23;
                if (mirror) {
                    __half2 H01 = *reinterpret_cast<__half2*>(&h01);
                    __half2 L01 = *reinterpret_cast<__half2*>(&l01);
                    __half2 H23 = *reinterpret_cast<__half2*>(&h23);
                    __half2 L23 = *reinterpret_cast<__half2*>(&l23);
                    Th[cl * TT + r0l]       = __low2half(H01);
                    Th[(cl + 1) * TT + r0l] = __high2half(H01);
                    Tl[cl * TT + r0l]       = __low2half(L01);
                    Tl[(cl + 1) * TT + r0l] = __high2half(L01);
                    Th[cl * TT + r1l]       = __low2half(H23);
                    Th[(cl + 1) * TT + r1l] = __high2half(H23);
                    Tl[cl * TT + r1l]       = __low2half(L23);
                    Tl[(cl + 1) * TT + r1l] = __high2half(L23);
                }
            } else {
                float* Cz = C + (size_t)blockIdx.z * zstride;
                *reinterpret_cast<float2*>(Cz + (size_t)r0 * ldc + col) = make_float2(c0, c1);
                *reinterpret_cast<float2*>(Cz + (size_t)r1 * ldc + col) = make_float2(c2, c3);
            }
        }
        if (EPI == 1) {
            s0 += __shfl_xor_sync(0xFFFFFFFFu, s0, 1);
            s0 += __shfl_xor_sync(0xFFFFFFFFu, s0, 2);
            s1 += __shfl_xor_sync(0xFFFFFFFFu, s1, 1);
            s1 += __shfl_xor_sync(0xFFFFFFFFu, s1, 2);
            if (tg == 0) {
                float* rp = rs + (size_t)(blockIdx.x * 2 + wn) * Nn;
                rp[r0] = s0;
                rp[r1] = s1;
            }
        }
    }

    if (mirror) {
        __syncthreads();
        // coalesced mirror write: mirror row = bn + c, cols bm..bm+127
#pragma unroll
        for (int i = 0; i < 8; i++) {
            int c  = (tid >> 4) + i * 16;
            int ch = tid & 15;
            uint4 vh = *reinterpret_cast<const uint4*>(&Th[c * TT + ch * 8]);
            uint4 vl = *reinterpret_cast<const uint4*>(&Tl[c * TT + ch * 8]);
            *reinterpret_cast<uint4*>(oh + (size_t)(bn + c) * ldc + bm + ch * 8) = vh;
            *reinterpret_cast<uint4*>(ol + (size_t)(bn + c) * ldc + bm + ch * 8) = vl;
        }
        // mirrored rowsum partials: slot 2*by + half (half = original row half)
        {
            int c = tid >> 1, half = tid & 1;
            const __half2* ph = reinterpret_cast<const __half2*>(&Th[c * TT + half * 64]);
            const __half2* pl = reinterpret_cast<const __half2*>(&Tl[c * TT + half * 64]);
            float s = 0.f;
#pragma unroll
            for (int k = 0; k < 32; k++) {
                float2 a = __half22float2(ph[k]);
                float2 b = __half22float2(pl[k]);
                s += a.x + a.y + b.x + b.y;
            }
            rs[(size_t)(blockIdx.y * 2 + half) * Nn + bn + c] = s;
        }
    }
}

// ---------------- conversion / utility kernels ----------------
__global__ void conv_split(const float* __restrict__ in, __half* __restrict__ oh,
                           __half* __restrict__ ol, size_t n4) {
    size_t i = (size_t)blockIdx.x * blockDim.x + threadIdx.x;
    if (i >= n4) return;
    float4 v = reinterpret_cast<const float4*>(in)[i];
    uint32_t h01, l01, h23, l23;
    splitpair(v.x, v.y, h01, l01);
    splitpair(v.z, v.w, h23, l23);
    reinterpret_cast<uint2*>(oh)[i] = make_uint2(h01, h23);
    reinterpret_cast<uint2*>(ol)[i] = make_uint2(l01, l23);
}

__global__ void fill_zero4(float* p, size_t n4) {
    size_t i = (size_t)blockIdx.x * blockDim.x + threadIdx.x;
    if (i < n4) reinterpret_cast<float4*>(p)[i] = make_float4(0.f, 0.f, 0.f, 0.f);
}

__global__ void scatter_edges(const int* __restrict__ ei, const float* __restrict__ ew,
                              float* __restrict__ A, int E) {
    int t = blockIdx.x * blockDim.x + threadIdx.x;
    if (t < E) {
        int r = ei[t];
        int c = ei[E + t];
        atomicAdd(A + (size_t)r * Nn + c, ew[t]);
    }
}

__global__ void rowsum_kernel(const float* __restrict__ A, float* __restrict__ rs) {
    int row = blockIdx.x;
    const float4* p = reinterpret_cast<const float4*>(A + (size_t)row * Nn);
    float s = 0.f;
    for (int i = threadIdx.x; i < Nn / 4; i += blockDim.x) {
        float4 v = p[i];
        s += v.x + v.y + v.z + v.w;
    }
    __shared__ float sh[256];
    sh[threadIdx.x] = s;
    __syncthreads();
    for (int d = 128; d; d >>= 1) {
        if (threadIdx.x < d) sh[threadIdx.x] += sh[threadIdx.x + d];
        __syncthreads();
    }
    if (threadIdx.x == 0) rs[row] = sh[0];
}

__global__ void transpose_f16(const float* __restrict__ in, __half* __restrict__ oh,
                              __half* __restrict__ ol, int R, int Cc, float scale) {
    __shared__ float t[32][33];
    int bx = blockIdx.x * 32, by = blockIdx.y * 32;
    int x = bx + threadIdx.x;
    for (int dy = 0; dy < 32; dy += 8) {
        int y = by + threadIdx.y + dy;
        if (x < Cc && y < R) t[threadIdx.y + dy][threadIdx.x] = in[(size_t)y * Cc + x];
    }
    __syncthreads();
    int xo = by + threadIdx.x;
    for (int dy = 0; dy < 32; dy += 8) {
        int yo = bx + threadIdx.y + dy;
        if (xo < R && yo < Cc) {
            float v = t[threadIdx.x][threadIdx.y + dy] * scale;
            __half h, l;
            split1(v, h, l);
            oh[(size_t)yo * R + xo] = h;
            ol[(size_t)yo * R + xo] = l;
        }
    }
}

// ---------------- SIMT GEMM for small-K matmuls (HW = h@gw, final out) -------
__global__ __launch_bounds__(256) void gemm_nn_splitk(
    const float* __restrict__ A, const float* __restrict__ B,
    float* __restrict__ part, int M, int Ncols, int K, int Kc)
{
    __shared__ float As[16][132];
    __shared__ float Bs[16][64];
    const int tid = threadIdx.x;
    const int tr = tid >> 4, tc = tid & 15;
    const int bm = blockIdx.y * 128, bn = blockIdx.x * 64;
    const int kbeg = blockIdx.z * Kc;

    float acc[8][4];
#pragma unroll
    for (int i = 0; i < 8; i++)
#pragma unroll
        for (int j = 0; j < 4; j++) acc[i][j] = 0.f;

    for (int k0 = kbeg; k0 < kbeg + Kc; k0 += 16) {
#pragma unroll
        for (int s = 0; s < 2; s++) {
            int slot = tid + s * 256;
            int r = slot >> 2, q = slot & 3;
            float4 va = *reinterpret_cast<const float4*>(A + (size_t)(bm + r) * K + k0 + q * 4);
            As[q * 4 + 0][r] = va.x; As[q * 4 + 1][r] = va.y;
            As[q * 4 + 2][r] = va.z; As[q * 4 + 3][r] = va.w;
        }
        {
            int r = tid >> 4, q = tid & 15;
            *reinterpret_cast<float4*>(&Bs[r][q * 4]) =
                *reinterpret_cast<const float4*>(B + (size_t)(k0 + r) * Ncols + bn + q * 4);
        }
        __syncthreads();
#pragma unroll
        for (int kk = 0; kk < 16; kk++) {
            float a[8], b[4];
            *reinterpret_cast<float4*>(&a[0]) = *reinterpret_cast<const float4*>(&As[kk][tr * 4]);
            *reinterpret_cast<float4*>(&a[4]) = *reinterpret_cast<const float4*>(&As[kk][64 + tr * 4]);
            *reinterpret_cast<float4*>(&b[0]) = *reinterpret_cast<const float4*>(&Bs[kk][tc * 4]);
#pragma unroll
            for (int i = 0; i < 8; i++)
#pragma unroll
                for (int j = 0; j < 4; j++) acc[i][j] += a[i] * b[j];
        }
        __syncthreads();
    }

    float* out = part + (size_t)blockIdx.z * M * Ncols;
#pragma unroll
    for (int i = 0; i < 8; i++) {
        int row = bm + ((i < 4) ? tr * 4 + i : 64 + tr * 4 + (i - 4));
        *reinterpret_cast<float4*>(out + (size_t)row * Ncols + bn + tc * 4) =
            make_float4(acc[i][0], acc[i][1], acc[i][2], acc[i][3]);
    }
}

__global__ void reduce_part(const float* __restrict__ part, float* __restrict__ out,
                            int M, int Ncols, int split, const float* __restrict__ bias,
                            float scale) {
    int idx = blockIdx.x * 256 + threadIdx.x;
    int total = M * Ncols;
    if (idx < total) {
        float s = 0.f;
        for (int p = 0; p < split; p++) s += part[(size_t)p * total + idx];
        s *= scale;
        if (bias) s += bias[idx % Ncols];
        out[idx] = s;
    }
}

// ---------------- attention coefficients + degree/dinv ----------------
__global__ void attention_kernel(const float* __restrict__ P0, const float* __restrict__ P1,
                                 const float* __restrict__ aw2, const float* __restrict__ ab2,
                                 const float* __restrict__ rs0, const float* __restrict__ rspart,
                                 float* __restrict__ a0o, float* __restrict__ a1o,
                                 float* __restrict__ dinv) {
    int warp = (blockIdx.x * blockDim.x + threadIdx.x) >> 5;
    int lane = threadIdx.x & 31;
    if (warp >= Nn) return;
    float s0 = 0.f, s1 = 0.f;
    for (int t = lane; t < ATT; t += 32) {
        float w2 = aw2[t];
        s0 += tanhf(P0[warp * ATT + t]) * w2;
        s1 += tanhf(P1[warp * ATT + t]) * w2;
    }
    float sr = rspart[(size_t)lane * Nn + warp] + rspart[(size_t)(lane + 32) * Nn + warp];
#pragma unroll
    for (int o = 16; o; o >>= 1) {
        s0 += __shfl_down_sync(0xFFFFFFFFu, s0, o);
        s1 += __shfl_down_sync(0xFFFFFFFFu, s1, o);
        sr += __shfl_down_sync(0xFFFFFFFFu, sr, o);
    }
    if (lane == 0) {
        float b2 = ab2[0];
        s0 += b2; s1 += b2;
        float m = fmaxf(s0, s1);
        float e0 = expf(s0 - m), e1 = expf(s1 - m);
        float inv = 1.f / (e0 + e1);
        float a0 = e0 * inv, a1 = e1 * inv;
        float deg = a0 * rs0[warp] + a1 * sr + 1.f;
        a0o[warp] = a0; a1o[warp] = a1;
        dinv[warp] = deg > 0.f ? rsqrtf(deg) : 0.f;
    }
}

// ---------------- A_m + final_A + An (f16 pairs, Ao from f16 pairs) ----------------
__global__ void build_An(const __half* __restrict__ Aoh, const __half* __restrict__ Aol,
                         __half* __restrict__ Sh, __half* __restrict__ Sl,
                         const float* __restrict__ a0, const float* __restrict__ a1,
                         const float* __restrict__ dinv, float* __restrict__ finalA) {
    size_t gid = (size_t)blockIdx.x * blockDim.x + threadIdx.x;
    if (gid >= (size_t)Nn * Nn / 4) return;
    int i  = (int)(gid / (Nn / 4));
    int j4 = (int)(gid % (Nn / 4)) * 4;
    uint2 ohv = *reinterpret_cast<const uint2*>(Aoh + (size_t)i * Nn + j4);
    uint2 olv = *reinterpret_cast<const uint2*>(Aol + (size_t)i * Nn + j4);
    uint2 shv = *reinterpret_cast<const uint2*>(Sh + (size_t)i * Nn + j4);
    uint2 slv = *reinterpret_cast<const uint2*>(Sl + (size_t)i * Nn + j4);
    float2 oa = __half22float2(*reinterpret_cast<__half2*>(&ohv.x));
    float2 ob = __half22float2(*reinterpret_cast<__half2*>(&ohv.y));
    float2 oc = __half22float2(*reinterpret_cast<__half2*>(&olv.x));
    float2 od = __half22float2(*reinterpret_cast<__half2*>(&olv.y));
    float4 o = make_float4(oa.x + oc.x, oa.y + oc.y, ob.x + od.x, ob.y + od.y);
    float2 sa = __half22float2(*reinterpret_cast<__half2*>(&shv.x));
    float2 sb = __half22float2(*reinterpret_cast<__half2*>(&shv.y));
    float2 sc = __half22float2(*reinterpret_cast<__half2*>(&slv.x));
    float2 sd = __half22float2(*reinterpret_cast<__half2*>(&slv.y));
    float4 s = make_float4(sa.x + sc.x, sa.y + sc.y, sb.x + sd.x, sb.y + sd.y);
    float A0 = a0[i], A1 = a1[i], di = dinv[i] * SCALE_AN;
    float4 am;
    am.x = A0 * o.x + A1 * s.x;
    am.y = A0 * o.y + A1 * s.y;
    am.z = A0 * o.z + A1 * s.z;
    am.w = A0 * o.w + A1 * s.w;
    if (finalA) *reinterpret_cast<float4*>(finalA + (size_t)i * Nn + j4) = am;
    float4 dj = *reinterpret_cast<const float4*>(dinv + j4);
    float4 an;
    an.x = di * dj.x * (am.x + ((j4 + 0 == i) ? 1.f : 0.f));
    an.y = di * dj.y * (am.y + ((j4 + 1 == i) ? 1.f : 0.f));
    an.z = di * dj.z * (am.z + ((j4 + 2 == i) ? 1.f : 0.f));
    an.w = di * dj.w * (am.w + ((j4 + 3 == i) ? 1.f : 0.f));
    uint32_t nh01, nl01, nh23, nl23;
    splitpair(an.x, an.y, nh01, nl01);
    splitpair(an.z, an.w, nh23, nl23);
    *reinterpret_cast<uint2*>(Sh + (size_t)i * Nn + j4) = make_uint2(nh01, nh23);
    *reinterpret_cast<uint2*>(Sl + (size_t)i * Nn + j4) = make_uint2(nl01, nl23);
}

// ---------------- BatchNorm (two-pass) ----------------
__global__ void bn_stats(const float* __restrict__ H, int dout,
                         float* __restrict__ mu, float* __restrict__ var) {
    int col = blockIdx.x * 32 + threadIdx.x;
    __shared__ float sh[8][32];
    __shared__ float shm[32];

    float s = 0.f;
    for (int r = threadIdx.y; r < Nn; r += 8)
        s += H[(size_t)r * dout + col];
    sh[threadIdx.y][threadIdx.x] = s;
    __syncthreads();
    if (threadIdx.y == 0) {
#pragma unroll
        for (int y = 1; y < 8; y++) s += sh[y][threadIdx.x];
        shm[threadIdx.x] = s / (float)Nn;
    }
    __syncthreads();
    float m = shm[threadIdx.x];

    float s2 = 0.f;
    for (int r = threadIdx.y; r < Nn; r += 8) {
        float d = H[(size_t)r * dout + col] - m;
        s2 += d * d;
    }
    __syncthreads();
    sh[threadIdx.y][threadIdx.x] = s2;
    __syncthreads();
    if (threadIdx.y == 0) {
#pragma unroll
        for (int y = 1; y < 8; y++) s2 += sh[y][threadIdx.x];
        mu[col]  = m;
        var[col] = s2 / (float)Nn;
    }
}

__global__ void bn_apply(const float* __restrict__ Hin, float* __restrict__ Hout,
                         __half* __restrict__ oh, __half* __restrict__ ol, int dout,
                         const float* __restrict__ mu, const float* __restrict__ var,
                         const float* __restrict__ gamma, const float* __restrict__ beta) {
    int idx = blockIdx.x * 256 + threadIdx.x;
    if (idx < Nn * dout) {
        int c = idx % dout;
        float x = Hin[idx];
        float y = gamma[c] * (x - mu[c]) * rsqrtf(var[c] + 1e-5f) + beta[c];
        y = y > 0.f ? y : 0.01f * y;
        Hout[idx] = y;
        __half h, l;
        split1(y, h, l);
        oh[idx] = h;
        ol[idx] = l;
    }
}

// ---------------- host orchestration ----------------
extern "C" void kernel_launch(void* const* d_in, const int* in_sizes, int n_in,
                              void* d_out, int out_size) {
    const float* X  = (const float*)d_in[0];
    const int*   ei = (const int*)d_in[1];
    const float* ew = (const float*)d_in[2];
    const float *gw[3], *gb[3], *bng[3], *bnb[3], *aw1[3], *ab1[3], *aw2[3], *ab2[3];
    for (int i = 0; i < 3; i++) {
        int b = 3 + i * 8;
        gw[i]  = (const float*)d_in[b + 0];
        gb[i]  = (const float*)d_in[b + 1];
        bng[i] = (const float*)d_in[b + 2];
        bnb[i] = (const float*)d_in[b + 3];
        aw1[i] = (const float*)d_in[b + 4];
        ab1[i] = (const float*)d_in[b + 5];
        aw2[i] = (const float*)d_in[b + 6];
        ab2[i] = (const float*)d_in[b + 7];
    }
    const float* lw = (const float*)d_in[27];
    const float* lb = (const float*)d_in[28];
    const int E = in_sizes[2];

    float *Ao, *H, *H2, *HW, *part, *P0, *P1, *rspart, *a0, *a1, *dinv, *rs0, *mu, *var;
    __half *Aoh, *Aol, *Sh, *Sl, *hh, *hl, *HWTh, *HWTl, *AWTh, *AWTl;
    cudaGetSymbolAddress((void**)&Ao,     g_Aorig);
    cudaGetSymbolAddress((void**)&Aoh,    g_Aoh);
    cudaGetSymbolAddress((void**)&Aol,    g_Aol);
    cudaGetSymbolAddress((void**)&Sh,     g_Sh);
    cudaGetSymbolAddress((void**)&Sl,     g_Sl);
    cudaGetSymbolAddress((void**)&H,      g_H);
    cudaGetSymbolAddress((void**)&H2,     g_H2);
    cudaGetSymbolAddress((void**)&HW,     g_HW);
    cudaGetSymbolAddress((void**)&hh,     g_hh);
    cudaGetSymbolAddress((void**)&hl,     g_hl);
    cudaGetSymbolAddress((void**)&HWTh,   g_HWTh);
    cudaGetSymbolAddress((void**)&HWTl,   g_HWTl);
    cudaGetSymbolAddress((void**)&AWTh,   g_AWTh);
    cudaGetSymbolAddress((void**)&AWTl,   g_AWTl);
    cudaGetSymbolAddress((void**)&part,   g_part);
    cudaGetSymbolAddress((void**)&P0,     g_P0);
    cudaGetSymbolAddress((void**)&P1,     g_P1);
    cudaGetSymbolAddress((void**)&rspart, g_rspart);
    cudaGetSymbolAddress((void**)&a0,     g_a0);
    cudaGetSymbolAddress((void**)&a1,     g_a1);
    cudaGetSymbolAddress((void**)&dinv,   g_dinv);
    cudaGetSymbolAddress((void**)&rs0,    g_rs0);
    cudaGetSymbolAddress((void**)&mu,     g_mu);
    cudaGetSymbolAddress((void**)&var,    g_var);

    const int SM128 = 2 * (2 * 128 * 20 + 2 * 128 * 20) * 4;  // 81920
    const int SM64  = 2 * (2 * 128 * 20 + 2 *  64 * 20) * 4;  // 61440
    cudaFuncSetAttribute(gemm_f16<128, 1>, cudaFuncAttributeMaxDynamicSharedMemorySize, SM128);
    cudaFuncSetAttribute(gemm_f16<128, 0>, cudaFuncAttributeMaxDynamicSharedMemorySize, SM128);
    cudaFuncSetAttribute(gemm_f16<64, 0>,  cudaFuncAttributeMaxDynamicSharedMemorySize, SM64);

    // 1..3: A_orig scatter + h split (keeps sigmoid GEMM as launch #4 for ncu)
    fill_zero4<<<(int)(((size_t)Nn * Nn / 4 + 255) / 256), 256>>>(Ao, (size_t)Nn * Nn / 4);
    scatter_edges<<<(E + 255) / 256, 256>>>(ei, ew, Ao, E);
    conv_split<<<(Nn * 256 / 4 + 255) / 256, 256>>>(X, hh, hl, Nn * 256 / 4);

    const int din[3] = {256, 256, 256};
    const int dof[3] = {256, 256, 128};
    const float* h = X;

    for (int L = 0; L < 3; L++) {
        const int K = din[L], dout = dof[L];

        // S = sigmoid(h h^T): symmetric — upper-triangular blocks + mirror
        gemm_f16<128, 1><<<dim3(32, 32, 1), 256, SM128>>>(
            hh, hl, hh, hl, nullptr, K, K, Nn, K / 32, 0LL, rspart, Sh, Sl);

        if (L == 0) {
            conv_split<<<(int)(((size_t)Nn * Nn / 4 + 255) / 256), 256>>>(
                Ao, Aoh, Aol, (size_t)Nn * Nn / 4);
            rowsum_kernel<<<Nn, 256>>>(Ao, rs0);
        }

        // attention projections (split-K 8)
        transpose_f16<<<dim3(2, Nn / 32), dim3(32, 8)>>>(aw1[L], AWTh, AWTl, Nn, ATT, SCALE_AW);
        gemm_f16<64, 0><<<dim3(1, 32, 8), 256, SM64>>>(
            Aoh, Aol, AWTh, AWTl, part, Nn, Nn, ATT, (Nn / 32) / 8,
            (long long)Nn * ATT, nullptr, nullptr, nullptr);
        reduce_part<<<(Nn * ATT + 255) / 256, 256>>>(part, P0, Nn, ATT, 8, ab1[L], 1.f / SCALE_AW);
        gemm_f16<64, 0><<<dim3(1, 32, 8), 256, SM64>>>(
            Sh, Sl, AWTh, AWTl, part, Nn, Nn, ATT, (Nn / 32) / 8,
            (long long)Nn * ATT, nullptr, nullptr, nullptr);
        reduce_part<<<(Nn * ATT + 255) / 256, 256>>>(part, P1, Nn, ATT, 8, ab1[L], 1.f / SCALE_AW);

        attention_kernel<<<Nn / 4, 128>>>(P0, P1, aw2[L], ab2[L], rs0, rspart, a0, a1, dinv);

        // HW = h @ gw (SIMT), then HWT f16 pairs
        gemm_nn_splitk<<<dim3(dout / 64, 32, 1), 256>>>(h, gw[L], part, Nn, dout, K, K);
        reduce_part<<<(Nn * dout + 255) / 256, 256>>>(part, HW, Nn, dout, 1, nullptr, 1.f);
        transpose_f16<<<dim3(dout / 32, Nn / 32), dim3(32, 8)>>>(HW, HWTh, HWTl, Nn, dout, 1.f);

        // An (scaled, f16 pairs in place over S); final_A on last layer
        float* finalA = nullptr;
        if (L == 2 && out_size >= Nn * OUTD + Nn * Nn)
            finalA = (float*)d_out + (size_t)Nn * OUTD;
        build_An<<<16384, 256>>>(Aoh, Aol, Sh, Sl, a0, a1, dinv, finalA);

        // H2 = (An_scaled @ HW) / SCALE_AN + gb
        const int zsp = (dout == 256) ? 4 : 8;
        gemm_f16<128, 0><<<dim3(dout / 128, 32, zsp), 256, SM128>>>(
            Sh, Sl, HWTh, HWTl, part, Nn, Nn, dout, (Nn / 32) / zsp,
            (long long)Nn * dout, nullptr, nullptr, nullptr);
        reduce_part<<<(Nn * dout + 255) / 256, 256>>>(part, H2, Nn, dout, zsp, gb[L], 1.f / SCALE_AN);

        // BatchNorm + LeakyReLU -> H + f16 pairs for next layer
        bn_stats<<<dout / 32, dim3(32, 8)>>>(H2, dout, mu, var);
        bn_apply<<<(Nn * dout + 255) / 256, 256>>>(H2, H, hh, hl, dout, mu, var, bng[L], bnb[L]);
        h = H;
    }

    // out = h @ lin_w + lin_b (K=128, SIMT)
    gemm_nn_splitk<<<dim3(1, 32, 1), 256>>>(h, lw, part, Nn, OUTD, 128, 128);
    reduce_part<<<(Nn * OUTD + 255) / 256, 256>>>(part, (float*)d_out, Nn, OUTD, 1, lb, 1.f);
}

// round 12
// speedup vs baseline: 1.2281x; 1.0717x over previous
#include <cuda_runtime.h>
#include <cuda_fp16.h>
#include <math.h>
#include <stdint.h>

constexpr int Nn  = 4096;
constexpr int ATT = 64;
constexpr int OUTD = 64;
constexpr float SCALE_AN = 16384.f;
constexpr float SCALE_AW = 64.f;

// ---------------- scratch (device globals; no allocation allowed) ----------------
__device__ float  g_Aorig[(size_t)Nn * Nn];
__device__ __half g_Aoh[(size_t)Nn * Nn];
__device__ __half g_Aol[(size_t)Nn * Nn];
__device__ __half g_Sh[(size_t)Nn * Nn];
__device__ __half g_Sl[(size_t)Nn * Nn];
__device__ float  g_H [Nn * 256];
__device__ float  g_H2[Nn * 256];
__device__ float  g_HW[Nn * 256];
__device__ __half g_hh[Nn * 256];
__device__ __half g_hl[Nn * 256];
__device__ __half g_HWTh[256 * Nn];
__device__ __half g_HWTl[256 * Nn];
__device__ __half g_AWTh[64 * Nn];
__device__ __half g_AWTl[64 * Nn];
__device__ __half g_GWTh[256 * 256];
__device__ __half g_GWTl[256 * 256];
__device__ float  g_part[(size_t)8 * Nn * 256];
__device__ float  g_rspart[64 * Nn];
__device__ float  g_a0[Nn], g_a1[Nn], g_dinv[Nn];
__device__ float  g_rs0[Nn];
__device__ float  g_mu[256], g_var[256];

// ---------------- helpers ----------------
__device__ __forceinline__ uint32_t smem_u32(const void* p) {
    uint32_t a;
    asm("{ .reg .u64 t; cvta.to.shared.u64 t, %1; cvt.u32.u64 %0, t; }" : "=r"(a) : "l"(p));
    return a;
}
__device__ __forceinline__ void cpa16(uint32_t dst, const void* src) {
    asm volatile("cp.async.cg.shared.global [%0], [%1], 16;" :: "r"(dst), "l"(src));
}
__device__ __forceinline__ void mma16(float (&c)[4], const uint32_t (&a)[4],
                                      uint32_t b0, uint32_t b1) {
    asm volatile(
        "mma.sync.aligned.m16n8k16.row.col.f32.f16.f16.f32 "
        "{%0,%1,%2,%3}, {%4,%5,%6,%7}, {%8,%9}, {%0,%1,%2,%3};"
        : "+f"(c[0]), "+f"(c[1]), "+f"(c[2]), "+f"(c[3])
        : "r"(a[0]), "r"(a[1]), "r"(a[2]), "r"(a[3]), "r"(b0), "r"(b1));
}
__device__ __forceinline__ void splitpair(float x, float y, uint32_t& h, uint32_t& l) {
    __half hx = __float2half_rn(x), hy = __float2half_rn(y);
    __half lx = __float2half_rn(x - __half2float(hx));
    __half ly = __float2half_rn(y - __half2float(hy));
    __half2 hp = __halves2half2(hx, hy), lp = __halves2half2(lx, ly);
    h = *reinterpret_cast<uint32_t*>(&hp);
    l = *reinterpret_cast<uint32_t*>(&lp);
}
__device__ __forceinline__ void split1(float x, __half& h, __half& l) {
    h = __float2half_rn(x);
    l = __float2half_rn(x - __half2float(h));
}
__device__ __forceinline__ float fast_sigmoid(float x) {
    return __fdividef(1.f, 1.f + __expf(-x));
}

// ============================================================================
// f16x3 NT GEMM, pre-split hi/lo f16 operands, double-buffered cp.async.
// EPI 0: f32 store to C (+z*zstride).
// EPI 1: SYMMETRIC sigmoid GEMM (A==B), compact 528-CTA upper-tri grid;
//        off-diagonal blocks mirror-write via smem transpose; rowsum partials.
// ============================================================================
template<int BN, int EPI>
__global__ void __launch_bounds__(256, 2) gemm_f16(
    const __half* __restrict__ Ah, const __half* __restrict__ Al,
    const __half* __restrict__ Bh, const __half* __restrict__ Bl,
    float* __restrict__ C, int lda, int ldb, int ldc, int nch,
    long long zstride, float* __restrict__ rs,
    __half* __restrict__ oh, __half* __restrict__ ol)
{
    constexpr int TS   = 20;                 // u32 stride per row (16 data + 4 pad)
    constexpr int TT   = 136;                // transpose tile row stride (halfs)
    constexpr int NT2  = BN / 16;
    constexpr int ABUF = 128 * TS;
    constexpr int BBUF = BN * TS;
    constexpr int BUFSZ = 2 * ABUF + 2 * BBUF;
    extern __shared__ uint32_t smu[];

    int bxv, byv;
    if (EPI == 1) {                          // decode compact upper-triangular id
        int t = blockIdx.x, j = 0;
        while (t >= 32 - j) { t -= 32 - j; j++; }
        byv = j; bxv = j + t;
    } else {
        bxv = blockIdx.x; byv = blockIdx.y;
    }

    const int tid  = threadIdx.x;
    const int warp = tid >> 5, lane = tid & 31;
    const int g = lane >> 2, tg = lane & 3;
    const int wm = warp >> 1, wn = warp & 1;
    const int rm = wm * 32, cn = wn * (BN / 2);
    const int bm = byv * 128, bn = bxv * BN;
    const int kbeg = blockIdx.z * nch * 32;

    const uint32_t smu_u = smem_u32(smu);

    auto issue = [&](int c) {
        const int b = c & 1;
        const int k0 = kbeg + c * 32;
        const uint32_t base = smu_u + b * BUFSZ * 4;
#pragma unroll
        for (int i = 0; i < 2; i++) {
            int idx = tid + i * 256;
            int r = idx >> 2, q = idx & 3;
            const size_t go = (size_t)(bm + r) * lda + k0 + q * 8;
            cpa16(base + (r * TS + q * 4) * 4, Ah + go);
            cpa16(base + (ABUF + r * TS + q * 4) * 4, Al + go);
        }
#pragma unroll
        for (int i = 0; i < BN / 64; i++) {
            int idx = tid + i * 256;
            int r = idx >> 2, q = idx & 3;
            const size_t go = (size_t)(bn + r) * ldb + k0 + q * 8;
            cpa16(base + (2 * ABUF + r * TS + q * 4) * 4, Bh + go);
            cpa16(base + (2 * ABUF + BBUF + r * TS + q * 4) * 4, Bl + go);
        }
        asm volatile("cp.async.commit_group;" ::: "memory");
    };

    float acc[2][NT2][4];
#pragma unroll
    for (int mt = 0; mt < 2; mt++)
#pragma unroll
        for (int nt = 0; nt < NT2; nt++)
#pragma unroll
            for (int j = 0; j < 4; j++) acc[mt][nt][j] = 0.f;

    issue(0);
    for (int c = 0; c < nch; c++) {
        if (c + 1 < nch) {
            issue(c + 1);
            asm volatile("cp.async.wait_group 1;" ::: "memory");
        } else {
            asm volatile("cp.async.wait_group 0;" ::: "memory");
        }
        __syncthreads();

        const uint32_t* Athi = smu + (c & 1) * BUFSZ;
        const uint32_t* Atlo = Athi + ABUF;
        const uint32_t* Bthi = Athi + 2 * ABUF;
        const uint32_t* Btlo = Bthi + BBUF;

#pragma unroll
        for (int ks = 0; ks < 2; ks++) {
            const int kp = ks * 8;
            uint32_t ah[2][4], al[2][4];
#pragma unroll
            for (int mt = 0; mt < 2; mt++) {
                const int ro = (rm + mt * 16 + g) * TS;
                ah[mt][0] = Athi[ro + kp + tg];
                ah[mt][1] = Athi[ro + 8 * TS + kp + tg];
                ah[mt][2] = Athi[ro + kp + tg + 4];
                ah[mt][3] = Athi[ro + 8 * TS + kp + tg + 4];
                al[mt][0] = Atlo[ro + kp + tg];
                al[mt][1] = Atlo[ro + 8 * TS + kp + tg];
                al[mt][2] = Atlo[ro + kp + tg + 4];
                al[mt][3] = Atlo[ro + 8 * TS + kp + tg + 4];
            }
#pragma unroll
            for (int nt = 0; nt < NT2; nt++) {
                const int bo = (cn + nt * 8 + g) * TS + kp;
                uint32_t bh0 = Bthi[bo + tg], bh1 = Bthi[bo + tg + 4];
                uint32_t bl0 = Btlo[bo + tg], bl1 = Btlo[bo + tg + 4];
#pragma unroll
                for (int mt = 0; mt < 2; mt++) {
                    mma16(acc[mt][nt], ah[mt], bh0, bh1);
                    mma16(acc[mt][nt], ah[mt], bl0, bl1);
                    mma16(acc[mt][nt], al[mt], bh0, bh1);
                }
            }
        }
        __syncthreads();
    }

    // ---------------- epilogue ----------------
    __half* Th = reinterpret_cast<__half*>(smu);
    __half* Tl = Th + 128 * TT;
    const bool mirror = (EPI == 1) && (bxv != byv);

#pragma unroll
    for (int mt = 0; mt < 2; mt++) {
        const int r0l = rm + mt * 16 + g;
        const int r1l = r0l + 8;
        const int r0 = bm + r0l, r1 = bm + r1l;
        float s0 = 0.f, s1 = 0.f;
#pragma unroll
        for (int nt = 0; nt < NT2; nt++) {
            float c0 = acc[mt][nt][0], c1 = acc[mt][nt][1];
            float c2 = acc[mt][nt][2], c3 = acc[mt][nt][3];
            const int cl = cn + nt * 8 + 2 * tg;
            const int col = bn + cl;
            if (EPI == 1) {
                c0 = fast_sigmoid(c0); c1 = fast_sigmoid(c1);
                c2 = fast_sigmoid(c2); c3 = fast_sigmoid(c3);
                s0 += c0 + c1; s1 += c2 + c3;
                uint32_t h01, l01, h23, l23;
                splitpair(c0, c1, h01, l01);
                splitpair(c2, c3, h23, l23);
                *reinterpret_cast<uint32_t*>(oh + (size_t)r0 * ldc + col) = h01;
                *reinterpret_cast<uint32_t*>(ol + (size_t)r0 * ldc + col) = l01;
                *reinterpret_cast<uint32_t*>(oh + (size_t)r1 * ldc + col) = h23;
                *reinterpret_cast<uint32_t*>(ol + (size_t)r1 * ldc + col) = l23;
                if (mirror) {
                    __half2 H01 = *reinterpret_cast<__half2*>(&h01);
                    __half2 L01 = *reinterpret_cast<__half2*>(&l01);
                    __half2 H23 = *reinterpret_cast<__half2*>(&h23);
                    __half2 L23 = *reinterpret_cast<__half2*>(&l23);
                    Th[cl * TT + r0l]       = __low2half(H01);
                    Th[(cl + 1) * TT + r0l] = __high2half(H01);
                    Tl[cl * TT + r0l]       = __low2half(L01);
                    Tl[(cl + 1) * TT + r0l] = __high2half(L01);
                    Th[cl * TT + r1l]       = __low2half(H23);
                    Th[(cl + 1) * TT + r1l] = __high2half(H23);
                    Tl[cl * TT + r1l]       = __low2half(L23);
                    Tl[(cl + 1) * TT + r1l] = __high2half(L23);
                }
            } else {
                float* Cz = C + (size_t)blockIdx.z * zstride;
                *reinterpret_cast<float2*>(Cz + (size_t)r0 * ldc + col) = make_float2(c0, c1);
                *reinterpret_cast<float2*>(Cz + (size_t)r1 * ldc + col) = make_float2(c2, c3);
            }
        }
        if (EPI == 1) {
            s0 += __shfl_xor_sync(0xFFFFFFFFu, s0, 1);
            s0 += __shfl_xor_sync(0xFFFFFFFFu, s0, 2);
            s1 += __shfl_xor_sync(0xFFFFFFFFu, s1, 1);
            s1 += __shfl_xor_sync(0xFFFFFFFFu, s1, 2);
            if (tg == 0) {
                float* rp = rs + (size_t)(bxv * 2 + wn) * Nn;
                rp[r0] = s0;
                rp[r1] = s1;
            }
        }
    }

    if (mirror) {
        __syncthreads();
#pragma unroll
        for (int i = 0; i < 8; i++) {
            int c  = (tid >> 4) + i * 16;
            int ch = tid & 15;
            uint4 vh = *reinterpret_cast<const uint4*>(&Th[c * TT + ch * 8]);
            uint4 vl = *reinterpret_cast<const uint4*>(&Tl[c * TT + ch * 8]);
            *reinterpret_cast<uint4*>(oh + (size_t)(bn + c) * ldc + bm + ch * 8) = vh;
            *reinterpret_cast<uint4*>(ol + (size_t)(bn + c) * ldc + bm + ch * 8) = vl;
        }
        {
            int c = tid >> 1, half = tid & 1;
            const __half2* ph = reinterpret_cast<const __half2*>(&Th[c * TT + half * 64]);
            const __half2* pl = reinterpret_cast<const __half2*>(&Tl[c * TT + half * 64]);
            float s = 0.f;
#pragma unroll
            for (int k = 0; k < 32; k++) {
                float2 a = __half22float2(ph[k]);
                float2 b = __half22float2(pl[k]);
                s += a.x + a.y + b.x + b.y;
            }
            rs[(size_t)(byv * 2 + half) * Nn + bn + c] = s;
        }
    }
}

// ---------------- conversion / utility kernels ----------------
__global__ void conv_split(const float* __restrict__ in, __half* __restrict__ oh,
                           __half* __restrict__ ol, size_t n4) {
    size_t i = (size_t)blockIdx.x * blockDim.x + threadIdx.x;
    if (i >= n4) return;
    float4 v = reinterpret_cast<const float4*>(in)[i];
    uint32_t h01, l01, h23, l23;
    splitpair(v.x, v.y, h01, l01);
    splitpair(v.z, v.w, h23, l23);
    reinterpret_cast<uint2*>(oh)[i] = make_uint2(h01, h23);
    reinterpret_cast<uint2*>(ol)[i] = make_uint2(l01, l23);
}

__global__ void fill_zero4(float* p, size_t n4) {
    size_t i = (size_t)blockIdx.x * blockDim.x + threadIdx.x;
    if (i < n4) reinterpret_cast<float4*>(p)[i] = make_float4(0.f, 0.f, 0.f, 0.f);
}

__global__ void scatter_edges(const int* __restrict__ ei, const float* __restrict__ ew,
                              float* __restrict__ A, int E) {
    int t = blockIdx.x * blockDim.x + threadIdx.x;
    if (t < E) {
        int r = ei[t];
        int c = ei[E + t];
        atomicAdd(A + (size_t)r * Nn + c, ew[t]);
    }
}

__global__ void rowsum_kernel(const float* __restrict__ A, float* __restrict__ rs) {
    int row = blockIdx.x;
    const float4* p = reinterpret_cast<const float4*>(A + (size_t)row * Nn);
    float s = 0.f;
    for (int i = threadIdx.x; i < Nn / 4; i += blockDim.x) {
        float4 v = p[i];
        s += v.x + v.y + v.z + v.w;
    }
    __shared__ float sh[256];
    sh[threadIdx.x] = s;
    __syncthreads();
    for (int d = 128; d; d >>= 1) {
        if (threadIdx.x < d) sh[threadIdx.x] += sh[threadIdx.x + d];
        __syncthreads();
    }
    if (threadIdx.x == 0) rs[row] = sh[0];
}

__global__ void transpose_f16(const float* __restrict__ in, __half* __restrict__ oh,
                              __half* __restrict__ ol, int R, int Cc, float scale) {
    __shared__ float t[32][33];
    int bx = blockIdx.x * 32, by = blockIdx.y * 32;
    int x = bx + threadIdx.x;
    for (int dy = 0; dy < 32; dy += 8) {
        int y = by + threadIdx.y + dy;
        if (x < Cc && y < R) t[threadIdx.y + dy][threadIdx.x] = in[(size_t)y * Cc + x];
    }
    __syncthreads();
    int xo = by + threadIdx.x;
    for (int dy = 0; dy < 32; dy += 8) {
        int yo = bx + threadIdx.y + dy;
        if (xo < R && yo < Cc) {
            float v = t[threadIdx.x][threadIdx.y + dy] * scale;
            __half h, l;
            split1(v, h, l);
            oh[(size_t)yo * R + xo] = h;
            ol[(size_t)yo * R + xo] = l;
        }
    }
}

// ---------------- SIMT GEMM (final out only) ----------------
__global__ __launch_bounds__(256) void gemm_nn_splitk(
    const float* __restrict__ A, const float* __restrict__ B,
    float* __restrict__ part, int M, int Ncols, int K, int Kc)
{
    __shared__ float As[16][132];
    __shared__ float Bs[16][64];
    const int tid = threadIdx.x;
    const int tr = tid >> 4, tc = tid & 15;
    const int bm = blockIdx.y * 128, bn = blockIdx.x * 64;
    const int kbeg = blockIdx.z * Kc;

    float acc[8][4];
#pragma unroll
    for (int i = 0; i < 8; i++)
#pragma unroll
        for (int j = 0; j < 4; j++) acc[i][j] = 0.f;

    for (int k0 = kbeg; k0 < kbeg + Kc; k0 += 16) {
#pragma unroll
        for (int s = 0; s < 2; s++) {
            int slot = tid + s * 256;
            int r = slot >> 2, q = slot & 3;
            float4 va = *reinterpret_cast<const float4*>(A + (size_t)(bm + r) * K + k0 + q * 4);
            As[q * 4 + 0][r] = va.x; As[q * 4 + 1][r] = va.y;
            As[q * 4 + 2][r] = va.z; As[q * 4 + 3][r] = va.w;
        }
        {
            int r = tid >> 4, q = tid & 15;
            *reinterpret_cast<float4*>(&Bs[r][q * 4]) =
                *reinterpret_cast<const float4*>(B + (size_t)(k0 + r) * Ncols + bn + q * 4);
        }
        __syncthreads();
#pragma unroll
        for (int kk = 0; kk < 16; kk++) {
            float a[8], b[4];
            *reinterpret_cast<float4*>(&a[0]) = *reinterpret_cast<const float4*>(&As[kk][tr * 4]);
            *reinterpret_cast<float4*>(&a[4]) = *reinterpret_cast<const float4*>(&As[kk][64 + tr * 4]);
            *reinterpret_cast<float4*>(&b[0]) = *reinterpret_cast<const float4*>(&Bs[kk][tc * 4]);
#pragma unroll
            for (int i = 0; i < 8; i++)
#pragma unroll
                for (int j = 0; j < 4; j++) acc[i][j] += a[i] * b[j];
        }
        __syncthreads();
    }

    float* out = part + (size_t)blockIdx.z * M * Ncols;
#pragma unroll
    for (int i = 0; i < 8; i++) {
        int row = bm + ((i < 4) ? tr * 4 + i : 64 + tr * 4 + (i - 4));
        *reinterpret_cast<float4*>(out + (size_t)row * Ncols + bn + tc * 4) =
            make_float4(acc[i][0], acc[i][1], acc[i][2], acc[i][3]);
    }
}

__global__ void reduce_part(const float* __restrict__ part, float* __restrict__ out,
                            int M, int Ncols, int split, const float* __restrict__ bias,
                            float scale) {
    int idx = blockIdx.x * 256 + threadIdx.x;
    int total = M * Ncols;
    if (idx < total) {
        float s = 0.f;
        for (int p = 0; p < split; p++) s += part[(size_t)p * total + idx];
        s *= scale;
        if (bias) s += bias[idx % Ncols];
        out[idx] = s;
    }
}

// ---------------- attention: fused split-K reduce + coeffs + degree ----------------
__global__ void attention_kernel(const float* __restrict__ partA, const float* __restrict__ partB,
                                 const float* __restrict__ ab1,
                                 const float* __restrict__ aw2, const float* __restrict__ ab2,
                                 const float* __restrict__ rs0, const float* __restrict__ rspart,
                                 float* __restrict__ a0o, float* __restrict__ a1o,
                                 float* __restrict__ dinv, float invs) {
    int warp = (blockIdx.x * blockDim.x + threadIdx.x) >> 5;
    int lane = threadIdx.x & 31;
    if (warp >= Nn) return;
    float s0 = 0.f, s1 = 0.f;
    for (int t = lane; t < ATT; t += 32) {
        float p0 = 0.f, p1 = 0.f;
        const size_t base = (size_t)warp * ATT + t;
#pragma unroll
        for (int z = 0; z < 8; z++) {
            p0 += partA[(size_t)z * Nn * ATT + base];
            p1 += partB[(size_t)z * Nn * ATT + base];
        }
        float b = ab1[t], w2 = aw2[t];
        s0 += tanhf(p0 * invs + b) * w2;
        s1 += tanhf(p1 * invs + b) * w2;
    }
    float sr = rspart[(size_t)lane * Nn + warp] + rspart[(size_t)(lane + 32) * Nn + warp];
#pragma unroll
    for (int o = 16; o; o >>= 1) {
        s0 += __shfl_down_sync(0xFFFFFFFFu, s0, o);
        s1 += __shfl_down_sync(0xFFFFFFFFu, s1, o);
        sr += __shfl_down_sync(0xFFFFFFFFu, sr, o);
    }
    if (lane == 0) {
        float b2 = ab2[0];
        s0 += b2; s1 += b2;
        float m = fmaxf(s0, s1);
        float e0 = __expf(s0 - m), e1 = __expf(s1 - m);
        float inv = __fdividef(1.f, e0 + e1);
        float a0 = e0 * inv, a1 = e1 * inv;
        float deg = a0 * rs0[warp] + a1 * sr + 1.f;
        a0o[warp] = a0; a1o[warp] = a1;
        dinv[warp] = deg > 0.f ? rsqrtf(deg) : 0.f;
    }
}

// ---------------- A_m + final_A + An (f16 pairs) ----------------
__global__ void build_An(const __half* __restrict__ Aoh, const __half* __restrict__ Aol,
                         __half* __restrict__ Sh, __half* __restrict__ Sl,
                         const float* __restrict__ a0, const float* __restrict__ a1,
                         const float* __restrict__ dinv, float* __restrict__ finalA) {
    size_t gid = (size_t)blockIdx.x * blockDim.x + threadIdx.x;
    if (gid >= (size_t)Nn * Nn / 4) return;
    int i  = (int)(gid / (Nn / 4));
    int j4 = (int)(gid % (Nn / 4)) * 4;
    uint2 ohv = *reinterpret_cast<const uint2*>(Aoh + (size_t)i * Nn + j4);
    uint2 olv = *reinterpret_cast<const uint2*>(Aol + (size_t)i * Nn + j4);
    uint2 shv = *reinterpret_cast<const uint2*>(Sh + (size_t)i * Nn + j4);
    uint2 slv = *reinterpret_cast<const uint2*>(Sl + (size_t)i * Nn + j4);
    float2 oa = __half22float2(*reinterpret_cast<__half2*>(&ohv.x));
    float2 ob = __half22float2(*reinterpret_cast<__half2*>(&ohv.y));
    float2 oc = __half22float2(*reinterpret_cast<__half2*>(&olv.x));
    float2 od = __half22float2(*reinterpret_cast<__half2*>(&olv.y));
    float4 o = make_float4(oa.x + oc.x, oa.y + oc.y, ob.x + od.x, ob.y + od.y);
    float2 sa = __half22float2(*reinterpret_cast<__half2*>(&shv.x));
    float2 sb = __half22float2(*reinterpret_cast<__half2*>(&shv.y));
    float2 sc = __half22float2(*reinterpret_cast<__half2*>(&slv.x));
    float2 sd = __half22float2(*reinterpret_cast<__half2*>(&slv.y));
    float4 s = make_float4(sa.x + sc.x, sa.y + sc.y, sb.x + sd.x, sb.y + sd.y);
    float A0 = a0[i], A1 = a1[i], di = dinv[i] * SCALE_AN;
    float4 am;
    am.x = A0 * o.x + A1 * s.x;
    am.y = A0 * o.y + A1 * s.y;
    am.z = A0 * o.z + A1 * s.z;
    am.w = A0 * o.w + A1 * s.w;
    if (finalA) *reinterpret_cast<float4*>(finalA + (size_t)i * Nn + j4) = am;
    float4 dj = *reinterpret_cast<const float4*>(dinv + j4);
    float4 an;
    an.x = di * dj.x * (am.x + ((j4 + 0 == i) ? 1.f : 0.f));
    an.y = di * dj.y * (am.y + ((j4 + 1 == i) ? 1.f : 0.f));
    an.z = di * dj.z * (am.z + ((j4 + 2 == i) ? 1.f : 0.f));
    an.w = di * dj.w * (am.w + ((j4 + 3 == i) ? 1.f : 0.f));
    uint32_t nh01, nl01, nh23, nl23;
    splitpair(an.x, an.y, nh01, nl01);
    splitpair(an.z, an.w, nh23, nl23);
    *reinterpret_cast<uint2*>(Sh + (size_t)i * Nn + j4) = make_uint2(nh01, nh23);
    *reinterpret_cast<uint2*>(Sl + (size_t)i * Nn + j4) = make_uint2(nl01, nl23);
}

// ---------------- BatchNorm (two-pass) ----------------
__global__ void bn_stats(const float* __restrict__ H, int dout,
                         float* __restrict__ mu, float* __restrict__ var) {
    int col = blockIdx.x * 32 + threadIdx.x;
    __shared__ float sh[8][32];
    __shared__ float shm[32];

    float s = 0.f;
    for (int r = threadIdx.y; r < Nn; r += 8)
        s += H[(size_t)r * dout + col];
    sh[threadIdx.y][threadIdx.x] = s;
    __syncthreads();
    if (threadIdx.y == 0) {
#pragma unroll
        for (int y = 1; y < 8; y++) s += sh[y][threadIdx.x];
        shm[threadIdx.x] = s / (float)Nn;
    }
    __syncthreads();
    float m = shm[threadIdx.x];

    float s2 = 0.f;
    for (int r = threadIdx.y; r < Nn; r += 8) {
        float d = H[(size_t)r * dout + col] - m;
        s2 += d * d;
    }
    __syncthreads();
    sh[threadIdx.y][threadIdx.x] = s2;
    __syncthreads();
    if (threadIdx.y == 0) {
#pragma unroll
        for (int y = 1; y < 8; y++) s2 += sh[y][threadIdx.x];
        mu[col]  = m;
        var[col] = s2 / (float)Nn;
    }
}

__global__ void bn_apply(const float* __restrict__ Hin, float* __restrict__ Hout,
                         __half* __restrict__ oh, __half* __restrict__ ol, int dout,
                         const float* __restrict__ mu, const float* __restrict__ var,
                         const float* __restrict__ gamma, const float* __restrict__ beta) {
    int idx = blockIdx.x * 256 + threadIdx.x;
    if (idx < Nn * dout) {
        int c = idx % dout;
        float x = Hin[idx];
        float y = gamma[c] * (x - mu[c]) * rsqrtf(var[c] + 1e-5f) + beta[c];
        y = y > 0.f ? y : 0.01f * y;
        Hout[idx] = y;
        __half h, l;
        split1(y, h, l);
        oh[idx] = h;
        ol[idx] = l;
    }
}

// ---------------- host orchestration ----------------
extern "C" void kernel_launch(void* const* d_in, const int* in_sizes, int n_in,
                              void* d_out, int out_size) {
    const float* X  = (const float*)d_in[0];
    const int*   ei = (const int*)d_in[1];
    const float* ew = (const float*)d_in[2];
    const float *gw[3], *gb[3], *bng[3], *bnb[3], *aw1[3], *ab1[3], *aw2[3], *ab2[3];
    for (int i = 0; i < 3; i++) {
        int b = 3 + i * 8;
        gw[i]  = (const float*)d_in[b + 0];
        gb[i]  = (const float*)d_in[b + 1];
        bng[i] = (const float*)d_in[b + 2];
        bnb[i] = (const float*)d_in[b + 3];
        aw1[i] = (const float*)d_in[b + 4];
        ab1[i] = (const float*)d_in[b + 5];
        aw2[i] = (const float*)d_in[b + 6];
        ab2[i] = (const float*)d_in[b + 7];
    }
    const float* lw = (const float*)d_in[27];
    const float* lb = (const float*)d_in[28];
    const int E = in_sizes[2];

    float *Ao, *H, *H2, *HW, *part, *rspart, *a0, *a1, *dinv, *rs0, *mu, *var;
    __half *Aoh, *Aol, *Sh, *Sl, *hh, *hl, *HWTh, *HWTl, *AWTh, *AWTl, *GWTh, *GWTl;
    cudaGetSymbolAddress((void**)&Ao,     g_Aorig);
    cudaGetSymbolAddress((void**)&Aoh,    g_Aoh);
    cudaGetSymbolAddress((void**)&Aol,    g_Aol);
    cudaGetSymbolAddress((void**)&Sh,     g_Sh);
    cudaGetSymbolAddress((void**)&Sl,     g_Sl);
    cudaGetSymbolAddress((void**)&H,      g_H);
    cudaGetSymbolAddress((void**)&H2,     g_H2);
    cudaGetSymbolAddress((void**)&HW,     g_HW);
    cudaGetSymbolAddress((void**)&hh,     g_hh);
    cudaGetSymbolAddress((void**)&hl,     g_hl);
    cudaGetSymbolAddress((void**)&HWTh,   g_HWTh);
    cudaGetSymbolAddress((void**)&HWTl,   g_HWTl);
    cudaGetSymbolAddress((void**)&AWTh,   g_AWTh);
    cudaGetSymbolAddress((void**)&AWTl,   g_AWTl);
    cudaGetSymbolAddress((void**)&GWTh,   g_GWTh);
    cudaGetSymbolAddress((void**)&GWTl,   g_GWTl);
    cudaGetSymbolAddress((void**)&part,   g_part);
    cudaGetSymbolAddress((void**)&rspart, g_rspart);
    cudaGetSymbolAddress((void**)&a0,     g_a0);
    cudaGetSymbolAddress((void**)&a1,     g_a1);
    cudaGetSymbolAddress((void**)&dinv,   g_dinv);
    cudaGetSymbolAddress((void**)&rs0,    g_rs0);
    cudaGetSymbolAddress((void**)&mu,     g_mu);
    cudaGetSymbolAddress((void**)&var,    g_var);

    const int SM128 = 2 * (2 * 128 * 20 + 2 * 128 * 20) * 4;  // 81920
    const int SM64  = 2 * (2 * 128 * 20 + 2 *  64 * 20) * 4;  // 61440
    cudaFuncSetAttribute(gemm_f16<128, 1>, cudaFuncAttributeMaxDynamicSharedMemorySize, SM128);
    cudaFuncSetAttribute(gemm_f16<128, 0>, cudaFuncAttributeMaxDynamicSharedMemorySize, SM128);
    cudaFuncSetAttribute(gemm_f16<64, 0>,  cudaFuncAttributeMaxDynamicSharedMemorySize, SM64);

    // attn split-K partial buffers (both fit inside g_part)
    float* partA = part;
    float* partB = part + (size_t)8 * Nn * ATT;

    // 1..3: A_orig scatter + h split (keeps sigmoid GEMM as launch #4 for ncu)
    fill_zero4<<<(int)(((size_t)Nn * Nn / 4 + 255) / 256), 256>>>(Ao, (size_t)Nn * Nn / 4);
    scatter_edges<<<(E + 255) / 256, 256>>>(ei, ew, Ao, E);
    conv_split<<<(Nn * 256 / 4 + 255) / 256, 256>>>(X, hh, hl, Nn * 256 / 4);

    const int din[3] = {256, 256, 256};
    const int dof[3] = {256, 256, 128};

    for (int L = 0; L < 3; L++) {
        const int K = din[L], dout = dof[L];

        // S = sigmoid(h h^T): symmetric, compact 528-CTA grid
        gemm_f16<128, 1><<<dim3(528, 1, 1), 256, SM128>>>(
            hh, hl, hh, hl, nullptr, K, K, Nn, K / 32, 0LL, rspart, Sh, Sl);

        if (L == 0) {
            conv_split<<<(int)(((size_t)Nn * Nn / 4 + 255) / 256), 256>>>(
                Ao, Aoh, Aol, (size_t)Nn * Nn / 4);
            rowsum_kernel<<<Nn, 256>>>(Ao, rs0);
        }

        // attention projections (split-K 8) -> raw partials; reduce fused below
        transpose_f16<<<dim3(2, Nn / 32), dim3(32, 8)>>>(aw1[L], AWTh, AWTl, Nn, ATT, SCALE_AW);
        gemm_f16<64, 0><<<dim3(1, 32, 8), 256, SM64>>>(
            Aoh, Aol, AWTh, AWTl, partA, Nn, Nn, ATT, (Nn / 32) / 8,
            (long long)Nn * ATT, nullptr, nullptr, nullptr);
        gemm_f16<64, 0><<<dim3(1, 32, 8), 256, SM64>>>(
            Sh, Sl, AWTh, AWTl, partB, Nn, Nn, ATT, (Nn / 32) / 8,
            (long long)Nn * ATT, nullptr, nullptr, nullptr);

        attention_kernel<<<Nn / 4, 128>>>(partA, partB, ab1[L], aw2[L], ab2[L],
                                          rs0, rspart, a0, a1, dinv, 1.f / SCALE_AW);

        // HW = h @ gw via tensor GEMM (direct store), then HWT f16 pairs
        transpose_f16<<<dim3(dout / 32, K / 32), dim3(32, 8)>>>(gw[L], GWTh, GWTl, K, dout, 1.f);
        gemm_f16<128, 0><<<dim3(dout / 128, 32, 1), 256, SM128>>>(
            hh, hl, GWTh, GWTl, HW, K, K, dout, K / 32, 0LL, nullptr, nullptr, nullptr);
        transpose_f16<<<dim3(dout / 32, Nn / 32), dim3(32, 8)>>>(HW, HWTh, HWTl, Nn, dout, 1.f);

        // An (scaled, f16 pairs in place over S); final_A on last layer
        float* finalA = nullptr;
        if (L == 2 && out_size >= Nn * OUTD + Nn * Nn)
            finalA = (float*)d_out + (size_t)Nn * OUTD;
        build_An<<<16384, 256>>>(Aoh, Aol, Sh, Sl, a0, a1, dinv, finalA);

        // H2 = (An_scaled @ HW) / SCALE_AN + gb
        const int zsp = (dout == 256) ? 4 : 8;
        gemm_f16<128, 0><<<dim3(dout / 128, 32, zsp), 256, SM128>>>(
            Sh, Sl, HWTh, HWTl, part, Nn, Nn, dout, (Nn / 32) / zsp,
            (long long)Nn * dout, nullptr, nullptr, nullptr);
        reduce_part<<<(Nn * dout + 255) / 256, 256>>>(part, H2, Nn, dout, zsp, gb[L], 1.f / SCALE_AN);

        // BatchNorm + LeakyReLU -> H + f16 pairs for next layer
        bn_stats<<<dout / 32, dim3(32, 8)>>>(H2, dout, mu, var);
        bn_apply<<<(Nn * dout + 255) / 256, 256>>>(H2, H, hh, hl, dout, mu, var, bng[L], bnb[L]);
    }

    // out = h @ lin_w + lin_b (K=128, SIMT)
    gemm_nn_splitk<<<dim3(1, 32, 1), 256>>>(H, lw, part, Nn, OUTD, 128, 128);
    reduce_part<<<(Nn * OUTD + 255) / 256, 256>>>(part, (float*)d_out, Nn, OUTD, 1, lb, 1.f);
}

// round 13
// speedup vs baseline: 1.3135x; 1.0696x over previous
#include <cuda_runtime.h>
#include <cuda_fp16.h>
#include <math.h>
#include <stdint.h>

constexpr int Nn  = 4096;
constexpr int ATT = 64;
constexpr int OUTD = 64;
constexpr float SCALE_AN = 16384.f;
constexpr float SCALE_AW = 64.f;

// ---------------- scratch (device globals; no allocation allowed) ----------------
__device__ float  g_Aorig[(size_t)Nn * Nn];
__device__ __half g_Sh[(size_t)Nn * Nn];
__device__ __half g_Sl[(size_t)Nn * Nn];
__device__ float  g_H [Nn * 256];
__device__ float  g_H2[Nn * 256];
__device__ float  g_HW[Nn * 256];
__device__ __half g_hh[Nn * 256];
__device__ __half g_hl[Nn * 256];
__device__ __half g_HWTh[256 * Nn];
__device__ __half g_HWTl[256 * Nn];
__device__ __half g_AWTh[64 * Nn];
__device__ __half g_AWTl[64 * Nn];
__device__ __half g_GWTh[256 * 256];
__device__ __half g_GWTl[256 * 256];
__device__ float  g_part[(size_t)8 * Nn * 256];
__device__ float  g_P0[Nn * ATT];
__device__ float  g_rspart[64 * Nn];
__device__ float  g_a0[Nn], g_a1[Nn], g_dinv[Nn];
__device__ float  g_rs0[Nn];
__device__ float  g_mu[256], g_var[256];

// ---------------- helpers ----------------
__device__ __forceinline__ uint32_t smem_u32(const void* p) {
    uint32_t a;
    asm("{ .reg .u64 t; cvta.to.shared.u64 t, %1; cvt.u32.u64 %0, t; }" : "=r"(a) : "l"(p));
    return a;
}
__device__ __forceinline__ void cpa16(uint32_t dst, const void* src) {
    asm volatile("cp.async.cg.shared.global [%0], [%1], 16;" :: "r"(dst), "l"(src));
}
__device__ __forceinline__ void mma16(float (&c)[4], const uint32_t (&a)[4],
                                      uint32_t b0, uint32_t b1) {
    asm volatile(
        "mma.sync.aligned.m16n8k16.row.col.f32.f16.f16.f32 "
        "{%0,%1,%2,%3}, {%4,%5,%6,%7}, {%8,%9}, {%0,%1,%2,%3};"
        : "+f"(c[0]), "+f"(c[1]), "+f"(c[2]), "+f"(c[3])
        : "r"(a[0]), "r"(a[1]), "r"(a[2]), "r"(a[3]), "r"(b0), "r"(b1));
}
__device__ __forceinline__ void splitpair(float x, float y, uint32_t& h, uint32_t& l) {
    __half hx = __float2half_rn(x), hy = __float2half_rn(y);
    __half lx = __float2half_rn(x - __half2float(hx));
    __half ly = __float2half_rn(y - __half2float(hy));
    __half2 hp = __halves2half2(hx, hy), lp = __halves2half2(lx, ly);
    h = *reinterpret_cast<uint32_t*>(&hp);
    l = *reinterpret_cast<uint32_t*>(&lp);
}
__device__ __forceinline__ void split1(float x, __half& h, __half& l) {
    h = __float2half_rn(x);
    l = __float2half_rn(x - __half2float(h));
}
__device__ __forceinline__ float fast_sigmoid(float x) {
    return __fdividef(1.f, 1.f + __expf(-x));
}

// ============================================================================
// f16x3 NT GEMM, pre-split hi/lo f16 operands, double-buffered cp.async.
// EPI 0: f32 store to C (+z*zstride).
// EPI 1: SYMMETRIC sigmoid GEMM (A==B), compact 528-CTA upper-tri grid;
//        off-diagonal blocks mirror-write via smem transpose; rowsum partials.
// ============================================================================
template<int BN, int EPI>
__global__ void __launch_bounds__(256, 2) gemm_f16(
    const __half* __restrict__ Ah, const __half* __restrict__ Al,
    const __half* __restrict__ Bh, const __half* __restrict__ Bl,
    float* __restrict__ C, int lda, int ldb, int ldc, int nch,
    long long zstride, float* __restrict__ rs,
    __half* __restrict__ oh, __half* __restrict__ ol)
{
    constexpr int TS   = 20;
    constexpr int TT   = 136;
    constexpr int NT2  = BN / 16;
    constexpr int ABUF = 128 * TS;
    constexpr int BBUF = BN * TS;
    constexpr int BUFSZ = 2 * ABUF + 2 * BBUF;
    extern __shared__ uint32_t smu[];

    int bxv, byv;
    if (EPI == 1) {
        int t = blockIdx.x, j = 0;
        while (t >= 32 - j) { t -= 32 - j; j++; }
        byv = j; bxv = j + t;
    } else {
        bxv = blockIdx.x; byv = blockIdx.y;
    }

    const int tid  = threadIdx.x;
    const int warp = tid >> 5, lane = tid & 31;
    const int g = lane >> 2, tg = lane & 3;
    const int wm = warp >> 1, wn = warp & 1;
    const int rm = wm * 32, cn = wn * (BN / 2);
    const int bm = byv * 128, bn = bxv * BN;
    const int kbeg = blockIdx.z * nch * 32;

    const uint32_t smu_u = smem_u32(smu);

    auto issue = [&](int c) {
        const int b = c & 1;
        const int k0 = kbeg + c * 32;
        const uint32_t base = smu_u + b * BUFSZ * 4;
#pragma unroll
        for (int i = 0; i < 2; i++) {
            int idx = tid + i * 256;
            int r = idx >> 2, q = idx & 3;
            const size_t go = (size_t)(bm + r) * lda + k0 + q * 8;
            cpa16(base + (r * TS + q * 4) * 4, Ah + go);
            cpa16(base + (ABUF + r * TS + q * 4) * 4, Al + go);
        }
#pragma unroll
        for (int i = 0; i < BN / 64; i++) {
            int idx = tid + i * 256;
            int r = idx >> 2, q = idx & 3;
            const size_t go = (size_t)(bn + r) * ldb + k0 + q * 8;
            cpa16(base + (2 * ABUF + r * TS + q * 4) * 4, Bh + go);
            cpa16(base + (2 * ABUF + BBUF + r * TS + q * 4) * 4, Bl + go);
        }
        asm volatile("cp.async.commit_group;" ::: "memory");
    };

    float acc[2][NT2][4];
#pragma unroll
    for (int mt = 0; mt < 2; mt++)
#pragma unroll
        for (int nt = 0; nt < NT2; nt++)
#pragma unroll
            for (int j = 0; j < 4; j++) acc[mt][nt][j] = 0.f;

    issue(0);
    for (int c = 0; c < nch; c++) {
        if (c + 1 < nch) {
            issue(c + 1);
            asm volatile("cp.async.wait_group 1;" ::: "memory");
        } else {
            asm volatile("cp.async.wait_group 0;" ::: "memory");
        }
        __syncthreads();

        const uint32_t* Athi = smu + (c & 1) * BUFSZ;
        const uint32_t* Atlo = Athi + ABUF;
        const uint32_t* Bthi = Athi + 2 * ABUF;
        const uint32_t* Btlo = Bthi + BBUF;

#pragma unroll
        for (int ks = 0; ks < 2; ks++) {
            const int kp = ks * 8;
            uint32_t ah[2][4], al[2][4];
#pragma unroll
            for (int mt = 0; mt < 2; mt++) {
                const int ro = (rm + mt * 16 + g) * TS;
                ah[mt][0] = Athi[ro + kp + tg];
                ah[mt][1] = Athi[ro + 8 * TS + kp + tg];
                ah[mt][2] = Athi[ro + kp + tg + 4];
                ah[mt][3] = Athi[ro + 8 * TS + kp + tg + 4];
                al[mt][0] = Atlo[ro + kp + tg];
                al[mt][1] = Atlo[ro + 8 * TS + kp + tg];
                al[mt][2] = Atlo[ro + kp + tg + 4];
                al[mt][3] = Atlo[ro + 8 * TS + kp + tg + 4];
            }
#pragma unroll
            for (int nt = 0; nt < NT2; nt++) {
                const int bo = (cn + nt * 8 + g) * TS + kp;
                uint32_t bh0 = Bthi[bo + tg], bh1 = Bthi[bo + tg + 4];
                uint32_t bl0 = Btlo[bo + tg], bl1 = Btlo[bo + tg + 4];
#pragma unroll
                for (int mt = 0; mt < 2; mt++) {
                    mma16(acc[mt][nt], ah[mt], bh0, bh1);
                    mma16(acc[mt][nt], ah[mt], bl0, bl1);
                    mma16(acc[mt][nt], al[mt], bh0, bh1);
                }
            }
        }
        __syncthreads();
    }

    // ---------------- epilogue ----------------
    __half* Th = reinterpret_cast<__half*>(smu);
    __half* Tl = Th + 128 * TT;
    const bool mirror = (EPI == 1) && (bxv != byv);

#pragma unroll
    for (int mt = 0; mt < 2; mt++) {
        const int r0l = rm + mt * 16 + g;
        const int r1l = r0l + 8;
        const int r0 = bm + r0l, r1 = bm + r1l;
        float s0 = 0.f, s1 = 0.f;
#pragma unroll
        for (int nt = 0; nt < NT2; nt++) {
            float c0 = acc[mt][nt][0], c1 = acc[mt][nt][1];
            float c2 = acc[mt][nt][2], c3 = acc[mt][nt][3];
            const int cl = cn + nt * 8 + 2 * tg;
            const int col = bn + cl;
            if (EPI == 1) {
                c0 = fast_sigmoid(c0); c1 = fast_sigmoid(c1);
                c2 = fast_sigmoid(c2); c3 = fast_sigmoid(c3);
                s0 += c0 + c1; s1 += c2 + c3;
                uint32_t h01, l01, h23, l23;
                splitpair(c0, c1, h01, l01);
                splitpair(c2, c3, h23, l23);
                *reinterpret_cast<uint32_t*>(oh + (size_t)r0 * ldc + col) = h01;
                *reinterpret_cast<uint32_t*>(ol + (size_t)r0 * ldc + col) = l01;
                *reinterpret_cast<uint32_t*>(oh + (size_t)r1 * ldc + col) = h23;
                *reinterpret_cast<uint32_t*>(ol + (size_t)r1 * ldc + col) = l23;
                if (mirror) {
                    __half2 H01 = *reinterpret_cast<__half2*>(&h01);
                    __half2 L01 = *reinterpret_cast<__half2*>(&l01);
                    __half2 H23 = *reinterpret_cast<__half2*>(&h23);
                    __half2 L23 = *reinterpret_cast<__half2*>(&l23);
                    Th[cl * TT + r0l]       = __low2half(H01);
                    Th[(cl + 1) * TT + r0l] = __high2half(H01);
                    Tl[cl * TT + r0l]       = __low2half(L01);
                    Tl[(cl + 1) * TT + r0l] = __high2half(L01);
                    Th[cl * TT + r1l]       = __low2half(H23);
                    Th[(cl + 1) * TT + r1l] = __high2half(H23);
                    Tl[cl * TT + r1l]       = __low2half(L23);
                    Tl[(cl + 1) * TT + r1l] = __high2half(L23);
                }
            } else {
                float* Cz = C + (size_t)blockIdx.z * zstride;
                *reinterpret_cast<float2*>(Cz + (size_t)r0 * ldc + col) = make_float2(c0, c1);
                *reinterpret_cast<float2*>(Cz + (size_t)r1 * ldc + col) = make_float2(c2, c3);
            }
        }
        if (EPI == 1) {
            s0 += __shfl_xor_sync(0xFFFFFFFFu, s0, 1);
            s0 += __shfl_xor_sync(0xFFFFFFFFu, s0, 2);
            s1 += __shfl_xor_sync(0xFFFFFFFFu, s1, 1);
            s1 += __shfl_xor_sync(0xFFFFFFFFu, s1, 2);
            if (tg == 0) {
                float* rp = rs + (size_t)(bxv * 2 + wn) * Nn;
                rp[r0] = s0;
                rp[r1] = s1;
            }
        }
    }

    if (mirror) {
        __syncthreads();
#pragma unroll
        for (int i = 0; i < 8; i++) {
            int c  = (tid >> 4) + i * 16;
            int ch = tid & 15;
            uint4 vh = *reinterpret_cast<const uint4*>(&Th[c * TT + ch * 8]);
            uint4 vl = *reinterpret_cast<const uint4*>(&Tl[c * TT + ch * 8]);
            *reinterpret_cast<uint4*>(oh + (size_t)(bn + c) * ldc + bm + ch * 8) = vh;
            *reinterpret_cast<uint4*>(ol + (size_t)(bn + c) * ldc + bm + ch * 8) = vl;
        }
        {
            int c = tid >> 1, half = tid & 1;
            const __half2* ph = reinterpret_cast<const __half2*>(&Th[c * TT + half * 64]);
            const __half2* pl = reinterpret_cast<const __half2*>(&Tl[c * TT + half * 64]);
            float s = 0.f;
#pragma unroll
            for (int k = 0; k < 32; k++) {
                float2 a = __half22float2(ph[k]);
                float2 b = __half22float2(pl[k]);
                s += a.x + a.y + b.x + b.y;
            }
            rs[(size_t)(byv * 2 + half) * Nn + bn + c] = s;
        }
    }
}

// ---------------- conversion / utility kernels ----------------
__global__ void conv_split(const float* __restrict__ in, __half* __restrict__ oh,
                           __half* __restrict__ ol, size_t n4) {
    size_t i = (size_t)blockIdx.x * blockDim.x + threadIdx.x;
    if (i >= n4) return;
    float4 v = reinterpret_cast<const float4*>(in)[i];
    uint32_t h01, l01, h23, l23;
    splitpair(v.x, v.y, h01, l01);
    splitpair(v.z, v.w, h23, l23);
    reinterpret_cast<uint2*>(oh)[i] = make_uint2(h01, h23);
    reinterpret_cast<uint2*>(ol)[i] = make_uint2(l01, l23);
}

__global__ void fill_zero4(float* p, size_t n4) {
    size_t i = (size_t)blockIdx.x * blockDim.x + threadIdx.x;
    if (i < n4) reinterpret_cast<float4*>(p)[i] = make_float4(0.f, 0.f, 0.f, 0.f);
}

__global__ void scatter_edges(const int* __restrict__ ei, const float* __restrict__ ew,
                              float* __restrict__ A, int E) {
    int t = blockIdx.x * blockDim.x + threadIdx.x;
    if (t < E) {
        int r = ei[t];
        int c = ei[E + t];
        atomicAdd(A + (size_t)r * Nn + c, ew[t]);
    }
}

// sparse P0 = A_orig @ aw1: one warp per edge, 64 cols, fp32 atomics (exact)
__global__ void sparse_p0(const int* __restrict__ ei, const float* __restrict__ ew,
                          const float* __restrict__ aw1, float* __restrict__ P0, int E) {
    int e = (blockIdx.x * blockDim.x + threadIdx.x) >> 5;
    int lane = threadIdx.x & 31;
    if (e >= E) return;
    int r = ei[e], c = ei[E + e];
    float w = ew[e];
    float2 v = *reinterpret_cast<const float2*>(aw1 + (size_t)c * ATT + lane * 2);
    atomicAdd(P0 + (size_t)r * ATT + lane * 2,     w * v.x);
    atomicAdd(P0 + (size_t)r * ATT + lane * 2 + 1, w * v.y);
}

__global__ void rowsum_kernel(const float* __restrict__ A, float* __restrict__ rs) {
    int row = blockIdx.x;
    const float4* p = reinterpret_cast<const float4*>(A + (size_t)row * Nn);
    float s = 0.f;
    for (int i = threadIdx.x; i < Nn / 4; i += blockDim.x) {
        float4 v = p[i];
        s += v.x + v.y + v.z + v.w;
    }
    __shared__ float sh[256];
    sh[threadIdx.x] = s;
    __syncthreads();
    for (int d = 128; d; d >>= 1) {
        if (threadIdx.x < d) sh[threadIdx.x] += sh[threadIdx.x + d];
        __syncthreads();
    }
    if (threadIdx.x == 0) rs[row] = sh[0];
}

__global__ void transpose_f16(const float* __restrict__ in, __half* __restrict__ oh,
                              __half* __restrict__ ol, int R, int Cc, float scale) {
    __shared__ float t[32][33];
    int bx = blockIdx.x * 32, by = blockIdx.y * 32;
    int x = bx + threadIdx.x;
    for (int dy = 0; dy < 32; dy += 8) {
        int y = by + threadIdx.y + dy;
        if (x < Cc && y < R) t[threadIdx.y + dy][threadIdx.x] = in[(size_t)y * Cc + x];
    }
    __syncthreads();
    int xo = by + threadIdx.x;
    for (int dy = 0; dy < 32; dy += 8) {
        int yo = bx + threadIdx.y + dy;
        if (xo < R && yo < Cc) {
            float v = t[threadIdx.x][threadIdx.y + dy] * scale;
            __half h, l;
            split1(v, h, l);
            oh[(size_t)yo * R + xo] = h;
            ol[(size_t)yo * R + xo] = l;
        }
    }
}

// ---------------- SIMT GEMM (final out only) ----------------
__global__ __launch_bounds__(256) void gemm_nn_splitk(
    const float* __restrict__ A, const float* __restrict__ B,
    float* __restrict__ part, int M, int Ncols, int K, int Kc)
{
    __shared__ float As[16][132];
    __shared__ float Bs[16][64];
    const int tid = threadIdx.x;
    const int tr = tid >> 4, tc = tid & 15;
    const int bm = blockIdx.y * 128, bn = blockIdx.x * 64;
    const int kbeg = blockIdx.z * Kc;

    float acc[8][4];
#pragma unroll
    for (int i = 0; i < 8; i++)
#pragma unroll
        for (int j = 0; j < 4; j++) acc[i][j] = 0.f;

    for (int k0 = kbeg; k0 < kbeg + Kc; k0 += 16) {
#pragma unroll
        for (int s = 0; s < 2; s++) {
            int slot = tid + s * 256;
            int r = slot >> 2, q = slot & 3;
            float4 va = *reinterpret_cast<const float4*>(A + (size_t)(bm + r) * K + k0 + q * 4);
            As[q * 4 + 0][r] = va.x; As[q * 4 + 1][r] = va.y;
            As[q * 4 + 2][r] = va.z; As[q * 4 + 3][r] = va.w;
        }
        {
            int r = tid >> 4, q = tid & 15;
            *reinterpret_cast<float4*>(&Bs[r][q * 4]) =
                *reinterpret_cast<const float4*>(B + (size_t)(k0 + r) * Ncols + bn + q * 4);
        }
        __syncthreads();
#pragma unroll
        for (int kk = 0; kk < 16; kk++) {
            float a[8], b[4];
            *reinterpret_cast<float4*>(&a[0]) = *reinterpret_cast<const float4*>(&As[kk][tr * 4]);
            *reinterpret_cast<float4*>(&a[4]) = *reinterpret_cast<const float4*>(&As[kk][64 + tr * 4]);
            *reinterpret_cast<float4*>(&b[0]) = *reinterpret_cast<const float4*>(&Bs[kk][tc * 4]);
#pragma unroll
            for (int i = 0; i < 8; i++)
#pragma unroll
                for (int j = 0; j < 4; j++) acc[i][j] += a[i] * b[j];
        }
        __syncthreads();
    }

    float* out = part + (size_t)blockIdx.z * M * Ncols;
#pragma unroll
    for (int i = 0; i < 8; i++) {
        int row = bm + ((i < 4) ? tr * 4 + i : 64 + tr * 4 + (i - 4));
        *reinterpret_cast<float4*>(out + (size_t)row * Ncols + bn + tc * 4) =
            make_float4(acc[i][0], acc[i][1], acc[i][2], acc[i][3]);
    }
}

__global__ void reduce_part(const float* __restrict__ part, float* __restrict__ out,
                            int M, int Ncols, int split, const float* __restrict__ bias,
                            float scale) {
    int idx = blockIdx.x * 256 + threadIdx.x;
    int total = M * Ncols;
    if (idx < total) {
        float s = 0.f;
        for (int p = 0; p < split; p++) s += part[(size_t)p * total + idx];
        s *= scale;
        if (bias) s += bias[idx % Ncols];
        out[idx] = s;
    }
}

// ---------------- attention: P0 dense read + partB reduce + coeffs ----------------
__global__ void attention_kernel(const float* __restrict__ P0, const float* __restrict__ partB,
                                 const float* __restrict__ ab1,
                                 const float* __restrict__ aw2, const float* __restrict__ ab2,
                                 const float* __restrict__ rs0, const float* __restrict__ rspart,
                                 float* __restrict__ a0o, float* __restrict__ a1o,
                                 float* __restrict__ dinv, float invs) {
    int warp = (blockIdx.x * blockDim.x + threadIdx.x) >> 5;
    int lane = threadIdx.x & 31;
    if (warp >= Nn) return;
    float s0 = 0.f, s1 = 0.f;
    for (int t = lane; t < ATT; t += 32) {
        const size_t base = (size_t)warp * ATT + t;
        float p1 = 0.f;
#pragma unroll
        for (int z = 0; z < 8; z++) p1 += partB[(size_t)z * Nn * ATT + base];
        float b = ab1[t], w2 = aw2[t];
        s0 += tanhf(P0[base] + b) * w2;
        s1 += tanhf(p1 * invs + b) * w2;
    }
    float sr = rspart[(size_t)lane * Nn + warp] + rspart[(size_t)(lane + 32) * Nn + warp];
#pragma unroll
    for (int o = 16; o; o >>= 1) {
        s0 += __shfl_down_sync(0xFFFFFFFFu, s0, o);
        s1 += __shfl_down_sync(0xFFFFFFFFu, s1, o);
        sr += __shfl_down_sync(0xFFFFFFFFu, sr, o);
    }
    if (lane == 0) {
        float b2 = ab2[0];
        s0 += b2; s1 += b2;
        float m = fmaxf(s0, s1);
        float e0 = __expf(s0 - m), e1 = __expf(s1 - m);
        float inv = __fdividef(1.f, e0 + e1);
        float a0 = e0 * inv, a1 = e1 * inv;
        float deg = a0 * rs0[warp] + a1 * sr + 1.f;
        a0o[warp] = a0; a1o[warp] = a1;
        dinv[warp] = deg > 0.f ? rsqrtf(deg) : 0.f;
    }
}

// ---------------- A_m + final_A + An (f16 pairs, Ao from f32) ----------------
__global__ void build_An(const float* __restrict__ Ao,
                         __half* __restrict__ Sh, __half* __restrict__ Sl,
                         const float* __restrict__ a0, const float* __restrict__ a1,
                         const float* __restrict__ dinv, float* __restrict__ finalA) {
    size_t gid = (size_t)blockIdx.x * blockDim.x + threadIdx.x;
    if (gid >= (size_t)Nn * Nn / 4) return;
    int i  = (int)(gid / (Nn / 4));
    int j4 = (int)(gid % (Nn / 4)) * 4;
    float4 o = *reinterpret_cast<const float4*>(Ao + (size_t)i * Nn + j4);
    uint2 shv = *reinterpret_cast<const uint2*>(Sh + (size_t)i * Nn + j4);
    uint2 slv = *reinterpret_cast<const uint2*>(Sl + (size_t)i * Nn + j4);
    float2 sa = __half22float2(*reinterpret_cast<__half2*>(&shv.x));
    float2 sb = __half22float2(*reinterpret_cast<__half2*>(&shv.y));
    float2 sc = __half22float2(*reinterpret_cast<__half2*>(&slv.x));
    float2 sd = __half22float2(*reinterpret_cast<__half2*>(&slv.y));
    float4 s = make_float4(sa.x + sc.x, sa.y + sc.y, sb.x + sd.x, sb.y + sd.y);
    float A0 = a0[i], A1 = a1[i], di = dinv[i] * SCALE_AN;
    float4 am;
    am.x = A0 * o.x + A1 * s.x;
    am.y = A0 * o.y + A1 * s.y;
    am.z = A0 * o.z + A1 * s.z;
    am.w = A0 * o.w + A1 * s.w;
    if (finalA) *reinterpret_cast<float4*>(finalA + (size_t)i * Nn + j4) = am;
    float4 dj = *reinterpret_cast<const float4*>(dinv + j4);
    float4 an;
    an.x = di * dj.x * (am.x + ((j4 + 0 == i) ? 1.f : 0.f));
    an.y = di * dj.y * (am.y + ((j4 + 1 == i) ? 1.f : 0.f));
    an.z = di * dj.z * (am.z + ((j4 + 2 == i) ? 1.f : 0.f));
    an.w = di * dj.w * (am.w + ((j4 + 3 == i) ? 1.f : 0.f));
    uint32_t nh01, nl01, nh23, nl23;
    splitpair(an.x, an.y, nh01, nl01);
    splitpair(an.z, an.w, nh23, nl23);
    *reinterpret_cast<uint2*>(Sh + (size_t)i * Nn + j4) = make_uint2(nh01, nh23);
    *reinterpret_cast<uint2*>(Sl + (size_t)i * Nn + j4) = make_uint2(nl01, nl23);
}

// ---------------- BatchNorm (two-pass) ----------------
__global__ void bn_stats(const float* __restrict__ H, int dout,
                         float* __restrict__ mu, float* __restrict__ var) {
    int col = blockIdx.x * 32 + threadIdx.x;
    __shared__ float sh[8][32];
    __shared__ float shm[32];

    float s = 0.f;
    for (int r = threadIdx.y; r < Nn; r += 8)
        s += H[(size_t)r * dout + col];
    sh[threadIdx.y][threadIdx.x] = s;
    __syncthreads();
    if (threadIdx.y == 0) {
#pragma unroll
        for (int y = 1; y < 8; y++) s += sh[y][threadIdx.x];
        shm[threadIdx.x] = s / (float)Nn;
    }
    __syncthreads();
    float m = shm[threadIdx.x];

    float s2 = 0.f;
    for (int r = threadIdx.y; r < Nn; r += 8) {
        float d = H[(size_t)r * dout + col] - m;
        s2 += d * d;
    }
    __syncthreads();
    sh[threadIdx.y][threadIdx.x] = s2;
    __syncthreads();
    if (threadIdx.y == 0) {
#pragma unroll
        for (int y = 1; y < 8; y++) s2 += sh[y][threadIdx.x];
        mu[col]  = m;
        var[col] = s2 / (float)Nn;
    }
}

__global__ void bn_apply(const float* __restrict__ Hin, float* __restrict__ Hout,
                         __half* __restrict__ oh, __half* __restrict__ ol, int dout,
                         const float* __restrict__ mu, const float* __restrict__ var,
                         const float* __restrict__ gamma, const float* __restrict__ beta) {
    int idx = blockIdx.x * 256 + threadIdx.x;
    if (idx < Nn * dout) {
        int c = idx % dout;
        float x = Hin[idx];
        float y = gamma[c] * (x - mu[c]) * rsqrtf(var[c] + 1e-5f) + beta[c];
        y = y > 0.f ? y : 0.01f * y;
        Hout[idx] = y;
        __half h, l;
        split1(y, h, l);
        oh[idx] = h;
        ol[idx] = l;
    }
}

// ---------------- host orchestration ----------------
extern "C" void kernel_launch(void* const* d_in, const int* in_sizes, int n_in,
                              void* d_out, int out_size) {
    const float* X  = (const float*)d_in[0];
    const int*   ei = (const int*)d_in[1];
    const float* ew = (const float*)d_in[2];
    const float *gw[3], *gb[3], *bng[3], *bnb[3], *aw1[3], *ab1[3], *aw2[3], *ab2[3];
    for (int i = 0; i < 3; i++) {
        int b = 3 + i * 8;
        gw[i]  = (const float*)d_in[b + 0];
        gb[i]  = (const float*)d_in[b + 1];
        bng[i] = (const float*)d_in[b + 2];
        bnb[i] = (const float*)d_in[b + 3];
        aw1[i] = (const float*)d_in[b + 4];
        ab1[i] = (const float*)d_in[b + 5];
        aw2[i] = (const float*)d_in[b + 6];
        ab2[i] = (const float*)d_in[b + 7];
    }
    const float* lw = (const float*)d_in[27];
    const float* lb = (const float*)d_in[28];
    const int E = in_sizes[2];

    float *Ao, *H, *H2, *HW, *part, *P0, *rspart, *a0, *a1, *dinv, *rs0, *mu, *var;
    __half *Sh, *Sl, *hh, *hl, *HWTh, *HWTl, *AWTh, *AWTl, *GWTh, *GWTl;
    cudaGetSymbolAddress((void**)&Ao,     g_Aorig);
    cudaGetSymbolAddress((void**)&Sh,     g_Sh);
    cudaGetSymbolAddress((void**)&Sl,     g_Sl);
    cudaGetSymbolAddress((void**)&H,      g_H);
    cudaGetSymbolAddress((void**)&H2,     g_H2);
    cudaGetSymbolAddress((void**)&HW,     g_HW);
    cudaGetSymbolAddress((void**)&hh,     g_hh);
    cudaGetSymbolAddress((void**)&hl,     g_hl);
    cudaGetSymbolAddress((void**)&HWTh,   g_HWTh);
    cudaGetSymbolAddress((void**)&HWTl,   g_HWTl);
    cudaGetSymbolAddress((void**)&AWTh,   g_AWTh);
    cudaGetSymbolAddress((void**)&AWTl,   g_AWTl);
    cudaGetSymbolAddress((void**)&GWTh,   g_GWTh);
    cudaGetSymbolAddress((void**)&GWTl,   g_GWTl);
    cudaGetSymbolAddress((void**)&part,   g_part);
    cudaGetSymbolAddress((void**)&P0,     g_P0);
    cudaGetSymbolAddress((void**)&rspart, g_rspart);
    cudaGetSymbolAddress((void**)&a0,     g_a0);
    cudaGetSymbolAddress((void**)&a1,     g_a1);
    cudaGetSymbolAddress((void**)&dinv,   g_dinv);
    cudaGetSymbolAddress((void**)&rs0,    g_rs0);
    cudaGetSymbolAddress((void**)&mu,     g_mu);
    cudaGetSymbolAddress((void**)&var,    g_var);

    const int SM128 = 2 * (2 * 128 * 20 + 2 * 128 * 20) * 4;  // 81920
    const int SM64  = 2 * (2 * 128 * 20 + 2 *  64 * 20) * 4;  // 61440
    cudaFuncSetAttribute(gemm_f16<128, 1>, cudaFuncAttributeMaxDynamicSharedMemorySize, SM128);
    cudaFuncSetAttribute(gemm_f16<128, 0>, cudaFuncAttributeMaxDynamicSharedMemorySize, SM128);
    cudaFuncSetAttribute(gemm_f16<64, 0>,  cudaFuncAttributeMaxDynamicSharedMemorySize, SM64);

    float* partB = part + (size_t)8 * Nn * ATT;

    // 1..3: A_orig scatter + h split (keeps sigmoid GEMM as launch #4 for ncu)
    fill_zero4<<<(int)(((size_t)Nn * Nn / 4 + 255) / 256), 256>>>(Ao, (size_t)Nn * Nn / 4);
    scatter_edges<<<(E + 255) / 256, 256>>>(ei, ew, Ao, E);
    conv_split<<<(Nn * 256 / 4 + 255) / 256, 256>>>(X, hh, hl, Nn * 256 / 4);

    const int din[3] = {256, 256, 256};
    const int dof[3] = {256, 256, 128};

    for (int L = 0; L < 3; L++) {
        const int K = din[L], dout = dof[L];

        // S = sigmoid(h h^T): symmetric, compact 528-CTA grid
        gemm_f16<128, 1><<<dim3(528, 1, 1), 256, SM128>>>(
            hh, hl, hh, hl, nullptr, K, K, Nn, K / 32, 0LL, rspart, Sh, Sl);

        if (L == 0) rowsum_kernel<<<Nn, 256>>>(Ao, rs0);

        // P0 = A_orig @ aw1 (sparse, exact); P1 = S @ (64*aw1) dense split-K 8
        fill_zero4<<<Nn * ATT / 4 / 256, 256>>>(P0, Nn * ATT / 4);
        sparse_p0<<<(E * 32 + 255) / 256, 256>>>(ei, ew, aw1[L], P0, E);
        transpose_f16<<<dim3(2, Nn / 32), dim3(32, 8)>>>(aw1[L], AWTh, AWTl, Nn, ATT, SCALE_AW);
        gemm_f16<64, 0><<<dim3(1, 32, 8), 256, SM64>>>(
            Sh, Sl, AWTh, AWTl, partB, Nn, Nn, ATT, (Nn / 32) / 8,
            (long long)Nn * ATT, nullptr, nullptr, nullptr);

        attention_kernel<<<Nn / 4, 128>>>(P0, partB, ab1[L], aw2[L], ab2[L],
                                          rs0, rspart, a0, a1, dinv, 1.f / SCALE_AW);

        // HW = h @ gw via tensor GEMM, then HWT f16 pairs
        transpose_f16<<<dim3(dout / 32, K / 32), dim3(32, 8)>>>(gw[L], GWTh, GWTl, K, dout, 1.f);
        gemm_f16<128, 0><<<dim3(dout / 128, 32, 1), 256, SM128>>>(
            hh, hl, GWTh, GWTl, HW, K, K, dout, K / 32, 0LL, nullptr, nullptr, nullptr);
        transpose_f16<<<dim3(dout / 32, Nn / 32), dim3(32, 8)>>>(HW, HWTh, HWTl, Nn, dout, 1.f);

        // An (scaled, f16 pairs in place over S); final_A on last layer
        float* finalA = nullptr;
        if (L == 2 && out_size >= Nn * OUTD + Nn * Nn)
            finalA = (float*)d_out + (size_t)Nn * OUTD;
        build_An<<<16384, 256>>>(Ao, Sh, Sl, a0, a1, dinv, finalA);

        // H2 = (An_scaled @ HW) / SCALE_AN + gb
        const int zsp = (dout == 256) ? 4 : 8;
        gemm_f16<128, 0><<<dim3(dout / 128, 32, zsp), 256, SM128>>>(
            Sh, Sl, HWTh, HWTl, part, Nn, Nn, dout, (Nn / 32) / zsp,
            (long long)Nn * dout, nullptr, nullptr, nullptr);
        reduce_part<<<(Nn * dout + 255) / 256, 256>>>(part, H2, Nn, dout, zsp, gb[L], 1.f / SCALE_AN);

        // BatchNorm + LeakyReLU -> H + f16 pairs for next layer
        bn_stats<<<dout / 32, dim3(32, 8)>>>(H2, dout, mu, var);
        bn_apply<<<(Nn * dout + 255) / 256, 256>>>(H2, H, hh, hl, dout, mu, var, bng[L], bnb[L]);
    }

    // out = h @ lin_w + lin_b (K=128, SIMT)
    gemm_nn_splitk<<<dim3(1, 32, 1), 256>>>(H, lw, part, Nn, OUTD, 128, 128);
    reduce_part<<<(Nn * OUTD + 255) / 256, 256>>>(part, (float*)d_out, Nn, OUTD, 1, lb, 1.f);
}

// round 14
// speedup vs baseline: 1.3270x; 1.0102x over previous
#include <cuda_runtime.h>
#include <cuda_fp16.h>
#include <math.h>
#include <stdint.h>

constexpr int Nn  = 4096;
constexpr int ATT = 64;
constexpr int OUTD = 64;
constexpr float SCALE_AN = 16384.f;
constexpr float SCALE_AW = 64.f;
constexpr int EMAX = 1 << 20;

// ---------------- scratch (device globals; no allocation allowed) ----------------
__device__ __half g_Sh[(size_t)Nn * Nn];
__device__ __half g_Sl[(size_t)Nn * Nn];
__device__ float  g_H [Nn * 256];
__device__ float  g_H2[Nn * 256];
__device__ float  g_V [Nn * 256];
__device__ float  g_AoV[Nn * 256];
__device__ __half g_hh[Nn * 256];
__device__ __half g_hl[Nn * 256];
__device__ __half g_VTh[256 * Nn];
__device__ __half g_VTl[256 * Nn];
__device__ __half g_AWTh[64 * Nn];
__device__ __half g_AWTl[64 * Nn];
__device__ __half g_GWTh[256 * 256];
__device__ __half g_GWTl[256 * 256];
__device__ float  g_part[(size_t)8 * Nn * 256];
__device__ float  g_P0[Nn * ATT];
__device__ float  g_rspart[64 * Nn];
__device__ float  g_a0[Nn], g_a1[Nn], g_dinv[Nn];
__device__ float  g_rs0[Nn];
__device__ float  g_mu[256], g_var[256];
__device__ int    g_csr_c[EMAX];
__device__ float  g_csr_w[EMAX];
__device__ int    g_counts[Nn];
__device__ int    g_offs[Nn + 1];
__device__ int    g_cursor[Nn];

// ---------------- helpers ----------------
__device__ __forceinline__ uint32_t smem_u32(const void* p) {
    uint32_t a;
    asm("{ .reg .u64 t; cvta.to.shared.u64 t, %1; cvt.u32.u64 %0, t; }" : "=r"(a) : "l"(p));
    return a;
}
__device__ __forceinline__ void cpa16(uint32_t dst, const void* src) {
    asm volatile("cp.async.cg.shared.global [%0], [%1], 16;" :: "r"(dst), "l"(src));
}
__device__ __forceinline__ void mma16(float (&c)[4], const uint32_t (&a)[4],
                                      uint32_t b0, uint32_t b1) {
    asm volatile(
        "mma.sync.aligned.m16n8k16.row.col.f32.f16.f16.f32 "
        "{%0,%1,%2,%3}, {%4,%5,%6,%7}, {%8,%9}, {%0,%1,%2,%3};"
        : "+f"(c[0]), "+f"(c[1]), "+f"(c[2]), "+f"(c[3])
        : "r"(a[0]), "r"(a[1]), "r"(a[2]), "r"(a[3]), "r"(b0), "r"(b1));
}
__device__ __forceinline__ void splitpair(float x, float y, uint32_t& h, uint32_t& l) {
    __half hx = __float2half_rn(x), hy = __float2half_rn(y);
    __half lx = __float2half_rn(x - __half2float(hx));
    __half ly = __float2half_rn(y - __half2float(hy));
    __half2 hp = __halves2half2(hx, hy), lp = __halves2half2(lx, ly);
    h = *reinterpret_cast<uint32_t*>(&hp);
    l = *reinterpret_cast<uint32_t*>(&lp);
}
__device__ __forceinline__ void split1(float x, __half& h, __half& l) {
    h = __float2half_rn(x);
    l = __float2half_rn(x - __half2float(h));
}
__device__ __forceinline__ float fast_sigmoid(float x) {
    return __fdividef(1.f, 1.f + __expf(-x));
}

// ============================================================================
// f16x3 NT GEMM, pre-split hi/lo f16 operands, double-buffered cp.async.
// EPI 0: f32 store to C (+z*zstride).
// EPI 1: SYMMETRIC sigmoid GEMM (A==B), compact 528-CTA upper-tri grid;
//        mirror writes via smem transpose; rowsum partials (rs).
// EPI 2: row-scaled store: C(f32, scale=rs[row]*SCALE_AN) + TRANSPOSED f16
//        pair store to oh/ol (stride Nn). BN must be 128.
// ============================================================================
template<int BN, int EPI>
__global__ void __launch_bounds__(256, 2) gemm_f16(
    const __half* __restrict__ Ah, const __half* __restrict__ Al,
    const __half* __restrict__ Bh, const __half* __restrict__ Bl,
    float* __restrict__ C, int lda, int ldb, int ldc, int nch,
    long long zstride, const float* __restrict__ rs,
    __half* __restrict__ oh, __half* __restrict__ ol,
    float* __restrict__ rsw)
{
    constexpr int TS   = 20;
    constexpr int TT   = 136;
    constexpr int NT2  = BN / 16;
    constexpr int ABUF = 128 * TS;
    constexpr int BBUF = BN * TS;
    constexpr int BUFSZ = 2 * ABUF + 2 * BBUF;
    extern __shared__ uint32_t smu[];

    int bxv, byv;
    if (EPI == 1) {
        int t = blockIdx.x, j = 0;
        while (t >= 32 - j) { t -= 32 - j; j++; }
        byv = j; bxv = j + t;
    } else {
        bxv = blockIdx.x; byv = blockIdx.y;
    }

    const int tid  = threadIdx.x;
    const int warp = tid >> 5, lane = tid & 31;
    const int g = lane >> 2, tg = lane & 3;
    const int wm = warp >> 1, wn = warp & 1;
    const int rm = wm * 32, cn = wn * (BN / 2);
    const int bm = byv * 128, bn = bxv * BN;
    const int kbeg = blockIdx.z * nch * 32;

    const uint32_t smu_u = smem_u32(smu);

    auto issue = [&](int c) {
        const int b = c & 1;
        const int k0 = kbeg + c * 32;
        const uint32_t base = smu_u + b * BUFSZ * 4;
#pragma unroll
        for (int i = 0; i < 2; i++) {
            int idx = tid + i * 256;
            int r = idx >> 2, q = idx & 3;
            const size_t go = (size_t)(bm + r) * lda + k0 + q * 8;
            cpa16(base + (r * TS + q * 4) * 4, Ah + go);
            cpa16(base + (ABUF + r * TS + q * 4) * 4, Al + go);
        }
#pragma unroll
        for (int i = 0; i < BN / 64; i++) {
            int idx = tid + i * 256;
            int r = idx >> 2, q = idx & 3;
            const size_t go = (size_t)(bn + r) * ldb + k0 + q * 8;
            cpa16(base + (2 * ABUF + r * TS + q * 4) * 4, Bh + go);
            cpa16(base + (2 * ABUF + BBUF + r * TS + q * 4) * 4, Bl + go);
        }
        asm volatile("cp.async.commit_group;" ::: "memory");
    };

    float acc[2][NT2][4];
#pragma unroll
    for (int mt = 0; mt < 2; mt++)
#pragma unroll
        for (int nt = 0; nt < NT2; nt++)
#pragma unroll
            for (int j = 0; j < 4; j++) acc[mt][nt][j] = 0.f;

    issue(0);
    for (int c = 0; c < nch; c++) {
        if (c + 1 < nch) {
            issue(c + 1);
            asm volatile("cp.async.wait_group 1;" ::: "memory");
        } else {
            asm volatile("cp.async.wait_group 0;" ::: "memory");
        }
        __syncthreads();

        const uint32_t* Athi = smu + (c & 1) * BUFSZ;
        const uint32_t* Atlo = Athi + ABUF;
        const uint32_t* Bthi = Athi + 2 * ABUF;
        const uint32_t* Btlo = Bthi + BBUF;

#pragma unroll
        for (int ks = 0; ks < 2; ks++) {
            const int kp = ks * 8;
            uint32_t ah[2][4], al[2][4];
#pragma unroll
            for (int mt = 0; mt < 2; mt++) {
                const int ro = (rm + mt * 16 + g) * TS;
                ah[mt][0] = Athi[ro + kp + tg];
                ah[mt][1] = Athi[ro + 8 * TS + kp + tg];
                ah[mt][2] = Athi[ro + kp + tg + 4];
                ah[mt][3] = Athi[ro + 8 * TS + kp + tg + 4];
                al[mt][0] = Atlo[ro + kp + tg];
                al[mt][1] = Atlo[ro + 8 * TS + kp + tg];
                al[mt][2] = Atlo[ro + kp + tg + 4];
                al[mt][3] = Atlo[ro + 8 * TS + kp + tg + 4];
            }
#pragma unroll
            for (int nt = 0; nt < NT2; nt++) {
                const int bo = (cn + nt * 8 + g) * TS + kp;
                uint32_t bh0 = Bthi[bo + tg], bh1 = Bthi[bo + tg + 4];
                uint32_t bl0 = Btlo[bo + tg], bl1 = Btlo[bo + tg + 4];
#pragma unroll
                for (int mt = 0; mt < 2; mt++) {
                    mma16(acc[mt][nt], ah[mt], bh0, bh1);
                    mma16(acc[mt][nt], ah[mt], bl0, bl1);
                    mma16(acc[mt][nt], al[mt], bh0, bh1);
                }
            }
        }
        __syncthreads();
    }

    // ---------------- epilogue ----------------
    __half* Th = reinterpret_cast<__half*>(smu);
    __half* Tl = Th + 128 * TT;
    const bool mirror = (EPI == 1) && (bxv != byv);
    const bool stash  = mirror || (EPI == 2);

#pragma unroll
    for (int mt = 0; mt < 2; mt++) {
        const int r0l = rm + mt * 16 + g;
        const int r1l = r0l + 8;
        const int r0 = bm + r0l, r1 = bm + r1l;
        float s0 = 0.f, s1 = 0.f;
        float sc0 = 1.f, sc1 = 1.f;
        if (EPI == 2) { sc0 = rs[r0] * SCALE_AN; sc1 = rs[r1] * SCALE_AN; }
#pragma unroll
        for (int nt = 0; nt < NT2; nt++) {
            float c0 = acc[mt][nt][0], c1 = acc[mt][nt][1];
            float c2 = acc[mt][nt][2], c3 = acc[mt][nt][3];
            const int cl = cn + nt * 8 + 2 * tg;
            const int col = bn + cl;
            if (EPI == 1) {
                c0 = fast_sigmoid(c0); c1 = fast_sigmoid(c1);
                c2 = fast_sigmoid(c2); c3 = fast_sigmoid(c3);
                s0 += c0 + c1; s1 += c2 + c3;
            } else if (EPI == 2) {
                c0 *= sc0; c1 *= sc0; c2 *= sc1; c3 *= sc1;
                *reinterpret_cast<float2*>(C + (size_t)r0 * ldc + col) = make_float2(c0, c1);
                *reinterpret_cast<float2*>(C + (size_t)r1 * ldc + col) = make_float2(c2, c3);
            } else {
                float* Cz = C + (size_t)blockIdx.z * zstride;
                *reinterpret_cast<float2*>(Cz + (size_t)r0 * ldc + col) = make_float2(c0, c1);
                *reinterpret_cast<float2*>(Cz + (size_t)r1 * ldc + col) = make_float2(c2, c3);
            }
            if (EPI == 1 || EPI == 2) {
                uint32_t h01, l01, h23, l23;
                splitpair(c0, c1, h01, l01);
                splitpair(c2, c3, h23, l23);
                if (EPI == 1) {
                    *reinterpret_cast<uint32_t*>(oh + (size_t)r0 * ldc + col) = h01;
                    *reinterpret_cast<uint32_t*>(ol + (size_t)r0 * ldc + col) = l01;
                    *reinterpret_cast<uint32_t*>(oh + (size_t)r1 * ldc + col) = h23;
                    *reinterpret_cast<uint32_t*>(ol + (size_t)r1 * ldc + col) = l23;
                }
                if (stash) {
                    __half2 H01 = *reinterpret_cast<__half2*>(&h01);
                    __half2 L01 = *reinterpret_cast<__half2*>(&l01);
                    __half2 H23 = *reinterpret_cast<__half2*>(&h23);
                    __half2 L23 = *reinterpret_cast<__half2*>(&l23);
                    Th[cl * TT + r0l]       = __low2half(H01);
                    Th[(cl + 1) * TT + r0l] = __high2half(H01);
                    Tl[cl * TT + r0l]       = __low2half(L01);
                    Tl[(cl + 1) * TT + r0l] = __high2half(L01);
                    Th[cl * TT + r1l]       = __low2half(H23);
                    Th[(cl + 1) * TT + r1l] = __high2half(H23);
                    Tl[cl * TT + r1l]       = __low2half(L23);
                    Tl[(cl + 1) * TT + r1l] = __high2half(L23);
                }
            }
        }
        if (EPI == 1) {
            s0 += __shfl_xor_sync(0xFFFFFFFFu, s0, 1);
            s0 += __shfl_xor_sync(0xFFFFFFFFu, s0, 2);
            s1 += __shfl_xor_sync(0xFFFFFFFFu, s1, 1);
            s1 += __shfl_xor_sync(0xFFFFFFFFu, s1, 2);
            if (tg == 0) {
                float* rp = rsw + (size_t)(bxv * 2 + wn) * Nn;
                rp[r0] = s0;
                rp[r1] = s1;
            }
        }
    }

    if (stash) {
        __syncthreads();
        // transposed write: row = bn + c (B/N dim), cols bm..bm+127
#pragma unroll
        for (int i = 0; i < 8; i++) {
            int c  = (tid >> 4) + i * 16;
            int ch = tid & 15;
            uint4 vh = *reinterpret_cast<const uint4*>(&Th[c * TT + ch * 8]);
            uint4 vl = *reinterpret_cast<const uint4*>(&Tl[c * TT + ch * 8]);
            *reinterpret_cast<uint4*>(oh + (size_t)(bn + c) * Nn + bm + ch * 8) = vh;
            *reinterpret_cast<uint4*>(ol + (size_t)(bn + c) * Nn + bm + ch * 8) = vl;
        }
        if (EPI == 1) {
            int c = tid >> 1, half = tid & 1;
            const __half2* ph = reinterpret_cast<const __half2*>(&Th[c * TT + half * 64]);
            const __half2* pl = reinterpret_cast<const __half2*>(&Tl[c * TT + half * 64]);
            float s = 0.f;
#pragma unroll
            for (int k = 0; k < 32; k++) {
                float2 a = __half22float2(ph[k]);
                float2 b = __half22float2(pl[k]);
                s += a.x + a.y + b.x + b.y;
            }
            rsw[(size_t)(byv * 2 + half) * Nn + bn + c] = s;
        }
    }
}

// ---------------- conversion / utility kernels ----------------
__global__ void conv_split(const float* __restrict__ in, __half* __restrict__ oh,
                           __half* __restrict__ ol, size_t n4) {
    size_t i = (size_t)blockIdx.x * blockDim.x + threadIdx.x;
    if (i >= n4) return;
    float4 v = reinterpret_cast<const float4*>(in)[i];
    uint32_t h01, l01, h23, l23;
    splitpair(v.x, v.y, h01, l01);
    splitpair(v.z, v.w, h23, l23);
    reinterpret_cast<uint2*>(oh)[i] = make_uint2(h01, h23);
    reinterpret_cast<uint2*>(ol)[i] = make_uint2(l01, l23);
}

__global__ void fill_zero4(float* p, size_t n4) {
    size_t i = (size_t)blockIdx.x * blockDim.x + threadIdx.x;
    if (i < n4) reinterpret_cast<float4*>(p)[i] = make_float4(0.f, 0.f, 0.f, 0.f);
}

__global__ void zero_int(int* p, int n) {
    int i = blockIdx.x * 256 + threadIdx.x;
    if (i < n) p[i] = 0;
}

// CSR build: count (+rs0), scan, scatter
__global__ void edge_count(const int* __restrict__ ei, const float* __restrict__ ew,
                           int* __restrict__ counts, float* __restrict__ rs0, int E) {
    int t = blockIdx.x * 256 + threadIdx.x;
    if (t < E) {
        atomicAdd(counts + ei[t], 1);
        atomicAdd(rs0 + ei[t], ew[t]);
    }
}

__global__ void scan_kernel(const int* __restrict__ counts, int* __restrict__ offs,
                            int* __restrict__ cursor) {
    __shared__ int ss[1024];
    int t = threadIdx.x;
    int b = t * 4;
    int c0 = counts[b], c1 = counts[b + 1], c2 = counts[b + 2], c3 = counts[b + 3];
    int loc = c0 + c1 + c2 + c3;
    ss[t] = loc;
    __syncthreads();
    for (int d = 1; d < 1024; d <<= 1) {
        int v = (t >= d) ? ss[t - d] : 0;
        __syncthreads();
        ss[t] += v;
        __syncthreads();
    }
    int excl = ss[t] - loc;
    offs[b] = excl;           cursor[b] = excl;
    offs[b + 1] = excl + c0;  cursor[b + 1] = excl + c0;
    offs[b + 2] = excl + c0 + c1; cursor[b + 2] = excl + c0 + c1;
    offs[b + 3] = excl + c0 + c1 + c2; cursor[b + 3] = excl + c0 + c1 + c2;
    if (t == 1023) offs[4096] = ss[1023];
}

__global__ void edge_scatter(const int* __restrict__ ei, const float* __restrict__ ew,
                             int* __restrict__ cursor, int* __restrict__ cc,
                             float* __restrict__ cw, int E) {
    int t = blockIdx.x * 256 + threadIdx.x;
    if (t < E) {
        int p = atomicAdd(cursor + ei[t], 1);
        cc[p] = ei[E + t];
        cw[p] = ew[t];
    }
}

// sparse P0 = A_orig @ aw1: warp per edge, fp32 atomics (exact)
__global__ void sparse_p0(const int* __restrict__ ei, const float* __restrict__ ew,
                          const float* __restrict__ aw1, float* __restrict__ P0, int E) {
    int e = (blockIdx.x * blockDim.x + threadIdx.x) >> 5;
    int lane = threadIdx.x & 31;
    if (e >= E) return;
    int r = ei[e], c = ei[E + e];
    float w = ew[e];
    float2 v = *reinterpret_cast<const float2*>(aw1 + (size_t)c * ATT + lane * 2);
    atomicAdd(P0 + (size_t)r * ATT + lane * 2,     w * v.x);
    atomicAdd(P0 + (size_t)r * ATT + lane * 2 + 1, w * v.y);
}

// AoV[r][:] = sum_{edges r->c} w * V[c][:]  (CSR gather, no atomics)
__global__ void spmm_csr(const int* __restrict__ offs, const int* __restrict__ cc,
                         const float* __restrict__ cw, const float* __restrict__ V,
                         float* __restrict__ out, int dout) {
    int r = blockIdx.x, t = threadIdx.x;
    if (t >= dout) return;
    int e0 = offs[r], e1 = offs[r + 1];
    float acc = 0.f;
    for (int e = e0; e < e1; e++) {
        int c = cc[e];
        float w = cw[e];
        acc += w * V[(size_t)c * dout + t];
    }
    out[(size_t)r * dout + t] = acc;
}

__global__ void transpose_f16(const float* __restrict__ in, __half* __restrict__ oh,
                              __half* __restrict__ ol, int R, int Cc, float scale) {
    __shared__ float t[32][33];
    int bx = blockIdx.x * 32, by = blockIdx.y * 32;
    int x = bx + threadIdx.x;
    for (int dy = 0; dy < 32; dy += 8) {
        int y = by + threadIdx.y + dy;
        if (x < Cc && y < R) t[threadIdx.y + dy][threadIdx.x] = in[(size_t)y * Cc + x];
    }
    __syncthreads();
    int xo = by + threadIdx.x;
    for (int dy = 0; dy < 32; dy += 8) {
        int yo = bx + threadIdx.y + dy;
        if (xo < R && yo < Cc) {
            float v = t[threadIdx.x][threadIdx.y + dy] * scale;
            __half h, l;
            split1(v, h, l);
            oh[(size_t)yo * R + xo] = h;
            ol[(size_t)yo * R + xo] = l;
        }
    }
}

// ---------------- SIMT GEMM (final out only) ----------------
__global__ __launch_bounds__(256) void gemm_nn_splitk(
    const float* __restrict__ A, const float* __restrict__ B,
    float* __restrict__ part, int M, int Ncols, int K, int Kc)
{
    __shared__ float As[16][132];
    __shared__ float Bs[16][64];
    const int tid = threadIdx.x;
    const int tr = tid >> 4, tc = tid & 15;
    const int bm = blockIdx.y * 128, bn = blockIdx.x * 64;
    const int kbeg = blockIdx.z * Kc;

    float acc[8][4];
#pragma unroll
    for (int i = 0; i < 8; i++)
#pragma unroll
        for (int j = 0; j < 4; j++) acc[i][j] = 0.f;

    for (int k0 = kbeg; k0 < kbeg + Kc; k0 += 16) {
#pragma unroll
        for (int s = 0; s < 2; s++) {
            int slot = tid + s * 256;
            int r = slot >> 2, q = slot & 3;
            float4 va = *reinterpret_cast<const float4*>(A + (size_t)(bm + r) * K + k0 + q * 4);
            As[q * 4 + 0][r] = va.x; As[q * 4 + 1][r] = va.y;
            As[q * 4 + 2][r] = va.z; As[q * 4 + 3][r] = va.w;
        }
        {
            int r = tid >> 4, q = tid & 15;
            *reinterpret_cast<float4*>(&Bs[r][q * 4]) =
                *reinterpret_cast<const float4*>(B + (size_t)(k0 + r) * Ncols + bn + q * 4);
        }
        __syncthreads();
#pragma unroll
        for (int kk = 0; kk < 16; kk++) {
            float a[8], b[4];
            *reinterpret_cast<float4*>(&a[0]) = *reinterpret_cast<const float4*>(&As[kk][tr * 4]);
            *reinterpret_cast<float4*>(&a[4]) = *reinterpret_cast<const float4*>(&As[kk][64 + tr * 4]);
            *reinterpret_cast<float4*>(&b[0]) = *reinterpret_cast<const float4*>(&Bs[kk][tc * 4]);
#pragma unroll
            for (int i = 0; i < 8; i++)
#pragma unroll
                for (int j = 0; j < 4; j++) acc[i][j] += a[i] * b[j];
        }
        __syncthreads();
    }

    float* out = part + (size_t)blockIdx.z * M * Ncols;
#pragma unroll
    for (int i = 0; i < 8; i++) {
        int row = bm + ((i < 4) ? tr * 4 + i : 64 + tr * 4 + (i - 4));
        *reinterpret_cast<float4*>(out + (size_t)row * Ncols + bn + tc * 4) =
            make_float4(acc[i][0], acc[i][1], acc[i][2], acc[i][3]);
    }
}

__global__ void reduce_part(const float* __restrict__ part, float* __restrict__ out,
                            int M, int Ncols, int split, const float* __restrict__ bias,
                            float scale) {
    int idx = blockIdx.x * 256 + threadIdx.x;
    int total = M * Ncols;
    if (idx < total) {
        float s = 0.f;
        for (int p = 0; p < split; p++) s += part[(size_t)p * total + idx];
        s *= scale;
        if (bias) s += bias[idx % Ncols];
        out[idx] = s;
    }
}

// ---------------- attention: P0 dense read + partB reduce + coeffs ----------------
__global__ void attention_kernel(const float* __restrict__ P0, const float* __restrict__ partB,
                                 const float* __restrict__ ab1,
                                 const float* __restrict__ aw2, const float* __restrict__ ab2,
                                 const float* __restrict__ rs0, const float* __restrict__ rspart,
                                 float* __restrict__ a0o, float* __restrict__ a1o,
                                 float* __restrict__ dinv, float invs) {
    int warp = (blockIdx.x * blockDim.x + threadIdx.x) >> 5;
    int lane = threadIdx.x & 31;
    if (warp >= Nn) return;
    float s0 = 0.f, s1 = 0.f;
    for (int t = lane; t < ATT; t += 32) {
        const size_t base = (size_t)warp * ATT + t;
        float p1 = 0.f;
#pragma unroll
        for (int z = 0; z < 8; z++) p1 += partB[(size_t)z * Nn * ATT + base];
        float b = ab1[t], w2 = aw2[t];
        s0 += tanhf(P0[base] + b) * w2;
        s1 += tanhf(p1 * invs + b) * w2;
    }
    float sr = rspart[(size_t)lane * Nn + warp] + rspart[(size_t)(lane + 32) * Nn + warp];
#pragma unroll
    for (int o = 16; o; o >>= 1) {
        s0 += __shfl_down_sync(0xFFFFFFFFu, s0, o);
        s1 += __shfl_down_sync(0xFFFFFFFFu, s1, o);
        sr += __shfl_down_sync(0xFFFFFFFFu, sr, o);
    }
    if (lane == 0) {
        float b2 = ab2[0];
        s0 += b2; s1 += b2;
        float m = fmaxf(s0, s1);
        float e0 = __expf(s0 - m), e1 = __expf(s1 - m);
        float inv = __fdividef(1.f, e0 + e1);
        float a0 = e0 * inv, a1 = e1 * inv;
        float deg = a0 * rs0[warp] + a1 * sr + 1.f;
        a0o[warp] = a0; a1o[warp] = a1;
        dinv[warp] = deg > 0.f ? rsqrtf(deg) : 0.f;
    }
}

// ---------------- H2 assembly: D*(a1*SV + V + a0*AoV)/SCALE ----------------
__global__ void assemble_H2(const float* __restrict__ part, int zsp,
                            const float* __restrict__ V, const float* __restrict__ AoV,
                            const float* __restrict__ a0, const float* __restrict__ a1,
                            const float* __restrict__ dinv, float* __restrict__ H2, int dout) {
    int idx = blockIdx.x * 256 + threadIdx.x;
    int total = Nn * dout;
    if (idx >= total) return;
    int i = idx / dout;
    float s = 0.f;
    for (int z = 0; z < zsp; z++) s += part[(size_t)z * total + idx];
    H2[idx] = dinv[i] * (a1[i] * s + V[idx] + a0[i] * AoV[idx]) * (1.f / SCALE_AN);
}

// ---------------- final_A = a1*S (dense) + a0*w (edges) ----------------
__global__ void finalA_dense(const __half* __restrict__ Sh, const __half* __restrict__ Sl,
                             const float* __restrict__ a1, float* __restrict__ FA) {
    size_t gid = (size_t)blockIdx.x * blockDim.x + threadIdx.x;
    if (gid >= (size_t)Nn * Nn / 4) return;
    int i  = (int)(gid / (Nn / 4));
    int j4 = (int)(gid % (Nn / 4)) * 4;
    uint2 shv = *reinterpret_cast<const uint2*>(Sh + (size_t)i * Nn + j4);
    uint2 slv = *reinterpret_cast<const uint2*>(Sl + (size_t)i * Nn + j4);
    float2 sa = __half22float2(*reinterpret_cast<__half2*>(&shv.x));
    float2 sb = __half22float2(*reinterpret_cast<__half2*>(&shv.y));
    float2 sc = __half22float2(*reinterpret_cast<__half2*>(&slv.x));
    float2 sd = __half22float2(*reinterpret_cast<__half2*>(&slv.y));
    float A1 = a1[i];
    float4 v = make_float4(A1 * (sa.x + sc.x), A1 * (sa.y + sc.y),
                           A1 * (sb.x + sd.x), A1 * (sb.y + sd.y));
    *reinterpret_cast<float4*>(FA + (size_t)i * Nn + j4) = v;
}

__global__ void finalA_edges(const int* __restrict__ ei, const float* __restrict__ ew,
                             const float* __restrict__ a0, float* __restrict__ FA, int E) {
    int t = blockIdx.x * 256 + threadIdx.x;
    if (t < E) {
        int r = ei[t], c = ei[E + t];
        atomicAdd(FA + (size_t)r * Nn + c, a0[r] * ew[t]);
    }
}

// ---------------- BatchNorm (two-pass) ----------------
__global__ void bn_stats(const float* __restrict__ H, int dout,
                         float* __restrict__ mu, float* __restrict__ var) {
    int col = blockIdx.x * 32 + threadIdx.x;
    __shared__ float sh[8][32];
    __shared__ float shm[32];

    float s = 0.f;
    for (int r = threadIdx.y; r < Nn; r += 8)
        s += H[(size_t)r * dout + col];
    sh[threadIdx.y][threadIdx.x] = s;
    __syncthreads();
    if (threadIdx.y == 0) {
#pragma unroll
        for (int y = 1; y < 8; y++) s += sh[y][threadIdx.x];
        shm[threadIdx.x] = s / (float)Nn;
    }
    __syncthreads();
    float m = shm[threadIdx.x];

    float s2 = 0.f;
    for (int r = threadIdx.y; r < Nn; r += 8) {
        float d = H[(size_t)r * dout + col] - m;
        s2 += d * d;
    }
    __syncthreads();
    sh[threadIdx.y][threadIdx.x] = s2;
    __syncthreads();
    if (threadIdx.y == 0) {
#pragma unroll
        for (int y = 1; y < 8; y++) s2 += sh[y][threadIdx.x];
        mu[col]  = m;
        var[col] = s2 / (float)Nn;
    }
}

__global__ void bn_apply(const float* __restrict__ Hin, float* __restrict__ Hout,
                         __half* __restrict__ oh, __half* __restrict__ ol, int dout,
                         const float* __restrict__ mu, const float* __restrict__ var,
                         const float* __restrict__ gamma, const float* __restrict__ beta) {
    int idx = blockIdx.x * 256 + threadIdx.x;
    if (idx < Nn * dout) {
        int c = idx % dout;
        float x = Hin[idx];
        float y = gamma[c] * (x - mu[c]) * rsqrtf(var[c] + 1e-5f) + beta[c];
        y = y > 0.f ? y : 0.01f * y;
        Hout[idx] = y;
        __half h, l;
        split1(y, h, l);
        oh[idx] = h;
        ol[idx] = l;
    }
}

// ---------------- host orchestration ----------------
extern "C" void kernel_launch(void* const* d_in, const int* in_sizes, int n_in,
                              void* d_out, int out_size) {
    const float* X  = (const float*)d_in[0];
    const int*   ei = (const int*)d_in[1];
    const float* ew = (const float*)d_in[2];
    const float *gw[3], *bng[3], *bnb[3], *aw1[3], *ab1[3], *aw2[3], *ab2[3];
    for (int i = 0; i < 3; i++) {
        int b = 3 + i * 8;
        gw[i]  = (const float*)d_in[b + 0];
        // d_in[b+1] = gcn bias: cancels exactly under training-mode BN
        bng[i] = (const float*)d_in[b + 2];
        bnb[i] = (const float*)d_in[b + 3];
        aw1[i] = (const float*)d_in[b + 4];
        ab1[i] = (const float*)d_in[b + 5];
        aw2[i] = (const float*)d_in[b + 6];
        ab2[i] = (const float*)d_in[b + 7];
    }
    const float* lw = (const float*)d_in[27];
    const float* lb = (const float*)d_in[28];
    const int E = in_sizes[2];

    float *H, *H2, *V, *AoV, *part, *P0, *rspart, *a0, *a1, *dinv, *rs0, *mu, *var, *csr_w;
    __half *Sh, *Sl, *hh, *hl, *VTh, *VTl, *AWTh, *AWTl, *GWTh, *GWTl;
    int *csr_c, *counts, *offs, *cursor;
    cudaGetSymbolAddress((void**)&Sh,     g_Sh);
    cudaGetSymbolAddress((void**)&Sl,     g_Sl);
    cudaGetSymbolAddress((void**)&H,      g_H);
    cudaGetSymbolAddress((void**)&H2,     g_H2);
    cudaGetSymbolAddress((void**)&V,      g_V);
    cudaGetSymbolAddress((void**)&AoV,    g_AoV);
    cudaGetSymbolAddress((void**)&hh,     g_hh);
    cudaGetSymbolAddress((void**)&hl,     g_hl);
    cudaGetSymbolAddress((void**)&VTh,    g_VTh);
    cudaGetSymbolAddress((void**)&VTl,    g_VTl);
    cudaGetSymbolAddress((void**)&AWTh,   g_AWTh);
    cudaGetSymbolAddress((void**)&AWTl,   g_AWTl);
    cudaGetSymbolAddress((void**)&GWTh,   g_GWTh);
    cudaGetSymbolAddress((void**)&GWTl,   g_GWTl);
    cudaGetSymbolAddress((void**)&part,   g_part);
    cudaGetSymbolAddress((void**)&P0,     g_P0);
    cudaGetSymbolAddress((void**)&rspart, g_rspart);
    cudaGetSymbolAddress((void**)&a0,     g_a0);
    cudaGetSymbolAddress((void**)&a1,     g_a1);
    cudaGetSymbolAddress((void**)&dinv,   g_dinv);
    cudaGetSymbolAddress((void**)&rs0,    g_rs0);
    cudaGetSymbolAddress((void**)&mu,     g_mu);
    cudaGetSymbolAddress((void**)&var,    g_var);
    cudaGetSymbolAddress((void**)&csr_c,  g_csr_c);
    cudaGetSymbolAddress((void**)&csr_w,  g_csr_w);
    cudaGetSymbolAddress((void**)&counts, g_counts);
    cudaGetSymbolAddress((void**)&offs,   g_offs);
    cudaGetSymbolAddress((void**)&cursor, g_cursor);

    const int SM128 = 2 * (2 * 128 * 20 + 2 * 128 * 20) * 4;  // 81920
    const int SM64  = 2 * (2 * 128 * 20 + 2 *  64 * 20) * 4;  // 61440
    cudaFuncSetAttribute(gemm_f16<128, 1>, cudaFuncAttributeMaxDynamicSharedMemorySize, SM128);
    cudaFuncSetAttribute(gemm_f16<128, 0>, cudaFuncAttributeMaxDynamicSharedMemorySize, SM128);
    cudaFuncSetAttribute(gemm_f16<128, 2>, cudaFuncAttributeMaxDynamicSharedMemorySize, SM128);
    cudaFuncSetAttribute(gemm_f16<64, 0>,  cudaFuncAttributeMaxDynamicSharedMemorySize, SM64);

    float* partB = part + (size_t)4 * Nn * 256;   // P1 partials region

    // ---------------- init: h split + CSR build + rs0 (all sparse) ----------------
    conv_split<<<(Nn * 256 / 4 + 255) / 256, 256>>>(X, hh, hl, Nn * 256 / 4);
    zero_int<<<(Nn + 255) / 256, 256>>>(counts, Nn);
    fill_zero4<<<(Nn / 4 + 255) / 256, 256>>>(rs0, Nn / 4);
    edge_count<<<(E + 255) / 256, 256>>>(ei, ew, counts, rs0, E);
    scan_kernel<<<1, 1024>>>(counts, offs, cursor);
    edge_scatter<<<(E + 255) / 256, 256>>>(ei, ew, cursor, csr_c, csr_w, E);

    const int din[3] = {256, 256, 256};
    const int dof[3] = {256, 256, 128};

    for (int L = 0; L < 3; L++) {
        const int K = din[L], dout = dof[L];

        // S = sigmoid(h h^T): symmetric, compact 528-CTA grid -> Sh/Sl + rowsum partials
        gemm_f16<128, 1><<<dim3(528, 1, 1), 256, SM128>>>(
            hh, hl, hh, hl, nullptr, K, K, Nn, K / 32, 0LL, nullptr, Sh, Sl, rspart);

        // P0 = A_orig @ aw1 (sparse, exact); P1 = S @ (64*aw1) (dense split-K 8)
        fill_zero4<<<Nn * ATT / 4 / 256, 256>>>(P0, Nn * ATT / 4);
        sparse_p0<<<(E * 32 + 255) / 256, 256>>>(ei, ew, aw1[L], P0, E);
        transpose_f16<<<dim3(2, Nn / 32), dim3(32, 8)>>>(aw1[L], AWTh, AWTl, Nn, ATT, SCALE_AW);
        gemm_f16<64, 0><<<dim3(1, 32, 8), 256, SM64>>>(
            Sh, Sl, AWTh, AWTl, partB, Nn, Nn, ATT, (Nn / 32) / 8,
            (long long)Nn * ATT, nullptr, nullptr, nullptr, nullptr);

        attention_kernel<<<Nn / 4, 128>>>(P0, partB, ab1[L], aw2[L], ab2[L],
                                          rs0, rspart, a0, a1, dinv, 1.f / SCALE_AW);

        // V = D * (h @ gw) * SCALE: tensor GEMM w/ row-scaled f32 + transposed f16 epilogue
        transpose_f16<<<dim3(dout / 32, K / 32), dim3(32, 8)>>>(gw[L], GWTh, GWTl, K, dout, 1.f);
        gemm_f16<128, 2><<<dim3(dout / 128, 32, 1), 256, SM128>>>(
            hh, hl, GWTh, GWTl, V, K, K, dout, K / 32, 0LL, dinv, VTh, VTl, nullptr);

        // AoV = Ao @ V (CSR gather, exact)
        spmm_csr<<<Nn, 256>>>(offs, csr_c, csr_w, V, AoV, dout);

        // SV = S @ V (dense split-K)
        const int zsp = (dout == 256) ? 4 : 8;
        gemm_f16<128, 0><<<dim3(dout / 128, 32, zsp), 256, SM128>>>(
            Sh, Sl, VTh, VTl, part, Nn, Nn, dout, (Nn / 32) / zsp,
            (long long)Nn * dout, nullptr, nullptr, nullptr, nullptr);

        // H2 = D*(a1*SV + V + a0*AoV)/SCALE  (gcn bias cancels in BN)
        assemble_H2<<<(Nn * dout + 255) / 256, 256>>>(part, zsp, V, AoV, a0, a1, dinv, H2, dout);

        // final_A on last layer: a1*S dense + a0*w at edges (exact)
        if (L == 2 && out_size >= Nn * OUTD + Nn * Nn) {
            float* FA = (float*)d_out + (size_t)Nn * OUTD;
            finalA_dense<<<16384, 256>>>(Sh, Sl, a1, FA);
            finalA_edges<<<(E + 255) / 256, 256>>>(ei, ew, a0, FA, E);
        }

        // BatchNorm + LeakyReLU -> H + f16 pairs for next layer
        bn_stats<<<dout / 32, dim3(32, 8)>>>(H2, dout, mu, var);
        bn_apply<<<(Nn * dout + 255) / 256, 256>>>(H2, H, hh, hl, dout, mu, var, bng[L], bnb[L]);
    }

    // out = H @ lin_w + lin_b (K=128, SIMT)
    gemm_nn_splitk<<<dim3(1, 32, 1), 256>>>(H, lw, part, Nn, OUTD, 128, 128);
    reduce_part<<<(Nn * OUTD + 255) / 256, 256>>>(part, (float*)d_out, Nn, OUTD, 1, lb, 1.f);
}